// round 4
// baseline (speedup 1.0000x reference)
#include <cuda_runtime.h>
#include <math.h>

#define Bb 512
#define Mm 64
#define Vv 20000
#define Ee 1024
#define Dd 384
#define Tt 100
#define SPLIT 10

// ---------------- scratch (device globals; no allocations allowed) ----------
__device__ float g_part[SPLIT * Bb * Ee];
__device__ float g_e1[Bb * Ee];
__device__ float g_hbow[Bb * Ee];
__device__ float g_q[Bb * Dd];
__device__ float g_qk[Bb * Dd];
__device__ float g_ebar[Bb * Dd];
__device__ float g_di[Bb * Dd];
__device__ float g_mu[Bb * Tt];
__device__ float g_lv[Bb * Tt];
__device__ float g_theta[Bb * Tt];
__device__ float g_logit[(size_t)Bb * Vv];
__device__ float g_colmu[Vv];
__device__ float g_colinv[Vv];
__device__ float g_recon[Bb];
__device__ float g_kl[Bb];

// ---------------- packed f32x2 helpers --------------------------------------
__device__ __forceinline__ unsigned long long pk2(float x, float y) {
    unsigned long long r;
    asm("mov.b64 %0, {%1, %2};" : "=l"(r) : "f"(x), "f"(y));
    return r;
}
__device__ __forceinline__ unsigned long long fma2(unsigned long long a,
                                                   unsigned long long b,
                                                   unsigned long long c) {
    unsigned long long d;
    asm("fma.rn.f32x2 %0, %1, %2, %3;" : "=l"(d) : "l"(a), "l"(b), "l"(c));
    return d;
}
__device__ __forceinline__ void upk2(unsigned long long v, float& lo, float& hi) {
    asm("mov.b64 {%0, %1}, %2;" : "=f"(lo), "=f"(hi) : "l"(v));
}
__device__ __forceinline__ float softplus_f(float x) {
    return x > 0.f ? x + log1pf(expf(-x)) : log1pf(expf(x));
}

// ===================== fc11 split-K GEMM (dominant op) =======================
__global__ __launch_bounds__(64) void fc11_kernel(const float* __restrict__ A,
                                                  const float* __restrict__ W) {
    __shared__ float As[32][68];
    __shared__ float Bs[32][68];
    const int bn = blockIdx.x * 64;
    const int bm = blockIdx.y * 64;
    const int s  = blockIdx.z;
    const int t  = threadIdx.x;
    const int ty = t >> 3, tx = t & 7;
    const int lr = t >> 3,  lk = t & 7;
    const int t0 = (s * 625) / SPLIT, t1 = ((s + 1) * 625) / SPLIT;

    unsigned long long acc[8][4];
#pragma unroll
    for (int i = 0; i < 8; i++)
#pragma unroll
        for (int j = 0; j < 4; j++) acc[i][j] = 0ull;

    for (int kt = t0; kt < t1; kt++) {
        const int k0 = kt * 32;
#pragma unroll
        for (int i = 0; i < 8; i++) {
            const int row = i * 8 + lr;
            float4 av = *(const float4*)&A[(size_t)(bm + row) * Vv + k0 + lk * 4];
            As[lk * 4 + 0][row] = av.x; As[lk * 4 + 1][row] = av.y;
            As[lk * 4 + 2][row] = av.z; As[lk * 4 + 3][row] = av.w;
            float4 bv = *(const float4*)&W[(size_t)(bn + row) * Vv + k0 + lk * 4];
            Bs[lk * 4 + 0][row] = bv.x; Bs[lk * 4 + 1][row] = bv.y;
            Bs[lk * 4 + 2][row] = bv.z; Bs[lk * 4 + 3][row] = bv.w;
        }
        __syncthreads();
#pragma unroll
        for (int kk = 0; kk < 32; kk++) {
            float4 a0 = *(const float4*)&As[kk][ty * 8];
            float4 a1 = *(const float4*)&As[kk][ty * 8 + 4];
            float4 b0 = *(const float4*)&Bs[kk][tx * 8];
            float4 b1 = *(const float4*)&Bs[kk][tx * 8 + 4];
            unsigned long long B0 = pk2(b0.x, b0.y), B1 = pk2(b0.z, b0.w);
            unsigned long long B2 = pk2(b1.x, b1.y), B3 = pk2(b1.z, b1.w);
            float ar[8] = {a0.x, a0.y, a0.z, a0.w, a1.x, a1.y, a1.z, a1.w};
#pragma unroll
            for (int i = 0; i < 8; i++) {
                unsigned long long Ai = pk2(ar[i], ar[i]);
                acc[i][0] = fma2(Ai, B0, acc[i][0]);
                acc[i][1] = fma2(Ai, B1, acc[i][1]);
                acc[i][2] = fma2(Ai, B2, acc[i][2]);
                acc[i][3] = fma2(Ai, B3, acc[i][3]);
            }
        }
        __syncthreads();
    }

#pragma unroll
    for (int i = 0; i < 8; i++) {
        const int gm = bm + ty * 8 + i;
        float* prow = g_part + ((size_t)s * Bb + gm) * Ee + bn + tx * 8;
#pragma unroll
        for (int j = 0; j < 4; j++) {
            float lo, hi;
            upk2(acc[i][j], lo, hi);
            prow[j * 2] = lo;
            prow[j * 2 + 1] = hi;
        }
    }
}

__global__ void fc11_reduce(const float* __restrict__ bias) {
    const int i = blockIdx.x * 256 + threadIdx.x;
    float v = bias[i & (Ee - 1)];
#pragma unroll
    for (int s = 0; s < SPLIT; s++) v += g_part[(size_t)s * (Bb * Ee) + i];
    g_e1[i] = softplus_f(v);
}

// ---------------- generic GEMM body, C = act(A @ B(T) + bias) ---------------
template <int ACT, bool BNT>
__device__ __forceinline__ void gemm64_body(const float* __restrict__ A,
                                            const float* __restrict__ Bm,
                                            const float* __restrict__ bias,
                                            float* __restrict__ C,
                                            int M, int N, int K) {
    __shared__ float As[16][64];
    __shared__ float Bs[16][64];
    const int bm = blockIdx.y * 64, bn = blockIdx.x * 64;
    const int tid = threadIdx.x;
    const int tr = tid >> 4, tc = tid & 15;
    const int lrow = tid >> 4;
    const int lk = tid & 15;

    unsigned long long acc[4][2];
#pragma unroll
    for (int i = 0; i < 4; i++) { acc[i][0] = 0ull; acc[i][1] = 0ull; }

    for (int k0 = 0; k0 < K; k0 += 16) {
#pragma unroll
        for (int i = 0; i < 4; i++) {
            int r = lrow + i * 16;
            int gk = k0 + lk;
            int gm = bm + r;
            As[lk][r] = (gm < M && gk < K) ? A[(size_t)gm * K + gk] : 0.f;
            int gn = bn + r;
            float v = 0.f;
            if (gn < N && gk < K)
                v = BNT ? Bm[(size_t)gn * K + gk] : Bm[(size_t)gk * N + gn];
            Bs[lk][r] = v;
        }
        __syncthreads();
#pragma unroll
        for (int kk = 0; kk < 16; kk++) {
            float a0 = As[kk][tr * 4 + 0];
            float a1 = As[kk][tr * 4 + 1];
            float a2 = As[kk][tr * 4 + 2];
            float a3 = As[kk][tr * 4 + 3];
            unsigned long long b0 =
                *reinterpret_cast<const unsigned long long*>(&Bs[kk][tc * 4]);
            unsigned long long b1 =
                *reinterpret_cast<const unsigned long long*>(&Bs[kk][tc * 4 + 2]);
            unsigned long long A0 = pk2(a0, a0), A1 = pk2(a1, a1);
            unsigned long long A2 = pk2(a2, a2), A3 = pk2(a3, a3);
            acc[0][0] = fma2(A0, b0, acc[0][0]); acc[0][1] = fma2(A0, b1, acc[0][1]);
            acc[1][0] = fma2(A1, b0, acc[1][0]); acc[1][1] = fma2(A1, b1, acc[1][1]);
            acc[2][0] = fma2(A2, b0, acc[2][0]); acc[2][1] = fma2(A2, b1, acc[2][1]);
            acc[3][0] = fma2(A3, b0, acc[3][0]); acc[3][1] = fma2(A3, b1, acc[3][1]);
        }
        __syncthreads();
    }

#pragma unroll
    for (int i = 0; i < 4; i++) {
        int gm = bm + tr * 4 + i;
        if (gm >= M) continue;
#pragma unroll
        for (int j2 = 0; j2 < 2; j2++) {
            float lo, hi;
            upk2(acc[i][j2], lo, hi);
            float vals[2] = {lo, hi};
#pragma unroll
            for (int u = 0; u < 2; u++) {
                int gn = bn + tc * 4 + j2 * 2 + u;
                if (gn < N) {
                    float v = vals[u] + (bias ? bias[gn] : 0.f);
                    if (ACT == 1) v = softplus_f(v);
                    C[(size_t)gm * N + gn] = v;
                }
            }
        }
    }
}

// ---- wrapper kernels binding scratch globals --------------------------------
__global__ void gemm_hbow(const float* __restrict__ W, const float* __restrict__ b) {
    gemm64_body<1, true>(g_e1, W, b, g_hbow, Bb, Ee, Ee);
}
__global__ void gemm_q(const float* __restrict__ W, const float* __restrict__ b) {
    gemm64_body<0, true>(g_hbow, W, b, g_q, Bb, Dd, Ee);
}
__global__ void gemm_qk(const float* __restrict__ W) {
    gemm64_body<0, false>(g_q, W, nullptr, g_qk, Bb, Dd, Dd);
}
__global__ void gemm_di(const float* __restrict__ W, const float* __restrict__ b) {
    gemm64_body<0, true>(g_ebar, W, b, g_di, Bb, Dd, Dd);
}
__global__ void gemm_mu(const float* __restrict__ W, const float* __restrict__ b) {
    gemm64_body<0, true>(g_di, W, b, g_mu, Bb, Tt, Dd);
}
__global__ void gemm_lv(const float* __restrict__ W, const float* __restrict__ b) {
    gemm64_body<0, true>(g_di, W, b, g_lv, Bb, Tt, Dd);
}
__global__ void gemm_logit(const float* __restrict__ W, const float* __restrict__ b) {
    gemm64_body<0, true>(g_theta, W, b, g_logit, Bb, Vv, Tt);
}

// ---------------- fused ragged single-query attention -----------------------
__global__ void attn_kernel(const float* __restrict__ emb,
                            const float* __restrict__ kb,
                            const int* __restrict__ lengths) {
    const int b = blockIdx.x, tid = threadIdx.x;  // 256 threads
    __shared__ float s_qk[Dd];
    __shared__ float s_sc[Mm];
    __shared__ float red[256];
    __shared__ float s_kbdot;
    const int len = lengths[b];

    float part = 0.f;
    for (int d = tid; d < Dd; d += 256) {
        s_qk[d] = g_qk[b * Dd + d];
        part += g_q[b * Dd + d] * kb[d];
    }
    red[tid] = part;
    __syncthreads();
    for (int s = 128; s > 0; s >>= 1) {
        if (tid < s) red[tid] += red[tid + s];
        __syncthreads();
    }
    if (tid == 0) s_kbdot = red[0];
    __syncthreads();
    const float kbdot = s_kbdot;

    const int wid = tid >> 5, lane = tid & 31;
    const float scale = 0.051031036307982884f;  // 1/sqrt(384)
    for (int m = wid; m < Mm; m += 8) {
        const float* er = emb + ((size_t)b * Mm + m) * Dd;
        float sum = 0.f;
#pragma unroll
        for (int i = 0; i < Dd / 32; i++) {
            int d = lane + 32 * i;
            sum += er[d] * s_qk[d];
        }
#pragma unroll
        for (int o = 16; o > 0; o >>= 1) sum += __shfl_xor_sync(0xffffffffu, sum, o);
        if (lane == 0) s_sc[m] = (m < len) ? (sum + kbdot) * scale : -1e30f;
    }
    __syncthreads();

    if (wid == 0) {
        float v0 = s_sc[lane], v1 = s_sc[lane + 32];
        float mx = fmaxf(v0, v1);
#pragma unroll
        for (int o = 16; o > 0; o >>= 1) mx = fmaxf(mx, __shfl_xor_sync(0xffffffffu, mx, o));
        float e0 = expf(v0 - mx), e1 = expf(v1 - mx);
        float ss = e0 + e1;
#pragma unroll
        for (int o = 16; o > 0; o >>= 1) ss += __shfl_xor_sync(0xffffffffu, ss, o);
        float inv = 1.f / ss;
        s_sc[lane] = e0 * inv;
        s_sc[lane + 32] = e1 * inv;
    }
    __syncthreads();

    for (int d = tid; d < Dd; d += 256) {
        float acc = 0.f;
#pragma unroll 8
        for (int m = 0; m < Mm; m++)
            acc += s_sc[m] * emb[((size_t)b * Mm + m) * Dd + d];
        g_ebar[b * Dd + d] = acc;
    }
}

// ---------------- BatchNorm over batch dim for [B,T], in place --------------
__device__ __forceinline__ void bn_cols_body(float* __restrict__ h,
                                             const float* __restrict__ bias) {
    const int t = blockIdx.x;
    const int tid = threadIdx.x;  // 256
    __shared__ float red[256];
    __shared__ float s_mu, s_inv;
    float v0 = h[(size_t)tid * Tt + t];
    float v1 = h[(size_t)(tid + 256) * Tt + t];
    red[tid] = v0 + v1;
    __syncthreads();
    for (int s = 128; s > 0; s >>= 1) {
        if (tid < s) red[tid] += red[tid + s];
        __syncthreads();
    }
    if (tid == 0) s_mu = red[0] * (1.f / Bb);
    __syncthreads();
    float mu = s_mu;
    float d0 = v0 - mu, d1 = v1 - mu;
    red[tid] = d0 * d0 + d1 * d1;
    __syncthreads();
    for (int s = 128; s > 0; s >>= 1) {
        if (tid < s) red[tid] += red[tid + s];
        __syncthreads();
    }
    if (tid == 0) s_inv = rsqrtf(red[0] * (1.f / Bb) + 1e-5f);
    __syncthreads();
    float inv = s_inv, bbv = bias[t];
    h[(size_t)tid * Tt + t] = d0 * inv + bbv;
    h[(size_t)(tid + 256) * Tt + t] = d1 * inv + bbv;
}
__global__ void bn_mu(const float* __restrict__ bias) { bn_cols_body(g_mu, bias); }
__global__ void bn_lv(const float* __restrict__ bias) { bn_cols_body(g_lv, bias); }

// ---------------- theta = softmax(mu), kl per sample -------------------------
__global__ void theta_kl_kernel() {
    const int b = blockIdx.x, tid = threadIdx.x;  // 128
    __shared__ float red[128];
    __shared__ float s_mx, s_sum;
    const bool ok = tid < Tt;
    const float m = ok ? g_mu[b * Tt + tid] : -1e30f;
    const float l = ok ? g_lv[b * Tt + tid] : 0.f;
    red[tid] = m;
    __syncthreads();
    for (int s = 64; s > 0; s >>= 1) {
        if (tid < s) red[tid] = fmaxf(red[tid], red[tid + s]);
        __syncthreads();
    }
    if (tid == 0) s_mx = red[0];
    __syncthreads();
    const float e = ok ? expf(m - s_mx) : 0.f;
    red[tid] = e;
    __syncthreads();
    for (int s = 64; s > 0; s >>= 1) {
        if (tid < s) red[tid] += red[tid + s];
        __syncthreads();
    }
    if (tid == 0) s_sum = red[0];
    __syncthreads();
    if (ok) g_theta[b * Tt + tid] = e / s_sum;

    const float INV_VAR2 = 1.0101010101010102f;    // 1/(1 - 1/T), T=100
    const float LOGV2 = -0.010050335853501441f;    // log(0.99)
    float term = ok ? (expf(l) * INV_VAR2 + m * m * INV_VAR2 + LOGV2 - l) : 0.f;
    red[tid] = term;
    __syncthreads();
    for (int s = 64; s > 0; s >>= 1) {
        if (tid < s) red[tid] += red[tid + s];
        __syncthreads();
    }
    if (tid == 0) g_kl[b] = 0.5f * (red[0] - (float)Tt);
}

// ---------------- per-vocab-column batch stats of logit ---------------------
__global__ void colstats_kernel() {
    const int v = blockIdx.x * blockDim.x + threadIdx.x;
    if (v >= Vv) return;
    float s = 0.f;
    for (int b = 0; b < Bb; b++) s += g_logit[(size_t)b * Vv + v];
    const float mean = s * (1.f / Bb);
    float var = 0.f;
    for (int b = 0; b < Bb; b++) {
        float d = g_logit[(size_t)b * Vv + v] - mean;
        var += d * d;
    }
    g_colmu[v] = mean;
    g_colinv[v] = rsqrtf(var * (1.f / Bb) + 1e-5f);
}

// ---------------- per-sample reconstruction loss -----------------------------
__global__ void recon_kernel(const float* __restrict__ bnb,
                             const float* __restrict__ x) {
    const int b = blockIdx.x, tid = threadIdx.x;  // 256
    __shared__ float s_m[256], s_s[256], s_xh[256], s_x[256];
    float mx = -1e30f, sm = 0.f, xh = 0.f, xs = 0.f;
    for (int v = tid; v < Vv; v += 256) {
        float hn = (g_logit[(size_t)b * Vv + v] - g_colmu[v]) * g_colinv[v] + bnb[v];
        float xv = x[(size_t)b * Vv + v];
        xh += xv * hn;
        xs += xv;
        float nm = fmaxf(mx, hn);
        sm = sm * expf(mx - nm) + expf(hn - nm);
        mx = nm;
    }
    s_m[tid] = mx; s_s[tid] = sm; s_xh[tid] = xh; s_x[tid] = xs;
    __syncthreads();
    if (tid == 0) {
        float M = -1e30f;
        for (int i = 0; i < 256; i++) M = fmaxf(M, s_m[i]);
        float S = 0.f, XH = 0.f, XS = 0.f;
        for (int i = 0; i < 256; i++) {
            S += s_s[i] * expf(s_m[i] - M);
            XH += s_xh[i];
            XS += s_x[i];
        }
        float lse = M + logf(S);
        g_recon[b] = lse * XS - XH;
    }
}

// ---------------- final scalar -----------------------------------------------
__global__ void final_reduce(float* __restrict__ out) {
    __shared__ float red[512];
    const int tid = threadIdx.x;
    red[tid] = g_recon[tid] + g_kl[tid];
    __syncthreads();
    for (int s = 256; s > 0; s >>= 1) {
        if (tid < s) red[tid] += red[tid + s];
        __syncthreads();
    }
    if (tid == 0) out[0] = red[0] * (1.f / Bb);
}

// =============================================================================
extern "C" void kernel_launch(void* const* d_in, const int* in_sizes, int n_in,
                              void* d_out, int out_size) {
    (void)in_sizes; (void)n_in; (void)out_size;
    const float* x        = (const float*)d_in[0];
    const float* emb      = (const float*)d_in[1];
    const int*   lengths  = (const int*)d_in[2];
    const float* fc11_w   = (const float*)d_in[3];
    const float* fc11_b   = (const float*)d_in[4];
    const float* fc12_w   = (const float*)d_in[5];
    const float* fc12_b   = (const float*)d_in[6];
    const float* q_w      = (const float*)d_in[7];
    const float* q_b      = (const float*)d_in[8];
    const float* k_w      = (const float*)d_in[9];
    const float* k_b      = (const float*)d_in[10];
    const float* v_w      = (const float*)d_in[11];
    const float* v_b      = (const float*)d_in[12];
    const float* mean_w   = (const float*)d_in[13];
    const float* mean_b   = (const float*)d_in[14];
    const float* logvar_w = (const float*)d_in[15];
    const float* logvar_b = (const float*)d_in[16];
    const float* mean_bn_b   = (const float*)d_in[17];
    const float* logvar_bn_b = (const float*)d_in[18];
    const float* dec_w    = (const float*)d_in[19];
    const float* dec_b    = (const float*)d_in[20];
    const float* dec_bn_b = (const float*)d_in[21];

    fc11_kernel<<<dim3(Ee / 64, Bb / 64, SPLIT), 64>>>(x, fc11_w);
    fc11_reduce<<<(Bb * Ee) / 256, 256>>>(fc11_b);
    gemm_hbow<<<dim3(Ee / 64, Bb / 64), 256>>>(fc12_w, fc12_b);
    gemm_q<<<dim3(Dd / 64, Bb / 64), 256>>>(q_w, q_b);
    gemm_qk<<<dim3(Dd / 64, Bb / 64), 256>>>(k_w);
    attn_kernel<<<Bb, 256>>>(emb, k_b, lengths);
    gemm_di<<<dim3(Dd / 64, Bb / 64), 256>>>(v_w, v_b);
    gemm_mu<<<dim3(2, Bb / 64), 256>>>(mean_w, mean_b);
    gemm_lv<<<dim3(2, Bb / 64), 256>>>(logvar_w, logvar_b);
    bn_mu<<<Tt, 256>>>(mean_bn_b);
    bn_lv<<<Tt, 256>>>(logvar_bn_b);
    theta_kl_kernel<<<Bb, 128>>>();
    gemm_logit<<<dim3((Vv + 63) / 64, Bb / 64), 256>>>(dec_w, dec_b);
    colstats_kernel<<<(Vv + 255) / 256, 256>>>();
    recon_kernel<<<Bb, 256>>>(dec_bn_b, x);
    final_reduce<<<1, Bb>>>((float*)d_out);
}

// round 8
// speedup vs baseline: 1.7095x; 1.7095x over previous
#include <cuda_runtime.h>
#include <cuda_bf16.h>
#include <math.h>
#include <stdint.h>

#define Bb 512
#define Mm 64
#define Vv 20000
#define Ee 1024
#define Dd 384
#define Tt 100
#define SPLIT 8
#define KP 20032            // Vv padded to multiple of 64
#define KTOT 313            // KP / 64

// ---------------- scratch (device globals; no allocations allowed) ----------
__device__ __nv_bfloat16 g_xb[(size_t)Bb * KP];   // 20.5 MB
__device__ __nv_bfloat16 g_wb[(size_t)Ee * KP];   // 41 MB
__device__ float g_part[SPLIT * Bb * Ee];         // 16 MB
__device__ float g_e1[Bb * Ee];
__device__ float g_hbow[Bb * Ee];
__device__ float g_q[Bb * Dd];
__device__ float g_qk[Bb * Dd];
__device__ float g_ebar[Bb * Dd];
__device__ float g_di[Bb * Dd];
__device__ float g_mu[Bb * Tt];
__device__ float g_lv[Bb * Tt];
__device__ float g_theta[Bb * Tt];
__device__ float g_logit[(size_t)Bb * Vv];
__device__ float g_colmu[Vv];
__device__ float g_colinv[Vv];
__device__ float g_recon[Bb];
__device__ float g_kl[Bb];

__device__ __forceinline__ float softplus_f(float x) {
    return x > 0.f ? x + log1pf(expf(-x)) : log1pf(expf(x));
}

// ---------------- fp32 -> bf16 conversion with K padding ---------------------
__global__ void cvt_bf16(const float* __restrict__ src, __nv_bfloat16* __restrict__ dst) {
    const int idx = blockIdx.x * 256 + threadIdx.x;
    const int row = idx / (KP / 8);
    const int cp = (idx % (KP / 8)) * 8;
    __nv_bfloat16 o[8];
    if (cp + 8 <= Vv) {   // Vv % 8 == 0 -> chunks are fully in-bounds or fully pad
        const float4 v0 = *(const float4*)&src[(size_t)row * Vv + cp];
        const float4 v1 = *(const float4*)&src[(size_t)row * Vv + cp + 4];
        o[0] = __float2bfloat16(v0.x); o[1] = __float2bfloat16(v0.y);
        o[2] = __float2bfloat16(v0.z); o[3] = __float2bfloat16(v0.w);
        o[4] = __float2bfloat16(v1.x); o[5] = __float2bfloat16(v1.y);
        o[6] = __float2bfloat16(v1.z); o[7] = __float2bfloat16(v1.w);
    } else {
#pragma unroll
        for (int i = 0; i < 8; i++) o[i] = __float2bfloat16(0.f);
    }
    *(uint4*)&dst[(size_t)row * KP + cp] = *(uint4*)o;
}

// ---------------- warp-level bf16 MMA (arch-neutral PTX, sm_80+) ------------
__device__ __forceinline__ void mma16816(float* c, const uint32_t* a, const uint32_t* b) {
    asm volatile(
        "mma.sync.aligned.m16n8k16.row.col.f32.bf16.bf16.f32 "
        "{%0,%1,%2,%3}, {%4,%5,%6,%7}, {%8,%9}, {%0,%1,%2,%3};"
        : "+f"(c[0]), "+f"(c[1]), "+f"(c[2]), "+f"(c[3])
        : "r"(a[0]), "r"(a[1]), "r"(a[2]), "r"(a[3]), "r"(b[0]), "r"(b[1]));
}

// ===================== fc11 via mma.sync bf16 ================================
// part[s][m][n] += Xb[m, kchunk] @ Wb[n, kchunk]^T
// Block 128x128, BK=64, 8 warps (2x4), warp tile 64x32, 4x4 m16n8k16.
#define PADR 72   // smem row stride in bf16 (64 data + 8 pad) -> conflict-free frags
__global__ __launch_bounds__(256) void fc11_mma() {
    __shared__ __nv_bfloat16 As[128][PADR];
    __shared__ __nv_bfloat16 Bs[128][PADR];
    const int tid = threadIdx.x;
    const int wid = tid >> 5, lane = tid & 31;
    const int wr = wid >> 2, wc = wid & 3;       // warp grid 2x4
    const int l4 = lane >> 2, lq = lane & 3;
    const int bn = blockIdx.x * 128;
    const int bm = blockIdx.y * 128;
    const int s = blockIdx.z;
    const int kt0 = (s * KTOT) / SPLIT, kt1 = ((s + 1) * KTOT) / SPLIT;

    float c[4][4][4];
#pragma unroll
    for (int i = 0; i < 4; i++)
#pragma unroll
        for (int j = 0; j < 4; j++)
#pragma unroll
            for (int u = 0; u < 4; u++) c[i][j][u] = 0.f;

    for (int kt = kt0; kt < kt1; kt++) {
        const int k0 = kt * 64;
        // load 128x64 bf16 tiles of A and B (4 uint4 per thread each)
#pragma unroll
        for (int i = 0; i < 4; i++) {
            const int idx = tid + 256 * i;
            const int row = idx >> 3, ch = idx & 7;
            uint4 va = *(const uint4*)&g_xb[(size_t)(bm + row) * KP + k0 + ch * 8];
            *(uint4*)&As[row][ch * 8] = va;
            uint4 vb = *(const uint4*)&g_wb[(size_t)(bn + row) * KP + k0 + ch * 8];
            *(uint4*)&Bs[row][ch * 8] = vb;
        }
        __syncthreads();

#pragma unroll
        for (int kk = 0; kk < 4; kk++) {
            const int kb = kk * 16 + lq * 2;
            uint32_t a[4][4], b[4][2];
#pragma unroll
            for (int i = 0; i < 4; i++) {
                const int r = wr * 64 + i * 16 + l4;
                a[i][0] = *(const uint32_t*)&As[r][kb];
                a[i][1] = *(const uint32_t*)&As[r + 8][kb];
                a[i][2] = *(const uint32_t*)&As[r][kb + 8];
                a[i][3] = *(const uint32_t*)&As[r + 8][kb + 8];
            }
#pragma unroll
            for (int j = 0; j < 4; j++) {
                const int n = wc * 32 + j * 8 + l4;
                b[j][0] = *(const uint32_t*)&Bs[n][kb];
                b[j][1] = *(const uint32_t*)&Bs[n][kb + 8];
            }
#pragma unroll
            for (int i = 0; i < 4; i++)
#pragma unroll
                for (int j = 0; j < 4; j++) mma16816(c[i][j], a[i], b[j]);
        }
        __syncthreads();
    }

    // store fp32 partials
#pragma unroll
    for (int i = 0; i < 4; i++) {
        const int row0 = bm + wr * 64 + i * 16 + l4;
#pragma unroll
        for (int j = 0; j < 4; j++) {
            const int col = bn + wc * 32 + j * 8 + lq * 2;
            float* p0 = g_part + ((size_t)s * Bb + row0) * Ee + col;
            float* p1 = g_part + ((size_t)s * Bb + row0 + 8) * Ee + col;
            p0[0] = c[i][j][0]; p0[1] = c[i][j][1];
            p1[0] = c[i][j][2]; p1[1] = c[i][j][3];
        }
    }
}

__global__ void fc11_reduce(const float* __restrict__ bias) {
    const int i = blockIdx.x * 256 + threadIdx.x;
    float v = bias[i & (Ee - 1)];
#pragma unroll
    for (int s = 0; s < SPLIT; s++) v += g_part[(size_t)s * (Bb * Ee) + i];
    g_e1[i] = softplus_f(v);
}

// ---------------- packed f32x2 helpers --------------------------------------
__device__ __forceinline__ unsigned long long pk2(float x, float y) {
    unsigned long long r;
    asm("mov.b64 %0, {%1, %2};" : "=l"(r) : "f"(x), "f"(y));
    return r;
}
__device__ __forceinline__ unsigned long long fma2(unsigned long long a,
                                                   unsigned long long b,
                                                   unsigned long long c) {
    unsigned long long d;
    asm("fma.rn.f32x2 %0, %1, %2, %3;" : "=l"(d) : "l"(a), "l"(b), "l"(c));
    return d;
}
__device__ __forceinline__ void upk2(unsigned long long v, float& lo, float& hi) {
    asm("mov.b64 {%0, %1}, %2;" : "=f"(lo), "=f"(hi) : "l"(v));
}

// ---------------- generic GEMM body with register double-buffering ----------
template <int ACT, bool BNT>
__device__ __forceinline__ void gemm64_body(const float* __restrict__ A,
                                            const float* __restrict__ Bm,
                                            const float* __restrict__ bias,
                                            float* __restrict__ C,
                                            int M, int N, int K) {
    __shared__ float As[16][64];
    __shared__ float Bs[16][64];
    const int bm = blockIdx.y * 64, bn = blockIdx.x * 64;
    const int tid = threadIdx.x;
    const int tr = tid >> 4, tc = tid & 15;
    const int lrow = tid >> 4;
    const int lk = tid & 15;

    unsigned long long acc[4][2];
#pragma unroll
    for (int i = 0; i < 4; i++) { acc[i][0] = 0ull; acc[i][1] = 0ull; }

    float pa[4], pb[4], na[4], nb[4];

#pragma unroll
    for (int i = 0; i < 4; i++) {
        int r = lrow + i * 16;
        int gk = lk;
        int gm = bm + r;
        pa[i] = (gm < M && gk < K) ? A[(size_t)gm * K + gk] : 0.f;
        int gn = bn + r;
        float v = 0.f;
        if (gn < N && gk < K)
            v = BNT ? Bm[(size_t)gn * K + gk] : Bm[(size_t)gk * N + gn];
        pb[i] = v;
    }

    for (int k0 = 0; k0 < K; k0 += 16) {
#pragma unroll
        for (int i = 0; i < 4; i++) {
            int r = lrow + i * 16;
            As[lk][r] = pa[i];
            Bs[lk][r] = pb[i];
        }
        __syncthreads();

        if (k0 + 16 < K) {
#pragma unroll
            for (int i = 0; i < 4; i++) {
                int r = lrow + i * 16;
                int gk = k0 + 16 + lk;
                int gm = bm + r;
                na[i] = (gm < M && gk < K) ? A[(size_t)gm * K + gk] : 0.f;
                int gn = bn + r;
                float v = 0.f;
                if (gn < N && gk < K)
                    v = BNT ? Bm[(size_t)gn * K + gk] : Bm[(size_t)gk * N + gn];
                nb[i] = v;
            }
        }

#pragma unroll
        for (int kk = 0; kk < 16; kk++) {
            float a0 = As[kk][tr * 4 + 0];
            float a1 = As[kk][tr * 4 + 1];
            float a2 = As[kk][tr * 4 + 2];
            float a3 = As[kk][tr * 4 + 3];
            unsigned long long b0 =
                *reinterpret_cast<const unsigned long long*>(&Bs[kk][tc * 4]);
            unsigned long long b1 =
                *reinterpret_cast<const unsigned long long*>(&Bs[kk][tc * 4 + 2]);
            unsigned long long A0 = pk2(a0, a0), A1 = pk2(a1, a1);
            unsigned long long A2 = pk2(a2, a2), A3 = pk2(a3, a3);
            acc[0][0] = fma2(A0, b0, acc[0][0]); acc[0][1] = fma2(A0, b1, acc[0][1]);
            acc[1][0] = fma2(A1, b0, acc[1][0]); acc[1][1] = fma2(A1, b1, acc[1][1]);
            acc[2][0] = fma2(A2, b0, acc[2][0]); acc[2][1] = fma2(A2, b1, acc[2][1]);
            acc[3][0] = fma2(A3, b0, acc[3][0]); acc[3][1] = fma2(A3, b1, acc[3][1]);
        }
        __syncthreads();
#pragma unroll
        for (int i = 0; i < 4; i++) { pa[i] = na[i]; pb[i] = nb[i]; }
    }

#pragma unroll
    for (int i = 0; i < 4; i++) {
        int gm = bm + tr * 4 + i;
        if (gm >= M) continue;
#pragma unroll
        for (int j2 = 0; j2 < 2; j2++) {
            float lo, hi;
            upk2(acc[i][j2], lo, hi);
            float vals[2] = {lo, hi};
#pragma unroll
            for (int u = 0; u < 2; u++) {
                int gn = bn + tc * 4 + j2 * 2 + u;
                if (gn < N) {
                    float v = vals[u] + (bias ? bias[gn] : 0.f);
                    if (ACT == 1) v = softplus_f(v);
                    C[(size_t)gm * N + gn] = v;
                }
            }
        }
    }
}

// ---- wrapper kernels binding scratch globals --------------------------------
__global__ void gemm_hbow(const float* __restrict__ W, const float* __restrict__ b) {
    gemm64_body<1, true>(g_e1, W, b, g_hbow, Bb, Ee, Ee);
}
__global__ void gemm_q(const float* __restrict__ W, const float* __restrict__ b) {
    gemm64_body<0, true>(g_hbow, W, b, g_q, Bb, Dd, Ee);
}
__global__ void gemm_qk(const float* __restrict__ W) {
    gemm64_body<0, false>(g_q, W, nullptr, g_qk, Bb, Dd, Dd);
}
__global__ void gemm_di(const float* __restrict__ W, const float* __restrict__ b) {
    gemm64_body<0, true>(g_ebar, W, b, g_di, Bb, Dd, Dd);
}
__global__ void gemm_mu(const float* __restrict__ W, const float* __restrict__ b) {
    gemm64_body<0, true>(g_di, W, b, g_mu, Bb, Tt, Dd);
}
__global__ void gemm_lv(const float* __restrict__ W, const float* __restrict__ b) {
    gemm64_body<0, true>(g_di, W, b, g_lv, Bb, Tt, Dd);
}
__global__ void gemm_logit(const float* __restrict__ W, const float* __restrict__ b) {
    gemm64_body<0, true>(g_theta, W, b, g_logit, Bb, Vv, Tt);
}

// ---------------- fused ragged single-query attention -----------------------
__global__ void attn_kernel(const float* __restrict__ emb,
                            const float* __restrict__ kb,
                            const int* __restrict__ lengths) {
    const int b = blockIdx.x, tid = threadIdx.x;  // 256 threads
    __shared__ float s_qk[Dd];
    __shared__ float s_sc[Mm];
    __shared__ float red[256];
    __shared__ float s_kbdot;
    const int len = lengths[b];

    float part = 0.f;
    for (int d = tid; d < Dd; d += 256) {
        s_qk[d] = g_qk[b * Dd + d];
        part += g_q[b * Dd + d] * kb[d];
    }
    red[tid] = part;
    __syncthreads();
    for (int s = 128; s > 0; s >>= 1) {
        if (tid < s) red[tid] += red[tid + s];
        __syncthreads();
    }
    if (tid == 0) s_kbdot = red[0];
    __syncthreads();
    const float kbdot = s_kbdot;

    const int wid = tid >> 5, lane = tid & 31;
    const float scale = 0.051031036307982884f;  // 1/sqrt(384)
    for (int m = wid; m < Mm; m += 8) {
        const float* er = emb + ((size_t)b * Mm + m) * Dd;
        float sum = 0.f;
#pragma unroll
        for (int i = 0; i < Dd / 32; i++) {
            int d = lane + 32 * i;
            sum += er[d] * s_qk[d];
        }
#pragma unroll
        for (int o = 16; o > 0; o >>= 1) sum += __shfl_xor_sync(0xffffffffu, sum, o);
        if (lane == 0) s_sc[m] = (m < len) ? (sum + kbdot) * scale : -1e30f;
    }
    __syncthreads();

    if (wid == 0) {
        float v0 = s_sc[lane], v1 = s_sc[lane + 32];
        float mx = fmaxf(v0, v1);
#pragma unroll
        for (int o = 16; o > 0; o >>= 1) mx = fmaxf(mx, __shfl_xor_sync(0xffffffffu, mx, o));
        float e0 = expf(v0 - mx), e1 = expf(v1 - mx);
        float ss = e0 + e1;
#pragma unroll
        for (int o = 16; o > 0; o >>= 1) ss += __shfl_xor_sync(0xffffffffu, ss, o);
        float inv = 1.f / ss;
        s_sc[lane] = e0 * inv;
        s_sc[lane + 32] = e1 * inv;
    }
    __syncthreads();

    for (int d = tid; d < Dd; d += 256) {
        float acc = 0.f;
#pragma unroll 8
        for (int m = 0; m < Mm; m++)
            acc += s_sc[m] * emb[((size_t)b * Mm + m) * Dd + d];
        g_ebar[b * Dd + d] = acc;
    }
}

// ---------------- BatchNorm over batch dim for [B,T], in place --------------
__device__ __forceinline__ void bn_cols_body(float* __restrict__ h,
                                             const float* __restrict__ bias) {
    const int t = blockIdx.x;
    const int tid = threadIdx.x;  // 256
    __shared__ float red[256];
    __shared__ float s_mu, s_inv;
    float v0 = h[(size_t)tid * Tt + t];
    float v1 = h[(size_t)(tid + 256) * Tt + t];
    red[tid] = v0 + v1;
    __syncthreads();
    for (int s = 128; s > 0; s >>= 1) {
        if (tid < s) red[tid] += red[tid + s];
        __syncthreads();
    }
    if (tid == 0) s_mu = red[0] * (1.f / Bb);
    __syncthreads();
    float mu = s_mu;
    float d0 = v0 - mu, d1 = v1 - mu;
    red[tid] = d0 * d0 + d1 * d1;
    __syncthreads();
    for (int s = 128; s > 0; s >>= 1) {
        if (tid < s) red[tid] += red[tid + s];
        __syncthreads();
    }
    if (tid == 0) s_inv = rsqrtf(red[0] * (1.f / Bb) + 1e-5f);
    __syncthreads();
    float inv = s_inv, bbv = bias[t];
    h[(size_t)tid * Tt + t] = d0 * inv + bbv;
    h[(size_t)(tid + 256) * Tt + t] = d1 * inv + bbv;
}
__global__ void bn_mu(const float* __restrict__ bias) { bn_cols_body(g_mu, bias); }
__global__ void bn_lv(const float* __restrict__ bias) { bn_cols_body(g_lv, bias); }

// ---------------- theta = softmax(mu), kl per sample -------------------------
__global__ void theta_kl_kernel() {
    const int b = blockIdx.x, tid = threadIdx.x;  // 128
    __shared__ float red[128];
    __shared__ float s_mx, s_sum;
    const bool ok = tid < Tt;
    const float m = ok ? g_mu[b * Tt + tid] : -1e30f;
    const float l = ok ? g_lv[b * Tt + tid] : 0.f;
    red[tid] = m;
    __syncthreads();
    for (int s = 64; s > 0; s >>= 1) {
        if (tid < s) red[tid] = fmaxf(red[tid], red[tid + s]);
        __syncthreads();
    }
    if (tid == 0) s_mx = red[0];
    __syncthreads();
    const float e = ok ? expf(m - s_mx) : 0.f;
    red[tid] = e;
    __syncthreads();
    for (int s = 64; s > 0; s >>= 1) {
        if (tid < s) red[tid] += red[tid + s];
        __syncthreads();
    }
    if (tid == 0) s_sum = red[0];
    __syncthreads();
    if (ok) g_theta[b * Tt + tid] = e / s_sum;

    const float INV_VAR2 = 1.0101010101010102f;    // 1/(1 - 1/T), T=100
    const float LOGV2 = -0.010050335853501441f;    // log(0.99)
    float term = ok ? (expf(l) * INV_VAR2 + m * m * INV_VAR2 + LOGV2 - l) : 0.f;
    red[tid] = term;
    __syncthreads();
    for (int s = 64; s > 0; s >>= 1) {
        if (tid < s) red[tid] += red[tid + s];
        __syncthreads();
    }
    if (tid == 0) g_kl[b] = 0.5f * (red[0] - (float)Tt);
}

// ---------------- per-vocab-column batch stats of logit (single pass) -------
__global__ void colstats_kernel() {
    const int v = blockIdx.x * blockDim.x + threadIdx.x;
    if (v >= Vv) return;
    float s = 0.f, s2 = 0.f;
#pragma unroll 8
    for (int b = 0; b < Bb; b++) {
        float x = g_logit[(size_t)b * Vv + v];
        s += x;
        s2 += x * x;
    }
    const float mean = s * (1.f / Bb);
    float var = fmaxf(s2 * (1.f / Bb) - mean * mean, 0.f);
    g_colmu[v] = mean;
    g_colinv[v] = rsqrtf(var + 1e-5f);
}

// ---------------- per-sample reconstruction loss -----------------------------
__global__ void recon_kernel(const float* __restrict__ bnb,
                             const float* __restrict__ x) {
    const int b = blockIdx.x, tid = threadIdx.x;  // 256
    __shared__ float s_m[256], s_s[256], s_xh[256], s_x[256];
    float mx = -1e30f, sm = 0.f, xh = 0.f, xs = 0.f;
    for (int v = tid; v < Vv; v += 256) {
        float hn = (g_logit[(size_t)b * Vv + v] - g_colmu[v]) * g_colinv[v] + bnb[v];
        float xv = x[(size_t)b * Vv + v];
        xh += xv * hn;
        xs += xv;
        float nm = fmaxf(mx, hn);
        sm = sm * expf(mx - nm) + expf(hn - nm);
        mx = nm;
    }
    s_m[tid] = mx; s_s[tid] = sm; s_xh[tid] = xh; s_x[tid] = xs;
    __syncthreads();
    if (tid == 0) {
        float M = -1e30f;
        for (int i = 0; i < 256; i++) M = fmaxf(M, s_m[i]);
        float S = 0.f, XH = 0.f, XS = 0.f;
        for (int i = 0; i < 256; i++) {
            S += s_s[i] * expf(s_m[i] - M);
            XH += s_xh[i];
            XS += s_x[i];
        }
        float lse = M + logf(S);
        g_recon[b] = lse * XS - XH;
    }
}

// ---------------- final scalar -----------------------------------------------
__global__ void final_reduce(float* __restrict__ out) {
    __shared__ float red[512];
    const int tid = threadIdx.x;
    red[tid] = g_recon[tid] + g_kl[tid];
    __syncthreads();
    for (int s = 256; s > 0; s >>= 1) {
        if (tid < s) red[tid] += red[tid + s];
        __syncthreads();
    }
    if (tid == 0) out[0] = red[0] * (1.f / Bb);
}

// =============================================================================
extern "C" void kernel_launch(void* const* d_in, const int* in_sizes, int n_in,
                              void* d_out, int out_size) {
    (void)in_sizes; (void)n_in; (void)out_size;
    const float* x        = (const float*)d_in[0];
    const float* emb      = (const float*)d_in[1];
    const int*   lengths  = (const int*)d_in[2];
    const float* fc11_w   = (const float*)d_in[3];
    const float* fc11_b   = (const float*)d_in[4];
    const float* fc12_w   = (const float*)d_in[5];
    const float* fc12_b   = (const float*)d_in[6];
    const float* q_w      = (const float*)d_in[7];
    const float* q_b      = (const float*)d_in[8];
    const float* k_w      = (const float*)d_in[9];
    const float* k_b      = (const float*)d_in[10];
    const float* v_w      = (const float*)d_in[11];
    const float* v_b      = (const float*)d_in[12];
    const float* mean_w   = (const float*)d_in[13];
    const float* mean_b   = (const float*)d_in[14];
    const float* logvar_w = (const float*)d_in[15];
    const float* logvar_b = (const float*)d_in[16];
    const float* mean_bn_b   = (const float*)d_in[17];
    const float* logvar_bn_b = (const float*)d_in[18];
    const float* dec_w    = (const float*)d_in[19];
    const float* dec_b    = (const float*)d_in[20];
    const float* dec_bn_b = (const float*)d_in[21];

    __nv_bfloat16* xb;
    __nv_bfloat16* wb;
    cudaGetSymbolAddress((void**)&xb, g_xb);
    cudaGetSymbolAddress((void**)&wb, g_wb);

    // 0. convert x and fc11_w to padded bf16
    cvt_bf16<<<(Bb * (KP / 8)) / 256, 256>>>(x, xb);
    cvt_bf16<<<(Ee * (KP / 8)) / 256, 256>>>(fc11_w, wb);
    // 1. fc11 via mma.sync bf16, split-K partials + reduce
    fc11_mma<<<dim3(Ee / 128, Bb / 128, SPLIT), 256>>>();
    fc11_reduce<<<(Bb * Ee) / 256, 256>>>(fc11_b);
    // 2..: rest of the network
    gemm_hbow<<<dim3(Ee / 64, Bb / 64), 256>>>(fc12_w, fc12_b);
    gemm_q<<<dim3(Dd / 64, Bb / 64), 256>>>(q_w, q_b);
    gemm_qk<<<dim3(Dd / 64, Bb / 64), 256>>>(k_w);
    attn_kernel<<<Bb, 256>>>(emb, k_b, lengths);
    gemm_di<<<dim3(Dd / 64, Bb / 64), 256>>>(v_w, v_b);
    gemm_mu<<<dim3(2, Bb / 64), 256>>>(mean_w, mean_b);
    gemm_lv<<<dim3(2, Bb / 64), 256>>>(logvar_w, logvar_b);
    bn_mu<<<Tt, 256>>>(mean_bn_b);
    bn_lv<<<Tt, 256>>>(logvar_bn_b);
    theta_kl_kernel<<<Bb, 128>>>();
    gemm_logit<<<dim3((Vv + 63) / 64, Bb / 64), 256>>>(dec_w, dec_b);
    colstats_kernel<<<(Vv + 255) / 256, 256>>>();
    recon_kernel<<<Bb, 256>>>(dec_bn_b, x);
    final_reduce<<<1, Bb>>>((float*)d_out);
}

// round 9
// speedup vs baseline: 2.0793x; 1.2163x over previous
#include <cuda_runtime.h>
#include <cuda_bf16.h>
#include <math.h>
#include <stdint.h>

#define Bb 512
#define Mm 64
#define Vv 20000
#define Ee 1024
#define Dd 384
#define Tt 100
#define SPLIT 8
#define KP 20032            // Vv padded to multiple of 64
#define KTOT 313            // KP / 64

// ---------------- scratch (device globals; no allocations allowed) ----------
__device__ __nv_bfloat16 g_xb[(size_t)Bb * KP];   // 20.5 MB
__device__ __nv_bfloat16 g_wb[(size_t)Ee * KP];   // 41 MB
__device__ float g_part[SPLIT * Bb * Ee];         // 16 MB
__device__ __nv_bfloat16 g_e1b[Bb * Ee];
__device__ __nv_bfloat16 g_fc12b[Ee * Ee];
__device__ __nv_bfloat16 g_qwb[Dd * Ee];
__device__ __nv_bfloat16 g_hbowb[Bb * Ee];
__device__ float g_hbow[Bb * Ee];
__device__ float g_q[Bb * Dd];
__device__ float g_qk[Bb * Dd];
__device__ float g_ebar[Bb * Dd];
__device__ float g_di[Bb * Dd];
__device__ float g_mu[Bb * Tt];
__device__ float g_lv[Bb * Tt];
__device__ float g_theta[Bb * Tt];
__device__ float g_logit[(size_t)Bb * Vv];
__device__ float g_colmu[Vv];
__device__ float g_colinv[Vv];
__device__ float g_recon[Bb];
__device__ float g_kl[Bb];

__device__ __forceinline__ float softplus_f(float x) {
    return x > 0.f ? x + log1pf(expf(-x)) : log1pf(expf(x));
}
__device__ __forceinline__ uint32_t smem_u32(const void* p) {
    uint32_t a;
    asm("{ .reg .u64 t; cvta.to.shared.u64 t, %1; cvt.u32.u64 %0, t; }"
        : "=r"(a) : "l"(p));
    return a;
}
__device__ __forceinline__ uint32_t lds32(uint32_t addr) {
    uint32_t v;
    asm volatile("ld.shared.b32 %0, [%1];" : "=r"(v) : "r"(addr));
    return v;
}

// ---------------- fp32 -> bf16 conversions -----------------------------------
__global__ void cvt_bf16(const float* __restrict__ src, __nv_bfloat16* __restrict__ dst) {
    const int idx = blockIdx.x * 256 + threadIdx.x;
    const int row = idx / (KP / 8);
    const int cp = (idx % (KP / 8)) * 8;
    __nv_bfloat16 o[8];
    if (cp + 8 <= Vv) {
        const float4 v0 = *(const float4*)&src[(size_t)row * Vv + cp];
        const float4 v1 = *(const float4*)&src[(size_t)row * Vv + cp + 4];
        o[0] = __float2bfloat16(v0.x); o[1] = __float2bfloat16(v0.y);
        o[2] = __float2bfloat16(v0.z); o[3] = __float2bfloat16(v0.w);
        o[4] = __float2bfloat16(v1.x); o[5] = __float2bfloat16(v1.y);
        o[6] = __float2bfloat16(v1.z); o[7] = __float2bfloat16(v1.w);
    } else {
#pragma unroll
        for (int i = 0; i < 8; i++) o[i] = __float2bfloat16(0.f);
    }
    *(uint4*)&dst[(size_t)row * KP + cp] = *(uint4*)o;
}

__global__ void cvt_plain(const float* __restrict__ src, __nv_bfloat16* __restrict__ dst) {
    const int i = (blockIdx.x * 256 + threadIdx.x) * 8;
    const float4 v0 = *(const float4*)&src[i];
    const float4 v1 = *(const float4*)&src[i + 4];
    __nv_bfloat16 o[8];
    o[0] = __float2bfloat16(v0.x); o[1] = __float2bfloat16(v0.y);
    o[2] = __float2bfloat16(v0.z); o[3] = __float2bfloat16(v0.w);
    o[4] = __float2bfloat16(v1.x); o[5] = __float2bfloat16(v1.y);
    o[6] = __float2bfloat16(v1.z); o[7] = __float2bfloat16(v1.w);
    *(uint4*)&dst[i] = *(uint4*)o;
}

// ---------------- warp-level bf16 MMA (arch-neutral PTX, sm_80+) ------------
__device__ __forceinline__ void mma16816(float* c, const uint32_t* a, const uint32_t* b) {
    asm volatile(
        "mma.sync.aligned.m16n8k16.row.col.f32.bf16.bf16.f32 "
        "{%0,%1,%2,%3}, {%4,%5,%6,%7}, {%8,%9}, {%0,%1,%2,%3};"
        : "+f"(c[0]), "+f"(c[1]), "+f"(c[2]), "+f"(c[3])
        : "r"(a[0]), "r"(a[1]), "r"(a[2]), "r"(a[3]), "r"(b[0]), "r"(b[1]));
}

// ===================== fc11 via cp.async 2-stage + mma.sync ==================
// XOR-swizzled layout: element (row, bf16col kb) at byte
//   row*128 + (((kb*2)>>4 ^ (row&7))<<4) + ((kb*2)&15)
// Stage st: A at dyn + st*32768, B at +16384. 64KB dynamic smem total.
__device__ __forceinline__ void fc11_load_stage(uint32_t sbase, int st, int kt,
                                                int bm, int bn, int tid) {
    const int k0 = kt * 64;
    const uint32_t abase = sbase + st * 32768;
    const uint32_t bbase = abase + 16384;
#pragma unroll
    for (int i = 0; i < 4; i++) {
        const int idx = tid + 256 * i;
        const int row = idx >> 3, ch = idx & 7;
        const uint32_t off = (uint32_t)row * 128u + (uint32_t)((ch ^ (row & 7)) << 4);
        const void* asrc = &g_xb[(size_t)(bm + row) * KP + k0 + ch * 8];
        asm volatile("cp.async.cg.shared.global [%0], [%1], 16;"
                     :: "r"(abase + off), "l"(asrc));
        const void* bsrc = &g_wb[(size_t)(bn + row) * KP + k0 + ch * 8];
        asm volatile("cp.async.cg.shared.global [%0], [%1], 16;"
                     :: "r"(bbase + off), "l"(bsrc));
    }
    asm volatile("cp.async.commit_group;");
}

__device__ __forceinline__ uint32_t swz(uint32_t row, uint32_t bytecol) {
    return row * 128u + ((((bytecol >> 4) ^ (row & 7u))) << 4) + (bytecol & 15u);
}

__global__ __launch_bounds__(256, 2) void fc11_mma2() {
    extern __shared__ char dynsmem[];
    const uint32_t sbase = smem_u32(dynsmem);
    const int tid = threadIdx.x;
    const int wid = tid >> 5, lane = tid & 31;
    const int wr = wid >> 2, wc = wid & 3;
    const int l4 = lane >> 2, lq = lane & 3;
    const int bn = blockIdx.x * 128;
    const int bm = blockIdx.y * 128;
    const int s = blockIdx.z;
    const int kt0 = (s * KTOT) / SPLIT, kt1 = ((s + 1) * KTOT) / SPLIT;
    const int niter = kt1 - kt0;

    float c[4][4][4];
#pragma unroll
    for (int i = 0; i < 4; i++)
#pragma unroll
        for (int j = 0; j < 4; j++)
#pragma unroll
            for (int u = 0; u < 4; u++) c[i][j][u] = 0.f;

    fc11_load_stage(sbase, 0, kt0, bm, bn, tid);

    for (int t = 0; t < niter; t++) {
        if (t + 1 < niter) {
            fc11_load_stage(sbase, (t + 1) & 1, kt0 + t + 1, bm, bn, tid);
            asm volatile("cp.async.wait_group 1;");
        } else {
            asm volatile("cp.async.wait_group 0;");
        }
        __syncthreads();

        const uint32_t abase = sbase + (t & 1) * 32768;
        const uint32_t bbase = abase + 16384;
#pragma unroll
        for (int kk = 0; kk < 4; kk++) {
            const uint32_t bytecol = (uint32_t)(kk * 32 + lq * 4);
            uint32_t a[4][4], b[4][2];
#pragma unroll
            for (int i = 0; i < 4; i++) {
                const uint32_t r = (uint32_t)(wr * 64 + i * 16 + l4);
                a[i][0] = lds32(abase + swz(r, bytecol));
                a[i][1] = lds32(abase + swz(r + 8, bytecol));
                a[i][2] = lds32(abase + swz(r, bytecol + 16));
                a[i][3] = lds32(abase + swz(r + 8, bytecol + 16));
            }
#pragma unroll
            for (int j = 0; j < 4; j++) {
                const uint32_t n = (uint32_t)(wc * 32 + j * 8 + l4);
                b[j][0] = lds32(bbase + swz(n, bytecol));
                b[j][1] = lds32(bbase + swz(n, bytecol + 16));
            }
#pragma unroll
            for (int i = 0; i < 4; i++)
#pragma unroll
                for (int j = 0; j < 4; j++) mma16816(c[i][j], a[i], b[j]);
        }
        __syncthreads();
    }

#pragma unroll
    for (int i = 0; i < 4; i++) {
        const int row0 = bm + wr * 64 + i * 16 + l4;
#pragma unroll
        for (int j = 0; j < 4; j++) {
            const int col = bn + wc * 32 + j * 8 + lq * 2;
            float* p0 = g_part + ((size_t)s * Bb + row0) * Ee + col;
            float* p1 = g_part + ((size_t)s * Bb + row0 + 8) * Ee + col;
            p0[0] = c[i][j][0]; p0[1] = c[i][j][1];
            p1[0] = c[i][j][2]; p1[1] = c[i][j][3];
        }
    }
}

__global__ void fc11_reduce(const float* __restrict__ bias) {
    const int i = blockIdx.x * 256 + threadIdx.x;
    float v = bias[i & (Ee - 1)];
#pragma unroll
    for (int s = 0; s < SPLIT; s++) v += g_part[(size_t)s * (Bb * Ee) + i];
    g_e1b[i] = __float2bfloat16(softplus_f(v));
}

// ===================== generic bf16 mma GEMM (single-buffer, PADR) ===========
// C[M,N] = act(A[M,K] @ W[N,K]^T + bias); M,N multiples of 128, K of 64.
#define PADR 72
template <int ACT, int WRITEB>
__global__ __launch_bounds__(256) void mma_gemm(const __nv_bfloat16* __restrict__ A,
                                                const __nv_bfloat16* __restrict__ W,
                                                const float* __restrict__ bias,
                                                float* __restrict__ C,
                                                __nv_bfloat16* __restrict__ Cb,
                                                int N, int K) {
    __shared__ __nv_bfloat16 As[128][PADR];
    __shared__ __nv_bfloat16 Bs[128][PADR];
    const int tid = threadIdx.x;
    const int wid = tid >> 5, lane = tid & 31;
    const int wr = wid >> 2, wc = wid & 3;
    const int l4 = lane >> 2, lq = lane & 3;
    const int bn = blockIdx.x * 128;
    const int bm = blockIdx.y * 128;

    float c[4][4][4];
#pragma unroll
    for (int i = 0; i < 4; i++)
#pragma unroll
        for (int j = 0; j < 4; j++)
#pragma unroll
            for (int u = 0; u < 4; u++) c[i][j][u] = 0.f;

    for (int k0 = 0; k0 < K; k0 += 64) {
#pragma unroll
        for (int i = 0; i < 4; i++) {
            const int idx = tid + 256 * i;
            const int row = idx >> 3, ch = idx & 7;
            uint4 va = *(const uint4*)&A[(size_t)(bm + row) * K + k0 + ch * 8];
            *(uint4*)&As[row][ch * 8] = va;
            uint4 vb = *(const uint4*)&W[(size_t)(bn + row) * K + k0 + ch * 8];
            *(uint4*)&Bs[row][ch * 8] = vb;
        }
        __syncthreads();

#pragma unroll
        for (int kk = 0; kk < 4; kk++) {
            const int kb = kk * 16 + lq * 2;
            uint32_t a[4][4], b[4][2];
#pragma unroll
            for (int i = 0; i < 4; i++) {
                const int r = wr * 64 + i * 16 + l4;
                a[i][0] = *(const uint32_t*)&As[r][kb];
                a[i][1] = *(const uint32_t*)&As[r + 8][kb];
                a[i][2] = *(const uint32_t*)&As[r][kb + 8];
                a[i][3] = *(const uint32_t*)&As[r + 8][kb + 8];
            }
#pragma unroll
            for (int j = 0; j < 4; j++) {
                const int n = wc * 32 + j * 8 + l4;
                b[j][0] = *(const uint32_t*)&Bs[n][kb];
                b[j][1] = *(const uint32_t*)&Bs[n][kb + 8];
            }
#pragma unroll
            for (int i = 0; i < 4; i++)
#pragma unroll
                for (int j = 0; j < 4; j++) mma16816(c[i][j], a[i], b[j]);
        }
        __syncthreads();
    }

#pragma unroll
    for (int i = 0; i < 4; i++) {
        const int row0 = bm + wr * 64 + i * 16 + l4;
#pragma unroll
        for (int j = 0; j < 4; j++) {
            const int col = bn + wc * 32 + j * 8 + lq * 2;
#pragma unroll
            for (int h = 0; h < 2; h++) {
                const int row = row0 + h * 8;
#pragma unroll
                for (int u = 0; u < 2; u++) {
                    float v = c[i][j][h * 2 + u] + bias[col + u];
                    if (ACT == 1) v = softplus_f(v);
                    C[(size_t)row * N + col + u] = v;
                    if (WRITEB) Cb[(size_t)row * N + col + u] = __float2bfloat16(v);
                }
            }
        }
    }
}

// ---------------- packed f32x2 helpers --------------------------------------
__device__ __forceinline__ unsigned long long pk2(float x, float y) {
    unsigned long long r;
    asm("mov.b64 %0, {%1, %2};" : "=l"(r) : "f"(x), "f"(y));
    return r;
}
__device__ __forceinline__ unsigned long long fma2(unsigned long long a,
                                                   unsigned long long b,
                                                   unsigned long long c) {
    unsigned long long d;
    asm("fma.rn.f32x2 %0, %1, %2, %3;" : "=l"(d) : "l"(a), "l"(b), "l"(c));
    return d;
}
__device__ __forceinline__ void upk2(unsigned long long v, float& lo, float& hi) {
    asm("mov.b64 {%0, %1}, %2;" : "=f"(lo), "=f"(hi) : "l"(v));
}

// ---------------- generic fp32 GEMM body (register double-buffered) ---------
template <int ACT, bool BNT>
__device__ __forceinline__ void gemm64_body(const float* __restrict__ A,
                                            const float* __restrict__ Bm,
                                            const float* __restrict__ bias,
                                            float* __restrict__ C,
                                            int M, int N, int K) {
    __shared__ float As[16][64];
    __shared__ float Bs[16][64];
    const int bm = blockIdx.y * 64, bn = blockIdx.x * 64;
    const int tid = threadIdx.x;
    const int tr = tid >> 4, tc = tid & 15;
    const int lrow = tid >> 4;
    const int lk = tid & 15;

    unsigned long long acc[4][2];
#pragma unroll
    for (int i = 0; i < 4; i++) { acc[i][0] = 0ull; acc[i][1] = 0ull; }

    float pa[4], pb[4], na[4], nb[4];

#pragma unroll
    for (int i = 0; i < 4; i++) {
        int r = lrow + i * 16;
        int gk = lk;
        int gm = bm + r;
        pa[i] = (gm < M && gk < K) ? A[(size_t)gm * K + gk] : 0.f;
        int gn = bn + r;
        float v = 0.f;
        if (gn < N && gk < K)
            v = BNT ? Bm[(size_t)gn * K + gk] : Bm[(size_t)gk * N + gn];
        pb[i] = v;
    }

    for (int k0 = 0; k0 < K; k0 += 16) {
#pragma unroll
        for (int i = 0; i < 4; i++) {
            int r = lrow + i * 16;
            As[lk][r] = pa[i];
            Bs[lk][r] = pb[i];
        }
        __syncthreads();

        if (k0 + 16 < K) {
#pragma unroll
            for (int i = 0; i < 4; i++) {
                int r = lrow + i * 16;
                int gk = k0 + 16 + lk;
                int gm = bm + r;
                na[i] = (gm < M && gk < K) ? A[(size_t)gm * K + gk] : 0.f;
                int gn = bn + r;
                float v = 0.f;
                if (gn < N && gk < K)
                    v = BNT ? Bm[(size_t)gn * K + gk] : Bm[(size_t)gk * N + gn];
                nb[i] = v;
            }
        }

#pragma unroll
        for (int kk = 0; kk < 16; kk++) {
            float a0 = As[kk][tr * 4 + 0];
            float a1 = As[kk][tr * 4 + 1];
            float a2 = As[kk][tr * 4 + 2];
            float a3 = As[kk][tr * 4 + 3];
            unsigned long long b0 =
                *reinterpret_cast<const unsigned long long*>(&Bs[kk][tc * 4]);
            unsigned long long b1 =
                *reinterpret_cast<const unsigned long long*>(&Bs[kk][tc * 4 + 2]);
            unsigned long long A0 = pk2(a0, a0), A1 = pk2(a1, a1);
            unsigned long long A2 = pk2(a2, a2), A3 = pk2(a3, a3);
            acc[0][0] = fma2(A0, b0, acc[0][0]); acc[0][1] = fma2(A0, b1, acc[0][1]);
            acc[1][0] = fma2(A1, b0, acc[1][0]); acc[1][1] = fma2(A1, b1, acc[1][1]);
            acc[2][0] = fma2(A2, b0, acc[2][0]); acc[2][1] = fma2(A2, b1, acc[2][1]);
            acc[3][0] = fma2(A3, b0, acc[3][0]); acc[3][1] = fma2(A3, b1, acc[3][1]);
        }
        __syncthreads();
#pragma unroll
        for (int i = 0; i < 4; i++) { pa[i] = na[i]; pb[i] = nb[i]; }
    }

#pragma unroll
    for (int i = 0; i < 4; i++) {
        int gm = bm + tr * 4 + i;
        if (gm >= M) continue;
#pragma unroll
        for (int j2 = 0; j2 < 2; j2++) {
            float lo, hi;
            upk2(acc[i][j2], lo, hi);
            float vals[2] = {lo, hi};
#pragma unroll
            for (int u = 0; u < 2; u++) {
                int gn = bn + tc * 4 + j2 * 2 + u;
                if (gn < N) {
                    float v = vals[u] + (bias ? bias[gn] : 0.f);
                    if (ACT == 1) v = softplus_f(v);
                    C[(size_t)gm * N + gn] = v;
                }
            }
        }
    }
}

// ---- wrapper kernels binding scratch globals --------------------------------
__global__ void gemm_qk(const float* __restrict__ W) {
    gemm64_body<0, false>(g_q, W, nullptr, g_qk, Bb, Dd, Dd);
}
__global__ void gemm_di(const float* __restrict__ W, const float* __restrict__ b) {
    gemm64_body<0, true>(g_ebar, W, b, g_di, Bb, Dd, Dd);
}
__global__ void gemm_mu(const float* __restrict__ W, const float* __restrict__ b) {
    gemm64_body<0, true>(g_di, W, b, g_mu, Bb, Tt, Dd);
}
__global__ void gemm_lv(const float* __restrict__ W, const float* __restrict__ b) {
    gemm64_body<0, true>(g_di, W, b, g_lv, Bb, Tt, Dd);
}
__global__ void gemm_logit(const float* __restrict__ W, const float* __restrict__ b) {
    gemm64_body<0, true>(g_theta, W, b, g_logit, Bb, Vv, Tt);
}

// ---------------- fused ragged single-query attention -----------------------
__global__ void attn_kernel(const float* __restrict__ emb,
                            const float* __restrict__ kb,
                            const int* __restrict__ lengths) {
    const int b = blockIdx.x, tid = threadIdx.x;  // 256 threads
    __shared__ float s_qk[Dd];
    __shared__ float s_sc[Mm];
    __shared__ float red[256];
    __shared__ float s_kbdot;
    const int len = lengths[b];

    float part = 0.f;
    for (int d = tid; d < Dd; d += 256) {
        s_qk[d] = g_qk[b * Dd + d];
        part += g_q[b * Dd + d] * kb[d];
    }
    red[tid] = part;
    __syncthreads();
    for (int s = 128; s > 0; s >>= 1) {
        if (tid < s) red[tid] += red[tid + s];
        __syncthreads();
    }
    if (tid == 0) s_kbdot = red[0];
    __syncthreads();
    const float kbdot = s_kbdot;

    const int wid = tid >> 5, lane = tid & 31;
    const float scale = 0.051031036307982884f;  // 1/sqrt(384)
    for (int m = wid; m < Mm; m += 8) {
        const float* er = emb + ((size_t)b * Mm + m) * Dd;
        float sum = 0.f;
#pragma unroll
        for (int i = 0; i < Dd / 32; i++) {
            int d = lane + 32 * i;
            sum += er[d] * s_qk[d];
        }
#pragma unroll
        for (int o = 16; o > 0; o >>= 1) sum += __shfl_xor_sync(0xffffffffu, sum, o);
        if (lane == 0) s_sc[m] = (m < len) ? (sum + kbdot) * scale : -1e30f;
    }
    __syncthreads();

    if (wid == 0) {
        float v0 = s_sc[lane], v1 = s_sc[lane + 32];
        float mx = fmaxf(v0, v1);
#pragma unroll
        for (int o = 16; o > 0; o >>= 1) mx = fmaxf(mx, __shfl_xor_sync(0xffffffffu, mx, o));
        float e0 = expf(v0 - mx), e1 = expf(v1 - mx);
        float ss = e0 + e1;
#pragma unroll
        for (int o = 16; o > 0; o >>= 1) ss += __shfl_xor_sync(0xffffffffu, ss, o);
        float inv = 1.f / ss;
        s_sc[lane] = e0 * inv;
        s_sc[lane + 32] = e1 * inv;
    }
    __syncthreads();

    for (int d = tid; d < Dd; d += 256) {
        float acc = 0.f;
#pragma unroll 8
        for (int m = 0; m < Mm; m++)
            acc += s_sc[m] * emb[((size_t)b * Mm + m) * Dd + d];
        g_ebar[b * Dd + d] = acc;
    }
}

// ---------------- BatchNorm over batch dim for [B,T], in place --------------
__device__ __forceinline__ void bn_cols_body(float* __restrict__ h,
                                             const float* __restrict__ bias) {
    const int t = blockIdx.x;
    const int tid = threadIdx.x;  // 256
    __shared__ float red[256];
    __shared__ float s_mu, s_inv;
    float v0 = h[(size_t)tid * Tt + t];
    float v1 = h[(size_t)(tid + 256) * Tt + t];
    red[tid] = v0 + v1;
    __syncthreads();
    for (int s = 128; s > 0; s >>= 1) {
        if (tid < s) red[tid] += red[tid + s];
        __syncthreads();
    }
    if (tid == 0) s_mu = red[0] * (1.f / Bb);
    __syncthreads();
    float mu = s_mu;
    float d0 = v0 - mu, d1 = v1 - mu;
    red[tid] = d0 * d0 + d1 * d1;
    __syncthreads();
    for (int s = 128; s > 0; s >>= 1) {
        if (tid < s) red[tid] += red[tid + s];
        __syncthreads();
    }
    if (tid == 0) s_inv = rsqrtf(red[0] * (1.f / Bb) + 1e-5f);
    __syncthreads();
    float inv = s_inv, bbv = bias[t];
    h[(size_t)tid * Tt + t] = d0 * inv + bbv;
    h[(size_t)(tid + 256) * Tt + t] = d1 * inv + bbv;
}
__global__ void bn_mu(const float* __restrict__ bias) { bn_cols_body(g_mu, bias); }
__global__ void bn_lv(const float* __restrict__ bias) { bn_cols_body(g_lv, bias); }

// ---------------- theta = softmax(mu), kl per sample -------------------------
__global__ void theta_kl_kernel() {
    const int b = blockIdx.x, tid = threadIdx.x;  // 128
    __shared__ float red[128];
    __shared__ float s_mx, s_sum;
    const bool ok = tid < Tt;
    const float m = ok ? g_mu[b * Tt + tid] : -1e30f;
    const float l = ok ? g_lv[b * Tt + tid] : 0.f;
    red[tid] = m;
    __syncthreads();
    for (int s = 64; s > 0; s >>= 1) {
        if (tid < s) red[tid] = fmaxf(red[tid], red[tid + s]);
        __syncthreads();
    }
    if (tid == 0) s_mx = red[0];
    __syncthreads();
    const float e = ok ? expf(m - s_mx) : 0.f;
    red[tid] = e;
    __syncthreads();
    for (int s = 64; s > 0; s >>= 1) {
        if (tid < s) red[tid] += red[tid + s];
        __syncthreads();
    }
    if (tid == 0) s_sum = red[0];
    __syncthreads();
    if (ok) g_theta[b * Tt + tid] = e / s_sum;

    const float INV_VAR2 = 1.0101010101010102f;    // 1/(1 - 1/T), T=100
    const float LOGV2 = -0.010050335853501441f;    // log(0.99)
    float term = ok ? (expf(l) * INV_VAR2 + m * m * INV_VAR2 + LOGV2 - l) : 0.f;
    red[tid] = term;
    __syncthreads();
    for (int s = 64; s > 0; s >>= 1) {
        if (tid < s) red[tid] += red[tid + s];
        __syncthreads();
    }
    if (tid == 0) g_kl[b] = 0.5f * (red[0] - (float)Tt);
}

// ---------------- per-vocab-column batch stats of logit (single pass) -------
__global__ void colstats_kernel() {
    const int v = blockIdx.x * blockDim.x + threadIdx.x;
    if (v >= Vv) return;
    float s = 0.f, s2 = 0.f;
#pragma unroll 8
    for (int b = 0; b < Bb; b++) {
        float x = g_logit[(size_t)b * Vv + v];
        s += x;
        s2 += x * x;
    }
    const float mean = s * (1.f / Bb);
    float var = fmaxf(s2 * (1.f / Bb) - mean * mean, 0.f);
    g_colmu[v] = mean;
    g_colinv[v] = rsqrtf(var + 1e-5f);
}

// ---------------- per-sample reconstruction loss -----------------------------
__global__ void recon_kernel(const float* __restrict__ bnb,
                             const float* __restrict__ x) {
    const int b = blockIdx.x, tid = threadIdx.x;  // 256
    __shared__ float s_m[256], s_s[256], s_xh[256], s_x[256];
    float mx = -1e30f, sm = 0.f, xh = 0.f, xs = 0.f;
    for (int v = tid; v < Vv; v += 256) {
        float hn = (g_logit[(size_t)b * Vv + v] - g_colmu[v]) * g_colinv[v] + bnb[v];
        float xv = x[(size_t)b * Vv + v];
        xh += xv * hn;
        xs += xv;
        float nm = fmaxf(mx, hn);
        sm = sm * expf(mx - nm) + expf(hn - nm);
        mx = nm;
    }
    s_m[tid] = mx; s_s[tid] = sm; s_xh[tid] = xh; s_x[tid] = xs;
    __syncthreads();
    if (tid == 0) {
        float M = -1e30f;
        for (int i = 0; i < 256; i++) M = fmaxf(M, s_m[i]);
        float S = 0.f, XH = 0.f, XS = 0.f;
        for (int i = 0; i < 256; i++) {
            S += s_s[i] * expf(s_m[i] - M);
            XH += s_xh[i];
            XS += s_x[i];
        }
        float lse = M + logf(S);
        g_recon[b] = lse * XS - XH;
    }
}

// ---------------- final scalar -----------------------------------------------
__global__ void final_reduce(float* __restrict__ out) {
    __shared__ float red[512];
    const int tid = threadIdx.x;
    red[tid] = g_recon[tid] + g_kl[tid];
    __syncthreads();
    for (int s = 256; s > 0; s >>= 1) {
        if (tid < s) red[tid] += red[tid + s];
        __syncthreads();
    }
    if (tid == 0) out[0] = red[0] * (1.f / Bb);
}

// =============================================================================
extern "C" void kernel_launch(void* const* d_in, const int* in_sizes, int n_in,
                              void* d_out, int out_size) {
    (void)in_sizes; (void)n_in; (void)out_size;
    const float* x        = (const float*)d_in[0];
    const float* emb      = (const float*)d_in[1];
    const int*   lengths  = (const int*)d_in[2];
    const float* fc11_w   = (const float*)d_in[3];
    const float* fc11_b   = (const float*)d_in[4];
    const float* fc12_w   = (const float*)d_in[5];
    const float* fc12_b   = (const float*)d_in[6];
    const float* q_w      = (const float*)d_in[7];
    const float* q_b      = (const float*)d_in[8];
    const float* k_w      = (const float*)d_in[9];
    const float* k_b      = (const float*)d_in[10];
    const float* v_w      = (const float*)d_in[11];
    const float* v_b      = (const float*)d_in[12];
    const float* mean_w   = (const float*)d_in[13];
    const float* mean_b   = (const float*)d_in[14];
    const float* logvar_w = (const float*)d_in[15];
    const float* logvar_b = (const float*)d_in[16];
    const float* mean_bn_b   = (const float*)d_in[17];
    const float* logvar_bn_b = (const float*)d_in[18];
    const float* dec_w    = (const float*)d_in[19];
    const float* dec_b    = (const float*)d_in[20];
    const float* dec_bn_b = (const float*)d_in[21];

    __nv_bfloat16 *xb, *wb, *fc12b, *qwb, *e1b, *hbowb;
    cudaGetSymbolAddress((void**)&xb, g_xb);
    cudaGetSymbolAddress((void**)&wb, g_wb);
    cudaGetSymbolAddress((void**)&fc12b, g_fc12b);
    cudaGetSymbolAddress((void**)&qwb, g_qwb);
    cudaGetSymbolAddress((void**)&e1b, g_e1b);
    cudaGetSymbolAddress((void**)&hbowb, g_hbowb);
    float *hbow, *q;
    cudaGetSymbolAddress((void**)&hbow, g_hbow);
    cudaGetSymbolAddress((void**)&q, g_q);

    cudaFuncSetAttribute(fc11_mma2, cudaFuncAttributeMaxDynamicSharedMemorySize, 65536);

    // 1-2: x conversion split into two launches (positions fc11_mma2 at launch #6
    //      so ncu -s 5 -c 1 profiles the dominant GEMM)
    cvt_bf16<<<(256 * (KP / 8)) / 256, 256>>>(x, xb);
    cvt_bf16<<<(256 * (KP / 8)) / 256, 256>>>(x + (size_t)256 * Vv, xb + (size_t)256 * KP);
    // 3: fc11_w conversion
    cvt_bf16<<<(Ee * (KP / 8)) / 256, 256>>>(fc11_w, wb);
    // 4-5: small weight conversions
    cvt_plain<<<(Ee * Ee / 8) / 256, 256>>>(fc12_w, fc12b);
    cvt_plain<<<(Dd * Ee / 8) / 256, 256>>>(q_w, qwb);
    // 6: fc11 GEMM (cp.async 2-stage, split-K)
    fc11_mma2<<<dim3(Ee / 128, Bb / 128, SPLIT), 256, 65536>>>();
    // 7: reduce partials -> e1 (bf16)
    fc11_reduce<<<(Bb * Ee) / 256, 256>>>(fc11_b);
    // 8: h_bow = softplus(e1 @ fc12^T + b)  [bf16 mma, dual fp32+bf16 out]
    mma_gemm<1, 1><<<dim3(Ee / 128, Bb / 128), 256>>>(e1b, fc12b, fc12_b, hbow, hbowb, Ee, Ee);
    // 9: q = h_bow @ q_w^T + q_b  [bf16 mma]
    mma_gemm<0, 0><<<dim3(Dd / 128, Bb / 128), 256>>>(hbowb, qwb, q_b, q, (__nv_bfloat16*)0, Dd, Ee);
    // 10..: rest of the network (fp32)
    gemm_qk<<<dim3(Dd / 64, Bb / 64), 256>>>(k_w);
    attn_kernel<<<Bb, 256>>>(emb, k_b, lengths);
    gemm_di<<<dim3(Dd / 64, Bb / 64), 256>>>(v_w, v_b);
    gemm_mu<<<dim3(2, Bb / 64), 256>>>(mean_w, mean_b);
    gemm_lv<<<dim3(2, Bb / 64), 256>>>(logvar_w, logvar_b);
    bn_mu<<<Tt, 256>>>(mean_bn_b);
    bn_lv<<<Tt, 256>>>(logvar_bn_b);
    theta_kl_kernel<<<Bb, 128>>>();
    gemm_logit<<<dim3((Vv + 63) / 64, Bb / 64), 256>>>(dec_w, dec_b);
    colstats_kernel<<<(Vv + 255) / 256, 256>>>();
    recon_kernel<<<Bb, 256>>>(dec_bn_b, x);
    final_reduce<<<1, Bb>>>((float*)d_out);
}

// round 11
// speedup vs baseline: 2.2802x; 1.0966x over previous
#include <cuda_runtime.h>
#include <cuda_bf16.h>
#include <math.h>
#include <stdint.h>

#define Bb 512
#define Mm 64
#define Vv 20000
#define Ee 1024
#define Dd 384
#define Tt 100
#define SPLIT 9
#define KP 20032            // Vv padded to multiple of 64
#define KTOT 313            // KP / 64

// ---------------- scratch (device globals; no allocations allowed) ----------
__device__ __nv_bfloat16 g_xb[(size_t)Bb * KP];   // 20.5 MB
__device__ __nv_bfloat16 g_wb[(size_t)Ee * KP];   // 41 MB
__device__ float g_part[SPLIT * Bb * Ee];         // 18.9 MB
__device__ __nv_bfloat16 g_e1b[Bb * Ee];
__device__ __nv_bfloat16 g_fc12b[Ee * Ee];
__device__ __nv_bfloat16 g_qwb[Dd * Ee];
__device__ __nv_bfloat16 g_hbowb[Bb * Ee];
__device__ float g_q[Bb * Dd];
__device__ float g_qk[Bb * Dd];
__device__ float g_ebar[Bb * Dd];
__device__ float g_di[Bb * Dd];
__device__ float g_mu[Bb * Tt];
__device__ float g_lv[Bb * Tt];
__device__ float g_theta[Bb * Tt];
__device__ float g_logit[(size_t)Bb * Vv];
__device__ float g_colmu[Vv];
__device__ float g_colinv[Vv];
__device__ float g_recon[Bb];
__device__ float g_kl[Bb];

__device__ __forceinline__ float softplus_f(float x) {
    return x > 0.f ? x + log1pf(expf(-x)) : log1pf(expf(x));
}
__device__ __forceinline__ uint32_t smem_u32(const void* p) {
    uint32_t a;
    asm("{ .reg .u64 t; cvta.to.shared.u64 t, %1; cvt.u32.u64 %0, t; }"
        : "=r"(a) : "l"(p));
    return a;
}
__device__ __forceinline__ uint32_t lds32(uint32_t addr) {
    uint32_t v;
    asm volatile("ld.shared.b32 %0, [%1];" : "=r"(v) : "r"(addr));
    return v;
}

// ---------------- fp32 -> bf16 conversions -----------------------------------
__global__ void cvt_bf16(const float* __restrict__ src, __nv_bfloat16* __restrict__ dst) {
    const int idx = blockIdx.x * 256 + threadIdx.x;
    const int row = idx / (KP / 8);
    const int cp = (idx % (KP / 8)) * 8;
    __nv_bfloat16 o[8];
    if (cp + 8 <= Vv) {
        const float4 v0 = *(const float4*)&src[(size_t)row * Vv + cp];
        const float4 v1 = *(const float4*)&src[(size_t)row * Vv + cp + 4];
        o[0] = __float2bfloat16(v0.x); o[1] = __float2bfloat16(v0.y);
        o[2] = __float2bfloat16(v0.z); o[3] = __float2bfloat16(v0.w);
        o[4] = __float2bfloat16(v1.x); o[5] = __float2bfloat16(v1.y);
        o[6] = __float2bfloat16(v1.z); o[7] = __float2bfloat16(v1.w);
    } else {
#pragma unroll
        for (int i = 0; i < 8; i++) o[i] = __float2bfloat16(0.f);
    }
    *(uint4*)&dst[(size_t)row * KP + cp] = *(uint4*)o;
}

// two plain conversions in one launch (no padding; lengths in 8-elem units)
__global__ void cvt_two(const float* __restrict__ sa, __nv_bfloat16* __restrict__ da, int na8,
                        const float* __restrict__ sb, __nv_bfloat16* __restrict__ db) {
    const int idx = blockIdx.x * 256 + threadIdx.x;
    const float* s;
    __nv_bfloat16* d;
    int i;
    if (idx < na8) { s = sa; d = da; i = idx * 8; }
    else           { s = sb; d = db; i = (idx - na8) * 8; }
    const float4 v0 = *(const float4*)&s[i];
    const float4 v1 = *(const float4*)&s[i + 4];
    __nv_bfloat16 o[8];
    o[0] = __float2bfloat16(v0.x); o[1] = __float2bfloat16(v0.y);
    o[2] = __float2bfloat16(v0.z); o[3] = __float2bfloat16(v0.w);
    o[4] = __float2bfloat16(v1.x); o[5] = __float2bfloat16(v1.y);
    o[6] = __float2bfloat16(v1.z); o[7] = __float2bfloat16(v1.w);
    *(uint4*)&d[i] = *(uint4*)o;
}

// ---------------- warp-level bf16 MMA (arch-neutral PTX, sm_80+) ------------
__device__ __forceinline__ void mma16816(float* c, const uint32_t* a, const uint32_t* b) {
    asm volatile(
        "mma.sync.aligned.m16n8k16.row.col.f32.bf16.bf16.f32 "
        "{%0,%1,%2,%3}, {%4,%5,%6,%7}, {%8,%9}, {%0,%1,%2,%3};"
        : "+f"(c[0]), "+f"(c[1]), "+f"(c[2]), "+f"(c[3])
        : "r"(a[0]), "r"(a[1]), "r"(a[2]), "r"(a[3]), "r"(b[0]), "r"(b[1]));
}

// ===================== fc11 via cp.async 3-stage + mma.sync ==================
// XOR-swizzled stage layout (16KB A + 16KB B per stage, 3 stages = 96KB).
__device__ __forceinline__ void fc11_load_stage(uint32_t sbase, int st, int kt,
                                                int bm, int bn, int tid) {
    const int k0 = kt * 64;
    const uint32_t abase = sbase + st * 32768;
    const uint32_t bbase = abase + 16384;
#pragma unroll
    for (int i = 0; i < 4; i++) {
        const int idx = tid + 256 * i;
        const int row = idx >> 3, ch = idx & 7;
        const uint32_t off = (uint32_t)row * 128u + (uint32_t)((ch ^ (row & 7)) << 4);
        const void* asrc = &g_xb[(size_t)(bm + row) * KP + k0 + ch * 8];
        asm volatile("cp.async.cg.shared.global [%0], [%1], 16;"
                     :: "r"(abase + off), "l"(asrc));
        const void* bsrc = &g_wb[(size_t)(bn + row) * KP + k0 + ch * 8];
        asm volatile("cp.async.cg.shared.global [%0], [%1], 16;"
                     :: "r"(bbase + off), "l"(bsrc));
    }
    asm volatile("cp.async.commit_group;");
}

__device__ __forceinline__ uint32_t swz(uint32_t row, uint32_t bytecol) {
    return row * 128u + ((((bytecol >> 4) ^ (row & 7u))) << 4) + (bytecol & 15u);
}

__global__ __launch_bounds__(256, 2) void fc11_mma2() {
    extern __shared__ char dynsmem[];
    const uint32_t sbase = smem_u32(dynsmem);
    const int tid = threadIdx.x;
    const int wid = tid >> 5, lane = tid & 31;
    const int wr = wid >> 2, wc = wid & 3;
    const int l4 = lane >> 2, lq = lane & 3;
    const int bn = blockIdx.x * 128;
    const int bm = blockIdx.y * 128;
    const int s = blockIdx.z;
    const int kt0 = (s * KTOT) / SPLIT, kt1 = ((s + 1) * KTOT) / SPLIT;
    const int niter = kt1 - kt0;

    float c[4][4][4];
#pragma unroll
    for (int i = 0; i < 4; i++)
#pragma unroll
        for (int j = 0; j < 4; j++)
#pragma unroll
            for (int u = 0; u < 4; u++) c[i][j][u] = 0.f;

    fc11_load_stage(sbase, 0, kt0, bm, bn, tid);
    if (niter > 1) fc11_load_stage(sbase, 1, kt0 + 1, bm, bn, tid);

    int st = 0;
    for (int t = 0; t < niter; t++) {
        if (t + 2 < niter) {
            int st2 = st + 2; if (st2 >= 3) st2 -= 3;
            fc11_load_stage(sbase, st2, kt0 + t + 2, bm, bn, tid);
            asm volatile("cp.async.wait_group 2;");
        } else if (t + 1 < niter) {
            asm volatile("cp.async.wait_group 1;");
        } else {
            asm volatile("cp.async.wait_group 0;");
        }
        __syncthreads();

        const uint32_t abase = sbase + st * 32768;
        const uint32_t bbase = abase + 16384;
#pragma unroll
        for (int kk = 0; kk < 4; kk++) {
            const uint32_t bytecol = (uint32_t)(kk * 32 + lq * 4);
            uint32_t a[4][4], b[4][2];
#pragma unroll
            for (int i = 0; i < 4; i++) {
                const uint32_t r = (uint32_t)(wr * 64 + i * 16 + l4);
                a[i][0] = lds32(abase + swz(r, bytecol));
                a[i][1] = lds32(abase + swz(r + 8, bytecol));
                a[i][2] = lds32(abase + swz(r, bytecol + 16));
                a[i][3] = lds32(abase + swz(r + 8, bytecol + 16));
            }
#pragma unroll
            for (int j = 0; j < 4; j++) {
                const uint32_t n = (uint32_t)(wc * 32 + j * 8 + l4);
                b[j][0] = lds32(bbase + swz(n, bytecol));
                b[j][1] = lds32(bbase + swz(n, bytecol + 16));
            }
#pragma unroll
            for (int i = 0; i < 4; i++)
#pragma unroll
                for (int j = 0; j < 4; j++) mma16816(c[i][j], a[i], b[j]);
        }
        __syncthreads();
        if (++st >= 3) st = 0;
    }

#pragma unroll
    for (int i = 0; i < 4; i++) {
        const int row0 = bm + wr * 64 + i * 16 + l4;
#pragma unroll
        for (int j = 0; j < 4; j++) {
            const int col = bn + wc * 32 + j * 8 + lq * 2;
            float* p0 = g_part + ((size_t)s * Bb + row0) * Ee + col;
            float* p1 = g_part + ((size_t)s * Bb + row0 + 8) * Ee + col;
            p0[0] = c[i][j][0]; p0[1] = c[i][j][1];
            p1[0] = c[i][j][2]; p1[1] = c[i][j][3];
        }
    }
}

__global__ void fc11_reduce(const float* __restrict__ bias) {
    const int i = blockIdx.x * 256 + threadIdx.x;
    float v = bias[i & (Ee - 1)];
#pragma unroll
    for (int s = 0; s < SPLIT; s++) v += g_part[(size_t)s * (Bb * Ee) + i];
    g_e1b[i] = __float2bfloat16(softplus_f(v));
}

// ===================== generic bf16 mma GEMM (single-buffer, PADR) ===========
// MODE: 0 = fp32 out only, 1 = bf16 out only
#define PADR 72
template <int ACT, int MODE>
__global__ __launch_bounds__(256) void mma_gemm(const __nv_bfloat16* __restrict__ A,
                                                const __nv_bfloat16* __restrict__ W,
                                                const float* __restrict__ bias,
                                                float* __restrict__ C,
                                                __nv_bfloat16* __restrict__ Cb,
                                                int N, int K) {
    __shared__ __nv_bfloat16 As[128][PADR];
    __shared__ __nv_bfloat16 Bs[128][PADR];
    const int tid = threadIdx.x;
    const int wid = tid >> 5, lane = tid & 31;
    const int wr = wid >> 2, wc = wid & 3;
    const int l4 = lane >> 2, lq = lane & 3;
    const int bn = blockIdx.x * 128;
    const int bm = blockIdx.y * 128;

    float c[4][4][4];
#pragma unroll
    for (int i = 0; i < 4; i++)
#pragma unroll
        for (int j = 0; j < 4; j++)
#pragma unroll
            for (int u = 0; u < 4; u++) c[i][j][u] = 0.f;

    for (int k0 = 0; k0 < K; k0 += 64) {
#pragma unroll
        for (int i = 0; i < 4; i++) {
            const int idx = tid + 256 * i;
            const int row = idx >> 3, ch = idx & 7;
            uint4 va = *(const uint4*)&A[(size_t)(bm + row) * K + k0 + ch * 8];
            *(uint4*)&As[row][ch * 8] = va;
            uint4 vb = *(const uint4*)&W[(size_t)(bn + row) * K + k0 + ch * 8];
            *(uint4*)&Bs[row][ch * 8] = vb;
        }
        __syncthreads();

#pragma unroll
        for (int kk = 0; kk < 4; kk++) {
            const int kb = kk * 16 + lq * 2;
            uint32_t a[4][4], b[4][2];
#pragma unroll
            for (int i = 0; i < 4; i++) {
                const int r = wr * 64 + i * 16 + l4;
                a[i][0] = *(const uint32_t*)&As[r][kb];
                a[i][1] = *(const uint32_t*)&As[r + 8][kb];
                a[i][2] = *(const uint32_t*)&As[r][kb + 8];
                a[i][3] = *(const uint32_t*)&As[r + 8][kb + 8];
            }
#pragma unroll
            for (int j = 0; j < 4; j++) {
                const int n = wc * 32 + j * 8 + l4;
                b[j][0] = *(const uint32_t*)&Bs[n][kb];
                b[j][1] = *(const uint32_t*)&Bs[n][kb + 8];
            }
#pragma unroll
            for (int i = 0; i < 4; i++)
#pragma unroll
                for (int j = 0; j < 4; j++) mma16816(c[i][j], a[i], b[j]);
        }
        __syncthreads();
    }

#pragma unroll
    for (int i = 0; i < 4; i++) {
        const int row0 = bm + wr * 64 + i * 16 + l4;
#pragma unroll
        for (int j = 0; j < 4; j++) {
            const int col = bn + wc * 32 + j * 8 + lq * 2;
#pragma unroll
            for (int h = 0; h < 2; h++) {
                const int row = row0 + h * 8;
#pragma unroll
                for (int u = 0; u < 2; u++) {
                    float v = c[i][j][h * 2 + u] + bias[col + u];
                    if (ACT == 1) v = softplus_f(v);
                    if (MODE == 0) C[(size_t)row * N + col + u] = v;
                    else Cb[(size_t)row * N + col + u] = __float2bfloat16(v);
                }
            }
        }
    }
}

// ---------------- packed f32x2 helpers --------------------------------------
__device__ __forceinline__ unsigned long long pk2(float x, float y) {
    unsigned long long r;
    asm("mov.b64 %0, {%1, %2};" : "=l"(r) : "f"(x), "f"(y));
    return r;
}
__device__ __forceinline__ unsigned long long fma2(unsigned long long a,
                                                   unsigned long long b,
                                                   unsigned long long c) {
    unsigned long long d;
    asm("fma.rn.f32x2 %0, %1, %2, %3;" : "=l"(d) : "l"(a), "l"(b), "l"(c));
    return d;
}
__device__ __forceinline__ void upk2(unsigned long long v, float& lo, float& hi) {
    asm("mov.b64 {%0, %1}, %2;" : "=f"(lo), "=f"(hi) : "l"(v));
}

// ---------------- generic fp32 GEMM body (register double-buffered) ---------
template <int ACT, bool BNT>
__device__ __forceinline__ void gemm64_body(const float* __restrict__ A,
                                            const float* __restrict__ Bm,
                                            const float* __restrict__ bias,
                                            float* __restrict__ C,
                                            int M, int N, int K) {
    __shared__ float As[16][64];
    __shared__ float Bs[16][64];
    const int bm = blockIdx.y * 64, bn = blockIdx.x * 64;
    const int tid = threadIdx.x;
    const int tr = tid >> 4, tc = tid & 15;
    const int lrow = tid >> 4;
    const int lk = tid & 15;

    unsigned long long acc[4][2];
#pragma unroll
    for (int i = 0; i < 4; i++) { acc[i][0] = 0ull; acc[i][1] = 0ull; }

    float pa[4], pb[4], na[4], nb[4];

#pragma unroll
    for (int i = 0; i < 4; i++) {
        int r = lrow + i * 16;
        int gk = lk;
        int gm = bm + r;
        pa[i] = (gm < M && gk < K) ? A[(size_t)gm * K + gk] : 0.f;
        int gn = bn + r;
        float v = 0.f;
        if (gn < N && gk < K)
            v = BNT ? Bm[(size_t)gn * K + gk] : Bm[(size_t)gk * N + gn];
        pb[i] = v;
    }

    for (int k0 = 0; k0 < K; k0 += 16) {
#pragma unroll
        for (int i = 0; i < 4; i++) {
            int r = lrow + i * 16;
            As[lk][r] = pa[i];
            Bs[lk][r] = pb[i];
        }
        __syncthreads();

        if (k0 + 16 < K) {
#pragma unroll
            for (int i = 0; i < 4; i++) {
                int r = lrow + i * 16;
                int gk = k0 + 16 + lk;
                int gm = bm + r;
                na[i] = (gm < M && gk < K) ? A[(size_t)gm * K + gk] : 0.f;
                int gn = bn + r;
                float v = 0.f;
                if (gn < N && gk < K)
                    v = BNT ? Bm[(size_t)gn * K + gk] : Bm[(size_t)gk * N + gn];
                nb[i] = v;
            }
        }

#pragma unroll
        for (int kk = 0; kk < 16; kk++) {
            float a0 = As[kk][tr * 4 + 0];
            float a1 = As[kk][tr * 4 + 1];
            float a2 = As[kk][tr * 4 + 2];
            float a3 = As[kk][tr * 4 + 3];
            unsigned long long b0 =
                *reinterpret_cast<const unsigned long long*>(&Bs[kk][tc * 4]);
            unsigned long long b1 =
                *reinterpret_cast<const unsigned long long*>(&Bs[kk][tc * 4 + 2]);
            unsigned long long A0 = pk2(a0, a0), A1 = pk2(a1, a1);
            unsigned long long A2 = pk2(a2, a2), A3 = pk2(a3, a3);
            acc[0][0] = fma2(A0, b0, acc[0][0]); acc[0][1] = fma2(A0, b1, acc[0][1]);
            acc[1][0] = fma2(A1, b0, acc[1][0]); acc[1][1] = fma2(A1, b1, acc[1][1]);
            acc[2][0] = fma2(A2, b0, acc[2][0]); acc[2][1] = fma2(A2, b1, acc[2][1]);
            acc[3][0] = fma2(A3, b0, acc[3][0]); acc[3][1] = fma2(A3, b1, acc[3][1]);
        }
        __syncthreads();
#pragma unroll
        for (int i = 0; i < 4; i++) { pa[i] = na[i]; pb[i] = nb[i]; }
    }

#pragma unroll
    for (int i = 0; i < 4; i++) {
        int gm = bm + tr * 4 + i;
        if (gm >= M) continue;
#pragma unroll
        for (int j2 = 0; j2 < 2; j2++) {
            float lo, hi;
            upk2(acc[i][j2], lo, hi);
            float vals[2] = {lo, hi};
#pragma unroll
            for (int u = 0; u < 2; u++) {
                int gn = bn + tc * 4 + j2 * 2 + u;
                if (gn < N) {
                    float v = vals[u] + (bias ? bias[gn] : 0.f);
                    if (ACT == 1) v = softplus_f(v);
                    C[(size_t)gm * N + gn] = v;
                }
            }
        }
    }
}

// ---- wrapper kernels binding scratch globals --------------------------------
__global__ void gemm_qk(const float* __restrict__ W) {
    gemm64_body<0, false>(g_q, W, nullptr, g_qk, Bb, Dd, Dd);
}
__global__ void gemm_di(const float* __restrict__ W, const float* __restrict__ b) {
    gemm64_body<0, true>(g_ebar, W, b, g_di, Bb, Dd, Dd);
}
// mu and lv fused into one launch via blockIdx.z
__global__ void gemm_mulv(const float* __restrict__ Wm, const float* __restrict__ bm_,
                          const float* __restrict__ Wl, const float* __restrict__ bl_) {
    if (blockIdx.z == 0)
        gemm64_body<0, true>(g_di, Wm, bm_, g_mu, Bb, Tt, Dd);
    else
        gemm64_body<0, true>(g_di, Wl, bl_, g_lv, Bb, Tt, Dd);
}
__global__ void gemm_logit(const float* __restrict__ W, const float* __restrict__ b) {
    gemm64_body<0, true>(g_theta, W, b, g_logit, Bb, Vv, Tt);
}

// ---------------- fused ragged single-query attention -----------------------
__global__ void attn_kernel(const float* __restrict__ emb,
                            const float* __restrict__ kb,
                            const int* __restrict__ lengths) {
    const int b = blockIdx.x, tid = threadIdx.x;  // 256 threads
    __shared__ float s_qk[Dd];
    __shared__ float s_sc[Mm];
    __shared__ float red[256];
    __shared__ float s_kbdot;
    const int len = lengths[b];

    float part = 0.f;
    for (int d = tid; d < Dd; d += 256) {
        s_qk[d] = g_qk[b * Dd + d];
        part += g_q[b * Dd + d] * kb[d];
    }
    red[tid] = part;
    __syncthreads();
    for (int s = 128; s > 0; s >>= 1) {
        if (tid < s) red[tid] += red[tid + s];
        __syncthreads();
    }
    if (tid == 0) s_kbdot = red[0];
    __syncthreads();
    const float kbdot = s_kbdot;

    const int wid = tid >> 5, lane = tid & 31;
    const float scale = 0.051031036307982884f;  // 1/sqrt(384)
    for (int m = wid; m < Mm; m += 8) {
        const float* er = emb + ((size_t)b * Mm + m) * Dd;
        float sum = 0.f;
#pragma unroll
        for (int i = 0; i < Dd / 32; i++) {
            int d = lane + 32 * i;
            sum += er[d] * s_qk[d];
        }
#pragma unroll
        for (int o = 16; o > 0; o >>= 1) sum += __shfl_xor_sync(0xffffffffu, sum, o);
        if (lane == 0) s_sc[m] = (m < len) ? (sum + kbdot) * scale : -1e30f;
    }
    __syncthreads();

    if (wid == 0) {
        float v0 = s_sc[lane], v1 = s_sc[lane + 32];
        float mx = fmaxf(v0, v1);
#pragma unroll
        for (int o = 16; o > 0; o >>= 1) mx = fmaxf(mx, __shfl_xor_sync(0xffffffffu, mx, o));
        float e0 = expf(v0 - mx), e1 = expf(v1 - mx);
        float ss = e0 + e1;
#pragma unroll
        for (int o = 16; o > 0; o >>= 1) ss += __shfl_xor_sync(0xffffffffu, ss, o);
        float inv = 1.f / ss;
        s_sc[lane] = e0 * inv;
        s_sc[lane + 32] = e1 * inv;
    }
    __syncthreads();

    for (int d = tid; d < Dd; d += 256) {
        float acc = 0.f;
#pragma unroll 8
        for (int m = 0; m < Mm; m++)
            acc += s_sc[m] * emb[((size_t)b * Mm + m) * Dd + d];
        g_ebar[b * Dd + d] = acc;
    }
}

// ---------------- BatchNorm over batch dim for [B,T], both arrays -----------
__global__ void bn_both(const float* __restrict__ bias_mu,
                        const float* __restrict__ bias_lv) {
    const int which = blockIdx.x >= Tt;
    const int t = which ? blockIdx.x - Tt : blockIdx.x;
    float* h = which ? g_lv : g_mu;
    const float* bias = which ? bias_lv : bias_mu;
    const int tid = threadIdx.x;  // 256
    __shared__ float red[256];
    __shared__ float s_mu, s_inv;
    float v0 = h[(size_t)tid * Tt + t];
    float v1 = h[(size_t)(tid + 256) * Tt + t];
    red[tid] = v0 + v1;
    __syncthreads();
    for (int s = 128; s > 0; s >>= 1) {
        if (tid < s) red[tid] += red[tid + s];
        __syncthreads();
    }
    if (tid == 0) s_mu = red[0] * (1.f / Bb);
    __syncthreads();
    float mu = s_mu;
    float d0 = v0 - mu, d1 = v1 - mu;
    red[tid] = d0 * d0 + d1 * d1;
    __syncthreads();
    for (int s = 128; s > 0; s >>= 1) {
        if (tid < s) red[tid] += red[tid + s];
        __syncthreads();
    }
    if (tid == 0) s_inv = rsqrtf(red[0] * (1.f / Bb) + 1e-5f);
    __syncthreads();
    float inv = s_inv, bbv = bias[t];
    h[(size_t)tid * Tt + t] = d0 * inv + bbv;
    h[(size_t)(tid + 256) * Tt + t] = d1 * inv + bbv;
}

// ---------------- theta = softmax(mu), kl per sample -------------------------
__global__ void theta_kl_kernel() {
    const int b = blockIdx.x, tid = threadIdx.x;  // 128
    __shared__ float red[128];
    __shared__ float s_mx, s_sum;
    const bool ok = tid < Tt;
    const float m = ok ? g_mu[b * Tt + tid] : -1e30f;
    const float l = ok ? g_lv[b * Tt + tid] : 0.f;
    red[tid] = m;
    __syncthreads();
    for (int s = 64; s > 0; s >>= 1) {
        if (tid < s) red[tid] = fmaxf(red[tid], red[tid + s]);
        __syncthreads();
    }
    if (tid == 0) s_mx = red[0];
    __syncthreads();
    const float e = ok ? expf(m - s_mx) : 0.f;
    red[tid] = e;
    __syncthreads();
    for (int s = 64; s > 0; s >>= 1) {
        if (tid < s) red[tid] += red[tid + s];
        __syncthreads();
    }
    if (tid == 0) s_sum = red[0];
    __syncthreads();
    if (ok) g_theta[b * Tt + tid] = e / s_sum;

    const float INV_VAR2 = 1.0101010101010102f;    // 1/(1 - 1/T), T=100
    const float LOGV2 = -0.010050335853501441f;    // log(0.99)
    float term = ok ? (expf(l) * INV_VAR2 + m * m * INV_VAR2 + LOGV2 - l) : 0.f;
    red[tid] = term;
    __syncthreads();
    for (int s = 64; s > 0; s >>= 1) {
        if (tid < s) red[tid] += red[tid + s];
        __syncthreads();
    }
    if (tid == 0) g_kl[b] = 0.5f * (red[0] - (float)Tt);
}

// ---------------- per-vocab-column batch stats of logit (single pass) -------
__global__ void colstats_kernel() {
    const int v = blockIdx.x * blockDim.x + threadIdx.x;
    if (v >= Vv) return;
    float s = 0.f, s2 = 0.f;
#pragma unroll 8
    for (int b = 0; b < Bb; b++) {
        float x = g_logit[(size_t)b * Vv + v];
        s += x;
        s2 += x * x;
    }
    const float mean = s * (1.f / Bb);
    float var = fmaxf(s2 * (1.f / Bb) - mean * mean, 0.f);
    g_colmu[v] = mean;
    g_colinv[v] = rsqrtf(var + 1e-5f);
}

// ---------------- per-sample reconstruction loss (tree-reduced tail) --------
__global__ void recon_kernel(const float* __restrict__ bnb,
                             const float* __restrict__ x) {
    const int b = blockIdx.x, tid = threadIdx.x;  // 256
    __shared__ float s_m[256], s_s[256], s_xh[256], s_x[256];
    float mx = -1e30f, sm = 0.f, xh = 0.f, xs = 0.f;
    for (int v = tid; v < Vv; v += 256) {
        float hn = (g_logit[(size_t)b * Vv + v] - g_colmu[v]) * g_colinv[v] + bnb[v];
        float xv = x[(size_t)b * Vv + v];
        xh += xv * hn;
        xs += xv;
        float nm = fmaxf(mx, hn);
        sm = sm * expf(mx - nm) + expf(hn - nm);
        mx = nm;
    }
    s_m[tid] = mx; s_s[tid] = sm; s_xh[tid] = xh; s_x[tid] = xs;
    __syncthreads();
    for (int st = 128; st > 0; st >>= 1) {
        if (tid < st) {
            float m2 = s_m[tid + st], sm2 = s_s[tid + st];
            float M = fmaxf(s_m[tid], m2);
            s_s[tid] = s_s[tid] * expf(s_m[tid] - M) + sm2 * expf(m2 - M);
            s_m[tid] = M;
            s_xh[tid] += s_xh[tid + st];
            s_x[tid] += s_x[tid + st];
        }
        __syncthreads();
    }
    if (tid == 0) {
        float lse = s_m[0] + logf(s_s[0]);
        g_recon[b] = lse * s_x[0] - s_xh[0];
    }
}

// ---------------- final scalar -----------------------------------------------
__global__ void final_reduce(float* __restrict__ out) {
    __shared__ float red[512];
    const int tid = threadIdx.x;
    red[tid] = g_recon[tid] + g_kl[tid];
    __syncthreads();
    for (int s = 256; s > 0; s >>= 1) {
        if (tid < s) red[tid] += red[tid + s];
        __syncthreads();
    }
    if (tid == 0) out[0] = red[0] * (1.f / Bb);
}

// =============================================================================
extern "C" void kernel_launch(void* const* d_in, const int* in_sizes, int n_in,
                              void* d_out, int out_size) {
    (void)in_sizes; (void)n_in; (void)out_size;
    const float* x        = (const float*)d_in[0];
    const float* emb      = (const float*)d_in[1];
    const int*   lengths  = (const int*)d_in[2];
    const float* fc11_w   = (const float*)d_in[3];
    const float* fc11_b   = (const float*)d_in[4];
    const float* fc12_w   = (const float*)d_in[5];
    const float* fc12_b   = (const float*)d_in[6];
    const float* q_w      = (const float*)d_in[7];
    const float* q_b      = (const float*)d_in[8];
    const float* k_w      = (const float*)d_in[9];
    const float* k_b      = (const float*)d_in[10];
    const float* v_w      = (const float*)d_in[11];
    const float* v_b      = (const float*)d_in[12];
    const float* mean_w   = (const float*)d_in[13];
    const float* mean_b   = (const float*)d_in[14];
    const float* logvar_w = (const float*)d_in[15];
    const float* logvar_b = (const float*)d_in[16];
    const float* mean_bn_b   = (const float*)d_in[17];
    const float* logvar_bn_b = (const float*)d_in[18];
    const float* dec_w    = (const float*)d_in[19];
    const float* dec_b    = (const float*)d_in[20];
    const float* dec_bn_b = (const float*)d_in[21];

    __nv_bfloat16 *xb, *wb, *fc12b, *qwb, *e1b, *hbowb;
    cudaGetSymbolAddress((void**)&xb, g_xb);
    cudaGetSymbolAddress((void**)&wb, g_wb);
    cudaGetSymbolAddress((void**)&fc12b, g_fc12b);
    cudaGetSymbolAddress((void**)&qwb, g_qwb);
    cudaGetSymbolAddress((void**)&e1b, g_e1b);
    cudaGetSymbolAddress((void**)&hbowb, g_hbowb);
    float* q;
    cudaGetSymbolAddress((void**)&q, g_q);

    cudaFuncSetAttribute(fc11_mma2, cudaFuncAttributeMaxDynamicSharedMemorySize, 98304);

    // 1: x conversion                      2: fc11_w conversion
    cvt_bf16<<<(Bb * (KP / 8)) / 256, 256>>>(x, xb);
    cvt_bf16<<<(Ee * (KP / 8)) / 256, 256>>>(fc11_w, wb);
    // 3: fc12_w + q_w conversion in one launch
    cvt_two<<<(Ee * Ee / 8 + Dd * Ee / 8) / 256, 256>>>(fc12_w, fc12b, Ee * Ee / 8, q_w, qwb);
    // 4: fc11 GEMM (3-stage cp.async, split-K=9)  <- profiled launch
    fc11_mma2<<<dim3(Ee / 128, Bb / 128, SPLIT), 256, 98304>>>();
    // 5: reduce partials -> e1 (bf16)
    fc11_reduce<<<(Bb * Ee) / 256, 256>>>(fc11_b);
    // 6: h_bow (bf16 out only)
    mma_gemm<1, 1><<<dim3(Ee / 128, Bb / 128), 256>>>(e1b, fc12b, fc12_b, (float*)0, hbowb, Ee, Ee);
    // 7: q (fp32 out)
    mma_gemm<0, 0><<<dim3(Dd / 128, Bb / 128), 256>>>(hbowb, qwb, q_b, q, (__nv_bfloat16*)0, Dd, Ee);
    // 8..: rest
    gemm_qk<<<dim3(Dd / 64, Bb / 64), 256>>>(k_w);
    attn_kernel<<<Bb, 256>>>(emb, k_b, lengths);
    gemm_di<<<dim3(Dd / 64, Bb / 64), 256>>>(v_w, v_b);
    gemm_mulv<<<dim3(2, Bb / 64, 2), 256>>>(mean_w, mean_b, logvar_w, logvar_b);
    bn_both<<<2 * Tt, 256>>>(mean_bn_b, logvar_bn_b);
    theta_kl_kernel<<<Bb, 128>>>();
    gemm_logit<<<dim3((Vv + 63) / 64, Bb / 64), 256>>>(dec_w, dec_b);
    colstats_kernel<<<(Vv + 255) / 256, 256>>>();
    recon_kernel<<<Bb, 256>>>(dec_bn_b, x);
    final_reduce<<<1, Bb>>>((float*)d_out);
}

// round 13
// speedup vs baseline: 2.4950x; 1.0942x over previous
#include <cuda_runtime.h>
#include <cuda_bf16.h>
#include <math.h>
#include <stdint.h>

#define Bb 512
#define Mm 64
#define Vv 20000
#define Ee 1024
#define Dd 384
#define Tt 100
#define SPLIT 9
#define KP 20032            // Vv padded to multiple of 64
#define KTOT 313            // KP / 64

// ---------------- scratch (device globals; no allocations allowed) ----------
__device__ __nv_bfloat16 g_xb[(size_t)Bb * KP];   // 20.5 MB
__device__ __nv_bfloat16 g_wb[(size_t)Ee * KP];   // 41 MB
__device__ float g_part[SPLIT * Bb * Ee];         // 18.9 MB
__device__ __nv_bfloat16 g_e1b[Bb * Ee];
__device__ __nv_bfloat16 g_fc12b[Ee * Ee];
__device__ __nv_bfloat16 g_qwb[Dd * Ee];
__device__ __nv_bfloat16 g_hbowb[Bb * Ee];
__device__ __nv_bfloat16 g_qb[Bb * Dd];
__device__ __nv_bfloat16 g_kwtb[Dd * Dd];
__device__ __nv_bfloat16 g_vwb[Dd * Dd];
__device__ __nv_bfloat16 g_ebarb[Bb * Dd];
__device__ float g_zeros[Dd];                     // zero-initialized, never written
__device__ float g_q[Bb * Dd];
__device__ float g_qk[Bb * Dd];
__device__ float g_di[Bb * Dd];
__device__ float g_mu[Bb * Tt];
__device__ float g_lv[Bb * Tt];
__device__ float g_theta[Bb * Tt];
__device__ float g_logit[(size_t)Bb * Vv];
__device__ float g_colmu[Vv];
__device__ float g_colinv[Vv];
__device__ float g_recon[Bb];
__device__ float g_kl[Bb];

__device__ __forceinline__ float softplus_f(float x) {
    return x > 0.f ? x + log1pf(expf(-x)) : log1pf(expf(x));
}
__device__ __forceinline__ uint32_t smem_u32(const void* p) {
    uint32_t a;
    asm("{ .reg .u64 t; cvta.to.shared.u64 t, %1; cvt.u32.u64 %0, t; }"
        : "=r"(a) : "l"(p));
    return a;
}
__device__ __forceinline__ uint32_t lds32(uint32_t addr) {
    uint32_t v;
    asm volatile("ld.shared.b32 %0, [%1];" : "=r"(v) : "r"(addr));
    return v;
}

// ---------------- fp32 -> bf16 conversions -----------------------------------
__global__ void cvt_bf16(const float* __restrict__ src, __nv_bfloat16* __restrict__ dst) {
    const int idx = blockIdx.x * 256 + threadIdx.x;
    const int row = idx / (KP / 8);
    const int cp = (idx % (KP / 8)) * 8;
    __nv_bfloat16 o[8];
    if (cp + 8 <= Vv) {
        const float4 v0 = *(const float4*)&src[(size_t)row * Vv + cp];
        const float4 v1 = *(const float4*)&src[(size_t)row * Vv + cp + 4];
        o[0] = __float2bfloat16(v0.x); o[1] = __float2bfloat16(v0.y);
        o[2] = __float2bfloat16(v0.z); o[3] = __float2bfloat16(v0.w);
        o[4] = __float2bfloat16(v1.x); o[5] = __float2bfloat16(v1.y);
        o[6] = __float2bfloat16(v1.z); o[7] = __float2bfloat16(v1.w);
    } else {
#pragma unroll
        for (int i = 0; i < 8; i++) o[i] = __float2bfloat16(0.f);
    }
    *(uint4*)&dst[(size_t)row * KP + cp] = *(uint4*)o;
}

// two plain conversions in one launch (lengths in 8-elem units)
__global__ void cvt_two(const float* __restrict__ sa, __nv_bfloat16* __restrict__ da, int na8,
                        const float* __restrict__ sb, __nv_bfloat16* __restrict__ db) {
    const int idx = blockIdx.x * 256 + threadIdx.x;
    const float* s;
    __nv_bfloat16* d;
    int i;
    if (idx < na8) { s = sa; d = da; i = idx * 8; }
    else           { s = sb; d = db; i = (idx - na8) * 8; }
    const float4 v0 = *(const float4*)&s[i];
    const float4 v1 = *(const float4*)&s[i + 4];
    __nv_bfloat16 o[8];
    o[0] = __float2bfloat16(v0.x); o[1] = __float2bfloat16(v0.y);
    o[2] = __float2bfloat16(v0.z); o[3] = __float2bfloat16(v0.w);
    o[4] = __float2bfloat16(v1.x); o[5] = __float2bfloat16(v1.y);
    o[6] = __float2bfloat16(v1.z); o[7] = __float2bfloat16(v1.w);
    *(uint4*)&d[i] = *(uint4*)o;
}

// k_w transpose-convert (kwt[d][e] = kw[e][d]) + v_w plain convert, one launch.
// Blocks [0,144): 32x32 transpose tiles (12x12 grid over 384x384).
// Blocks [144,216): plain convert of v_w (384*384/8/256 = 72 blocks).
__global__ void cvt_small(const float* __restrict__ kw, __nv_bfloat16* __restrict__ kwt,
                          const float* __restrict__ vw, __nv_bfloat16* __restrict__ vwb) {
    if (blockIdx.x < 144) {
        __shared__ float t[32][33];
        const int bx = (blockIdx.x % 12) * 32, by = (blockIdx.x / 12) * 32;
        const int tx = threadIdx.x & 31, ty = threadIdx.x >> 5;  // 32x8
#pragma unroll
        for (int i = 0; i < 32; i += 8)
            t[ty + i][tx] = kw[(size_t)(by + ty + i) * Dd + bx + tx];
        __syncthreads();
#pragma unroll
        for (int i = 0; i < 32; i += 8)
            kwt[(size_t)(bx + ty + i) * Dd + by + tx] = __float2bfloat16(t[tx][ty + i]);
    } else {
        const int i = ((blockIdx.x - 144) * 256 + threadIdx.x) * 8;
        const float4 v0 = *(const float4*)&vw[i];
        const float4 v1 = *(const float4*)&vw[i + 4];
        __nv_bfloat16 o[8];
        o[0] = __float2bfloat16(v0.x); o[1] = __float2bfloat16(v0.y);
        o[2] = __float2bfloat16(v0.z); o[3] = __float2bfloat16(v0.w);
        o[4] = __float2bfloat16(v1.x); o[5] = __float2bfloat16(v1.y);
        o[6] = __float2bfloat16(v1.z); o[7] = __float2bfloat16(v1.w);
        *(uint4*)&vwb[i] = *(uint4*)o;
    }
}

// ---------------- warp-level bf16 MMA (arch-neutral PTX, sm_80+) ------------
__device__ __forceinline__ void mma16816(float* c, const uint32_t* a, const uint32_t* b) {
    asm volatile(
        "mma.sync.aligned.m16n8k16.row.col.f32.bf16.bf16.f32 "
        "{%0,%1,%2,%3}, {%4,%5,%6,%7}, {%8,%9}, {%0,%1,%2,%3};"
        : "+f"(c[0]), "+f"(c[1]), "+f"(c[2]), "+f"(c[3])
        : "r"(a[0]), "r"(a[1]), "r"(a[2]), "r"(a[3]), "r"(b[0]), "r"(b[1]));
}

// ===================== fc11 via cp.async 3-stage + mma.sync ==================
__device__ __forceinline__ void fc11_load_stage(uint32_t sbase, int st, int kt,
                                                int bm, int bn, int tid) {
    const int k0 = kt * 64;
    const uint32_t abase = sbase + st * 32768;
    const uint32_t bbase = abase + 16384;
#pragma unroll
    for (int i = 0; i < 4; i++) {
        const int idx = tid + 256 * i;
        const int row = idx >> 3, ch = idx & 7;
        const uint32_t off = (uint32_t)row * 128u + (uint32_t)((ch ^ (row & 7)) << 4);
        const void* asrc = &g_xb[(size_t)(bm + row) * KP + k0 + ch * 8];
        asm volatile("cp.async.cg.shared.global [%0], [%1], 16;"
                     :: "r"(abase + off), "l"(asrc));
        const void* bsrc = &g_wb[(size_t)(bn + row) * KP + k0 + ch * 8];
        asm volatile("cp.async.cg.shared.global [%0], [%1], 16;"
                     :: "r"(bbase + off), "l"(bsrc));
    }
    asm volatile("cp.async.commit_group;");
}

__device__ __forceinline__ uint32_t swz(uint32_t row, uint32_t bytecol) {
    return row * 128u + ((((bytecol >> 4) ^ (row & 7u))) << 4) + (bytecol & 15u);
}

__global__ __launch_bounds__(256, 2) void fc11_mma2() {
    extern __shared__ char dynsmem[];
    const uint32_t sbase = smem_u32(dynsmem);
    const int tid = threadIdx.x;
    const int wid = tid >> 5, lane = tid & 31;
    const int wr = wid >> 2, wc = wid & 3;
    const int l4 = lane >> 2, lq = lane & 3;
    const int bn = blockIdx.x * 128;
    const int bm = blockIdx.y * 128;
    const int s = blockIdx.z;
    const int kt0 = (s * KTOT) / SPLIT, kt1 = ((s + 1) * KTOT) / SPLIT;
    const int niter = kt1 - kt0;

    float c[4][4][4];
#pragma unroll
    for (int i = 0; i < 4; i++)
#pragma unroll
        for (int j = 0; j < 4; j++)
#pragma unroll
            for (int u = 0; u < 4; u++) c[i][j][u] = 0.f;

    fc11_load_stage(sbase, 0, kt0, bm, bn, tid);
    if (niter > 1) fc11_load_stage(sbase, 1, kt0 + 1, bm, bn, tid);

    int st = 0;
    for (int t = 0; t < niter; t++) {
        if (t + 2 < niter) {
            int st2 = st + 2; if (st2 >= 3) st2 -= 3;
            fc11_load_stage(sbase, st2, kt0 + t + 2, bm, bn, tid);
            asm volatile("cp.async.wait_group 2;");
        } else if (t + 1 < niter) {
            asm volatile("cp.async.wait_group 1;");
        } else {
            asm volatile("cp.async.wait_group 0;");
        }
        __syncthreads();

        const uint32_t abase = sbase + st * 32768;
        const uint32_t bbase = abase + 16384;
#pragma unroll
        for (int kk = 0; kk < 4; kk++) {
            const uint32_t bytecol = (uint32_t)(kk * 32 + lq * 4);
            uint32_t a[4][4], b[4][2];
#pragma unroll
            for (int i = 0; i < 4; i++) {
                const uint32_t r = (uint32_t)(wr * 64 + i * 16 + l4);
                a[i][0] = lds32(abase + swz(r, bytecol));
                a[i][1] = lds32(abase + swz(r + 8, bytecol));
                a[i][2] = lds32(abase + swz(r, bytecol + 16));
                a[i][3] = lds32(abase + swz(r + 8, bytecol + 16));
            }
#pragma unroll
            for (int j = 0; j < 4; j++) {
                const uint32_t n = (uint32_t)(wc * 32 + j * 8 + l4);
                b[j][0] = lds32(bbase + swz(n, bytecol));
                b[j][1] = lds32(bbase + swz(n, bytecol + 16));
            }
#pragma unroll
            for (int i = 0; i < 4; i++)
#pragma unroll
                for (int j = 0; j < 4; j++) mma16816(c[i][j], a[i], b[j]);
        }
        __syncthreads();
        if (++st >= 3) st = 0;
    }

#pragma unroll
    for (int i = 0; i < 4; i++) {
        const int row0 = bm + wr * 64 + i * 16 + l4;
#pragma unroll
        for (int j = 0; j < 4; j++) {
            const int col = bn + wc * 32 + j * 8 + lq * 2;
            float* p0 = g_part + ((size_t)s * Bb + row0) * Ee + col;
            float* p1 = g_part + ((size_t)s * Bb + row0 + 8) * Ee + col;
            p0[0] = c[i][j][0]; p0[1] = c[i][j][1];
            p1[0] = c[i][j][2]; p1[1] = c[i][j][3];
        }
    }
}

__global__ void fc11_reduce(const float* __restrict__ bias) {
    const int i = blockIdx.x * 256 + threadIdx.x;
    float v = bias[i & (Ee - 1)];
#pragma unroll
    for (int s = 0; s < SPLIT; s++) v += g_part[(size_t)s * (Bb * Ee) + i];
    g_e1b[i] = __float2bfloat16(softplus_f(v));
}

// ===================== generic bf16 mma GEMM (single-buffer, PADR) ===========
// MODE: 0 = fp32 out only, 1 = bf16 out only, 2 = both
#define PADR 72
template <int ACT, int MODE>
__global__ __launch_bounds__(256) void mma_gemm(const __nv_bfloat16* __restrict__ A,
                                                const __nv_bfloat16* __restrict__ W,
                                                const float* __restrict__ bias,
                                                float* __restrict__ C,
                                                __nv_bfloat16* __restrict__ Cb,
                                                int N, int K) {
    __shared__ __nv_bfloat16 As[128][PADR];
    __shared__ __nv_bfloat16 Bs[128][PADR];
    const int tid = threadIdx.x;
    const int wid = tid >> 5, lane = tid & 31;
    const int wr = wid >> 2, wc = wid & 3;
    const int l4 = lane >> 2, lq = lane & 3;
    const int bn = blockIdx.x * 128;
    const int bm = blockIdx.y * 128;

    float c[4][4][4];
#pragma unroll
    for (int i = 0; i < 4; i++)
#pragma unroll
        for (int j = 0; j < 4; j++)
#pragma unroll
            for (int u = 0; u < 4; u++) c[i][j][u] = 0.f;

    for (int k0 = 0; k0 < K; k0 += 64) {
#pragma unroll
        for (int i = 0; i < 4; i++) {
            const int idx = tid + 256 * i;
            const int row = idx >> 3, ch = idx & 7;
            uint4 va = *(const uint4*)&A[(size_t)(bm + row) * K + k0 + ch * 8];
            *(uint4*)&As[row][ch * 8] = va;
            uint4 vb = *(const uint4*)&W[(size_t)(bn + row) * K + k0 + ch * 8];
            *(uint4*)&Bs[row][ch * 8] = vb;
        }
        __syncthreads();

#pragma unroll
        for (int kk = 0; kk < 4; kk++) {
            const int kb = kk * 16 + lq * 2;
            uint32_t a[4][4], b[4][2];
#pragma unroll
            for (int i = 0; i < 4; i++) {
                const int r = wr * 64 + i * 16 + l4;
                a[i][0] = *(const uint32_t*)&As[r][kb];
                a[i][1] = *(const uint32_t*)&As[r + 8][kb];
                a[i][2] = *(const uint32_t*)&As[r][kb + 8];
                a[i][3] = *(const uint32_t*)&As[r + 8][kb + 8];
            }
#pragma unroll
            for (int j = 0; j < 4; j++) {
                const int n = wc * 32 + j * 8 + l4;
                b[j][0] = *(const uint32_t*)&Bs[n][kb];
                b[j][1] = *(const uint32_t*)&Bs[n][kb + 8];
            }
#pragma unroll
            for (int i = 0; i < 4; i++)
#pragma unroll
                for (int j = 0; j < 4; j++) mma16816(c[i][j], a[i], b[j]);
        }
        __syncthreads();
    }

#pragma unroll
    for (int i = 0; i < 4; i++) {
        const int row0 = bm + wr * 64 + i * 16 + l4;
#pragma unroll
        for (int j = 0; j < 4; j++) {
            const int col = bn + wc * 32 + j * 8 + lq * 2;
#pragma unroll
            for (int h = 0; h < 2; h++) {
                const int row = row0 + h * 8;
#pragma unroll
                for (int u = 0; u < 2; u++) {
                    float v = c[i][j][h * 2 + u] + bias[col + u];
                    if (ACT == 1) v = softplus_f(v);
                    if (MODE == 0 || MODE == 2) C[(size_t)row * N + col + u] = v;
                    if (MODE == 1 || MODE == 2)
                        Cb[(size_t)row * N + col + u] = __float2bfloat16(v);
                }
            }
        }
    }
}

// ---------------- packed f32x2 helpers --------------------------------------
__device__ __forceinline__ unsigned long long pk2(float x, float y) {
    unsigned long long r;
    asm("mov.b64 %0, {%1, %2};" : "=l"(r) : "f"(x), "f"(y));
    return r;
}
__device__ __forceinline__ unsigned long long fma2(unsigned long long a,
                                                   unsigned long long b,
                                                   unsigned long long c) {
    unsigned long long d;
    asm("fma.rn.f32x2 %0, %1, %2, %3;" : "=l"(d) : "l"(a), "l"(b), "l"(c));
    return d;
}
__device__ __forceinline__ void upk2(unsigned long long v, float& lo, float& hi) {
    asm("mov.b64 {%0, %1}, %2;" : "=f"(lo), "=f"(hi) : "l"(v));
}

// ---------------- generic fp32 GEMM body (register double-buffered) ---------
template <int ACT, bool BNT>
__device__ __forceinline__ void gemm64_body(const float* __restrict__ A,
                                            const float* __restrict__ Bm,
                                            const float* __restrict__ bias,
                                            float* __restrict__ C,
                                            int M, int N, int K) {
    __shared__ float As[16][64];
    __shared__ float Bs[16][64];
    const int bm = blockIdx.y * 64, bn = blockIdx.x * 64;
    const int tid = threadIdx.x;
    const int tr = tid >> 4, tc = tid & 15;
    const int lrow = tid >> 4;
    const int lk = tid & 15;

    unsigned long long acc[4][2];
#pragma unroll
    for (int i = 0; i < 4; i++) { acc[i][0] = 0ull; acc[i][1] = 0ull; }

    float pa[4], pb[4], na[4], nb[4];

#pragma unroll
    for (int i = 0; i < 4; i++) {
        int r = lrow + i * 16;
        int gk = lk;
        int gm = bm + r;
        pa[i] = (gm < M && gk < K) ? A[(size_t)gm * K + gk] : 0.f;
        int gn = bn + r;
        float v = 0.f;
        if (gn < N && gk < K)
            v = BNT ? Bm[(size_t)gn * K + gk] : Bm[(size_t)gk * N + gn];
        pb[i] = v;
    }

    for (int k0 = 0; k0 < K; k0 += 16) {
#pragma unroll
        for (int i = 0; i < 4; i++) {
            int r = lrow + i * 16;
            As[lk][r] = pa[i];
            Bs[lk][r] = pb[i];
        }
        __syncthreads();

        if (k0 + 16 < K) {
#pragma unroll
            for (int i = 0; i < 4; i++) {
                int r = lrow + i * 16;
                int gk = k0 + 16 + lk;
                int gm = bm + r;
                na[i] = (gm < M && gk < K) ? A[(size_t)gm * K + gk] : 0.f;
                int gn = bn + r;
                float v = 0.f;
                if (gn < N && gk < K)
                    v = BNT ? Bm[(size_t)gn * K + gk] : Bm[(size_t)gk * N + gn];
                nb[i] = v;
            }
        }

#pragma unroll
        for (int kk = 0; kk < 16; kk++) {
            float a0 = As[kk][tr * 4 + 0];
            float a1 = As[kk][tr * 4 + 1];
            float a2 = As[kk][tr * 4 + 2];
            float a3 = As[kk][tr * 4 + 3];
            unsigned long long b0 =
                *reinterpret_cast<const unsigned long long*>(&Bs[kk][tc * 4]);
            unsigned long long b1 =
                *reinterpret_cast<const unsigned long long*>(&Bs[kk][tc * 4 + 2]);
            unsigned long long A0 = pk2(a0, a0), A1 = pk2(a1, a1);
            unsigned long long A2 = pk2(a2, a2), A3 = pk2(a3, a3);
            acc[0][0] = fma2(A0, b0, acc[0][0]); acc[0][1] = fma2(A0, b1, acc[0][1]);
            acc[1][0] = fma2(A1, b0, acc[1][0]); acc[1][1] = fma2(A1, b1, acc[1][1]);
            acc[2][0] = fma2(A2, b0, acc[2][0]); acc[2][1] = fma2(A2, b1, acc[2][1]);
            acc[3][0] = fma2(A3, b0, acc[3][0]); acc[3][1] = fma2(A3, b1, acc[3][1]);
        }
        __syncthreads();
#pragma unroll
        for (int i = 0; i < 4; i++) { pa[i] = na[i]; pb[i] = nb[i]; }
    }

#pragma unroll
    for (int i = 0; i < 4; i++) {
        int gm = bm + tr * 4 + i;
        if (gm >= M) continue;
#pragma unroll
        for (int j2 = 0; j2 < 2; j2++) {
            float lo, hi;
            upk2(acc[i][j2], lo, hi);
            float vals[2] = {lo, hi};
#pragma unroll
            for (int u = 0; u < 2; u++) {
                int gn = bn + tc * 4 + j2 * 2 + u;
                if (gn < N) {
                    float v = vals[u] + (bias ? bias[gn] : 0.f);
                    if (ACT == 1) v = softplus_f(v);
                    C[(size_t)gm * N + gn] = v;
                }
            }
        }
    }
}

// ---- wrapper kernels binding scratch globals --------------------------------
// mu and lv fused into one launch via blockIdx.z
__global__ void gemm_mulv(const float* __restrict__ Wm, const float* __restrict__ bm_,
                          const float* __restrict__ Wl, const float* __restrict__ bl_) {
    if (blockIdx.z == 0)
        gemm64_body<0, true>(g_di, Wm, bm_, g_mu, Bb, Tt, Dd);
    else
        gemm64_body<0, true>(g_di, Wl, bl_, g_lv, Bb, Tt, Dd);
}
__global__ void gemm_logit(const float* __restrict__ W, const float* __restrict__ b) {
    gemm64_body<0, true>(g_theta, W, b, g_logit, Bb, Vv, Tt);
}

// ---------------- fused ragged single-query attention -----------------------
__global__ void attn_kernel(const float* __restrict__ emb,
                            const float* __restrict__ kb,
                            const int* __restrict__ lengths) {
    const int b = blockIdx.x, tid = threadIdx.x;  // 256 threads
    __shared__ float s_qk[Dd];
    __shared__ float s_sc[Mm];
    __shared__ float red[256];
    __shared__ float s_kbdot;
    const int len = lengths[b];

    float part = 0.f;
    for (int d = tid; d < Dd; d += 256) {
        s_qk[d] = g_qk[b * Dd + d];
        part += g_q[b * Dd + d] * kb[d];
    }
    red[tid] = part;
    __syncthreads();
    for (int s = 128; s > 0; s >>= 1) {
        if (tid < s) red[tid] += red[tid + s];
        __syncthreads();
    }
    if (tid == 0) s_kbdot = red[0];
    __syncthreads();
    const float kbdot = s_kbdot;

    const int wid = tid >> 5, lane = tid & 31;
    const float scale = 0.051031036307982884f;  // 1/sqrt(384)
    for (int m = wid; m < Mm; m += 8) {
        const float* er = emb + ((size_t)b * Mm + m) * Dd;
        float sum = 0.f;
#pragma unroll
        for (int i = 0; i < Dd / 32; i++) {
            int d = lane + 32 * i;
            sum += er[d] * s_qk[d];
        }
#pragma unroll
        for (int o = 16; o > 0; o >>= 1) sum += __shfl_xor_sync(0xffffffffu, sum, o);
        if (lane == 0) s_sc[m] = (m < len) ? (sum + kbdot) * scale : -1e30f;
    }
    __syncthreads();

    if (wid == 0) {
        float v0 = s_sc[lane], v1 = s_sc[lane + 32];
        float mx = fmaxf(v0, v1);
#pragma unroll
        for (int o = 16; o > 0; o >>= 1) mx = fmaxf(mx, __shfl_xor_sync(0xffffffffu, mx, o));
        float e0 = expf(v0 - mx), e1 = expf(v1 - mx);
        float ss = e0 + e1;
#pragma unroll
        for (int o = 16; o > 0; o >>= 1) ss += __shfl_xor_sync(0xffffffffu, ss, o);
        float inv = 1.f / ss;
        s_sc[lane] = e0 * inv;
        s_sc[lane + 32] = e1 * inv;
    }
    __syncthreads();

    for (int d = tid; d < Dd; d += 256) {
        float acc = 0.f;
#pragma unroll 8
        for (int m = 0; m < Mm; m++)
            acc += s_sc[m] * emb[((size_t)b * Mm + m) * Dd + d];
        g_ebarb[b * Dd + d] = __float2bfloat16(acc);
    }
}

// ---------------- BatchNorm over batch dim for [B,T], both arrays -----------
__global__ void bn_both(const float* __restrict__ bias_mu,
                        const float* __restrict__ bias_lv) {
    const int which = blockIdx.x >= Tt;
    const int t = which ? blockIdx.x - Tt : blockIdx.x;
    float* h = which ? g_lv : g_mu;
    const float* bias = which ? bias_lv : bias_mu;
    const int tid = threadIdx.x;  // 256
    __shared__ float red[256];
    __shared__ float s_mu, s_inv;
    float v0 = h[(size_t)tid * Tt + t];
    float v1 = h[(size_t)(tid + 256) * Tt + t];
    red[tid] = v0 + v1;
    __syncthreads();
    for (int s = 128; s > 0; s >>= 1) {
        if (tid < s) red[tid] += red[tid + s];
        __syncthreads();
    }
    if (tid == 0) s_mu = red[0] * (1.f / Bb);
    __syncthreads();
    float mu = s_mu;
    float d0 = v0 - mu, d1 = v1 - mu;
    red[tid] = d0 * d0 + d1 * d1;
    __syncthreads();
    for (int s = 128; s > 0; s >>= 1) {
        if (tid < s) red[tid] += red[tid + s];
        __syncthreads();
    }
    if (tid == 0) s_inv = rsqrtf(red[0] * (1.f / Bb) + 1e-5f);
    __syncthreads();
    float inv = s_inv, bbv = bias[t];
    h[(size_t)tid * Tt + t] = d0 * inv + bbv;
    h[(size_t)(tid + 256) * Tt + t] = d1 * inv + bbv;
}

// ---------------- theta = softmax(mu), kl per sample -------------------------
__global__ void theta_kl_kernel() {
    const int b = blockIdx.x, tid = threadIdx.x;  // 128
    __shared__ float red[128];
    __shared__ float s_mx, s_sum;
    const bool ok = tid < Tt;
    const float m = ok ? g_mu[b * Tt + tid] : -1e30f;
    const float l = ok ? g_lv[b * Tt + tid] : 0.f;
    red[tid] = m;
    __syncthreads();
    for (int s = 64; s > 0; s >>= 1) {
        if (tid < s) red[tid] = fmaxf(red[tid], red[tid + s]);
        __syncthreads();
    }
    if (tid == 0) s_mx = red[0];
    __syncthreads();
    const float e = ok ? expf(m - s_mx) : 0.f;
    red[tid] = e;
    __syncthreads();
    for (int s = 64; s > 0; s >>= 1) {
        if (tid < s) red[tid] += red[tid + s];
        __syncthreads();
    }
    if (tid == 0) s_sum = red[0];
    __syncthreads();
    if (ok) g_theta[b * Tt + tid] = e / s_sum;

    const float INV_VAR2 = 1.0101010101010102f;    // 1/(1 - 1/T), T=100
    const float LOGV2 = -0.010050335853501441f;    // log(0.99)
    float term = ok ? (expf(l) * INV_VAR2 + m * m * INV_VAR2 + LOGV2 - l) : 0.f;
    red[tid] = term;
    __syncthreads();
    for (int s = 64; s > 0; s >>= 1) {
        if (tid < s) red[tid] += red[tid + s];
        __syncthreads();
    }
    if (tid == 0) g_kl[b] = 0.5f * (red[0] - (float)Tt);
}

// ---------------- per-vocab-column batch stats of logit (single pass) -------
__global__ void colstats_kernel() {
    const int v = blockIdx.x * blockDim.x + threadIdx.x;
    if (v >= Vv) return;
    float s = 0.f, s2 = 0.f;
#pragma unroll 8
    for (int b = 0; b < Bb; b++) {
        float x = g_logit[(size_t)b * Vv + v];
        s += x;
        s2 += x * x;
    }
    const float mean = s * (1.f / Bb);
    float var = fmaxf(s2 * (1.f / Bb) - mean * mean, 0.f);
    g_colmu[v] = mean;
    g_colinv[v] = rsqrtf(var + 1e-5f);
}

// ---------------- per-sample reconstruction loss (tree-reduced tail) --------
__global__ void recon_kernel(const float* __restrict__ bnb,
                             const float* __restrict__ x) {
    const int b = blockIdx.x, tid = threadIdx.x;  // 256
    __shared__ float s_m[256], s_s[256], s_xh[256], s_x[256];
    float mx = -1e30f, sm = 0.f, xh = 0.f, xs = 0.f;
    for (int v = tid; v < Vv; v += 256) {
        float hn = (g_logit[(size_t)b * Vv + v] - g_colmu[v]) * g_colinv[v] + bnb[v];
        float xv = x[(size_t)b * Vv + v];
        xh += xv * hn;
        xs += xv;
        float nm = fmaxf(mx, hn);
        sm = sm * expf(mx - nm) + expf(hn - nm);
        mx = nm;
    }
    s_m[tid] = mx; s_s[tid] = sm; s_xh[tid] = xh; s_x[tid] = xs;
    __syncthreads();
    for (int st = 128; st > 0; st >>= 1) {
        if (tid < st) {
            float m2 = s_m[tid + st], sm2 = s_s[tid + st];
            float M = fmaxf(s_m[tid], m2);
            s_s[tid] = s_s[tid] * expf(s_m[tid] - M) + sm2 * expf(m2 - M);
            s_m[tid] = M;
            s_xh[tid] += s_xh[tid + st];
            s_x[tid] += s_x[tid + st];
        }
        __syncthreads();
    }
    if (tid == 0) {
        float lse = s_m[0] + logf(s_s[0]);
        g_recon[b] = lse * s_x[0] - s_xh[0];
    }
}

// ---------------- final scalar -----------------------------------------------
__global__ void final_reduce(float* __restrict__ out) {
    __shared__ float red[512];
    const int tid = threadIdx.x;
    red[tid] = g_recon[tid] + g_kl[tid];
    __syncthreads();
    for (int s = 256; s > 0; s >>= 1) {
        if (tid < s) red[tid] += red[tid + s];
        __syncthreads();
    }
    if (tid == 0) out[0] = red[0] * (1.f / Bb);
}

// =============================================================================
extern "C" void kernel_launch(void* const* d_in, const int* in_sizes, int n_in,
                              void* d_out, int out_size) {
    (void)in_sizes; (void)n_in; (void)out_size;
    const float* x        = (const float*)d_in[0];
    const float* emb      = (const float*)d_in[1];
    const int*   lengths  = (const int*)d_in[2];
    const float* fc11_w   = (const float*)d_in[3];
    const float* fc11_b   = (const float*)d_in[4];
    const float* fc12_w   = (const float*)d_in[5];
    const float* fc12_b   = (const float*)d_in[6];
    const float* q_w      = (const float*)d_in[7];
    const float* q_b      = (const float*)d_in[8];
    const float* k_w      = (const float*)d_in[9];
    const float* k_b      = (const float*)d_in[10];
    const float* v_w      = (const float*)d_in[11];
    const float* v_b      = (const float*)d_in[12];
    const float* mean_w   = (const float*)d_in[13];
    const float* mean_b   = (const float*)d_in[14];
    const float* logvar_w = (const float*)d_in[15];
    const float* logvar_b = (const float*)d_in[16];
    const float* mean_bn_b   = (const float*)d_in[17];
    const float* logvar_bn_b = (const float*)d_in[18];
    const float* dec_w    = (const float*)d_in[19];
    const float* dec_b    = (const float*)d_in[20];
    const float* dec_bn_b = (const float*)d_in[21];

    __nv_bfloat16 *xb, *wb, *fc12b, *qwb, *e1b, *hbowb, *qb, *kwtb, *vwb, *ebarb;
    cudaGetSymbolAddress((void**)&xb, g_xb);
    cudaGetSymbolAddress((void**)&wb, g_wb);
    cudaGetSymbolAddress((void**)&fc12b, g_fc12b);
    cudaGetSymbolAddress((void**)&qwb, g_qwb);
    cudaGetSymbolAddress((void**)&e1b, g_e1b);
    cudaGetSymbolAddress((void**)&hbowb, g_hbowb);
    cudaGetSymbolAddress((void**)&qb, g_qb);
    cudaGetSymbolAddress((void**)&kwtb, g_kwtb);
    cudaGetSymbolAddress((void**)&vwb, g_vwb);
    cudaGetSymbolAddress((void**)&ebarb, g_ebarb);
    float *q, *qk, *di, *zeros;
    cudaGetSymbolAddress((void**)&q, g_q);
    cudaGetSymbolAddress((void**)&qk, g_qk);
    cudaGetSymbolAddress((void**)&di, g_di);
    cudaGetSymbolAddress((void**)&zeros, g_zeros);

    cudaFuncSetAttribute(fc11_mma2, cudaFuncAttributeMaxDynamicSharedMemorySize, 98304);

    // 1: x conversion                      2: fc11_w conversion
    cvt_bf16<<<(Bb * (KP / 8)) / 256, 256>>>(x, xb);
    cvt_bf16<<<(Ee * (KP / 8)) / 256, 256>>>(fc11_w, wb);
    // 3: fc12_w + q_w conversion in one launch
    cvt_two<<<(Ee * Ee / 8 + Dd * Ee / 8) / 256, 256>>>(fc12_w, fc12b, Ee * Ee / 8, q_w, qwb);
    // 4: fc11 GEMM (3-stage cp.async, split-K=9)  <- profiled launch
    fc11_mma2<<<dim3(Ee / 128, Bb / 128, SPLIT), 256, 98304>>>();
    // 5: reduce partials -> e1 (bf16)
    fc11_reduce<<<(Bb * Ee) / 256, 256>>>(fc11_b);
    // 6: h_bow (bf16 out)
    mma_gemm<1, 1><<<dim3(Ee / 128, Bb / 128), 256>>>(e1b, fc12b, fc12_b, (float*)0, hbowb, Ee, Ee);
    // 7: q (fp32 + bf16 out)
    mma_gemm<0, 2><<<dim3(Dd / 128, Bb / 128), 256>>>(hbowb, qwb, q_b, q, qb, Dd, Ee);
    // 8: k_w transpose-convert + v_w convert (needed by 9 and 11)
    cvt_small<<<216, 256>>>(k_w, kwtb, v_w, vwb);
    // 9: qk = q @ k_w  (bf16 mma, zero bias)
    mma_gemm<0, 0><<<dim3(Dd / 128, Bb / 128), 256>>>(qb, kwtb, zeros, qk, (__nv_bfloat16*)0, Dd, Dd);
    // 10: attention -> ebar (bf16)
    attn_kernel<<<Bb, 256>>>(emb, k_b, lengths);
    // 11: d_i = ebar @ v_w^T + v_b  (bf16 mma)
    mma_gemm<0, 0><<<dim3(Dd / 128, Bb / 128), 256>>>(ebarb, vwb, v_b, di, (__nv_bfloat16*)0, Dd, Dd);
    // 12..: tail
    gemm_mulv<<<dim3(2, Bb / 64, 2), 256>>>(mean_w, mean_b, logvar_w, logvar_b);
    bn_both<<<2 * Tt, 256>>>(mean_bn_b, logvar_bn_b);
    theta_kl_kernel<<<Bb, 128>>>();
    gemm_logit<<<dim3((Vv + 63) / 64, Bb / 64), 256>>>(dec_w, dec_b);
    colstats_kernel<<<(Vv + 255) / 256, 256>>>();
    recon_kernel<<<Bb, 256>>>(dec_bn_b, x);
    final_reduce<<<1, Bb>>>((float*)d_out);
}

// round 14
// speedup vs baseline: 3.1498x; 1.2625x over previous
#include <cuda_runtime.h>
#include <cuda_bf16.h>
#include <math.h>
#include <stdint.h>

#define Bb 512
#define Mm 64
#define Vv 20000
#define VP 20096            // Vv padded to multiple of 128 (N tiles for logit mma)
#define Ee 1024
#define Dd 384
#define Tt 100
#define TP 128              // Tt padded to 128 (K for logit mma)
#define SPLIT 9
#define KP 20032            // Vv padded to multiple of 64
#define KTOT 313            // KP / 64

// ---------------- scratch (device globals; no allocations allowed) ----------
__device__ __nv_bfloat16 g_xb[(size_t)Bb * KP];   // 20.5 MB
__device__ __nv_bfloat16 g_wb[(size_t)Ee * KP];   // 41 MB
__device__ float g_part[SPLIT * Bb * Ee];         // 18.9 MB
__device__ __nv_bfloat16 g_e1b[Bb * Ee];
__device__ __nv_bfloat16 g_fc12b[Ee * Ee];
__device__ __nv_bfloat16 g_qwb[Dd * Ee];
__device__ __nv_bfloat16 g_hbowb[Bb * Ee];
__device__ __nv_bfloat16 g_qb[Bb * Dd];
__device__ __nv_bfloat16 g_kwtb[Dd * Dd];
__device__ __nv_bfloat16 g_vwb[Dd * Dd];
__device__ __nv_bfloat16 g_ebarb[Bb * Dd];
__device__ __nv_bfloat16 g_thetab[Bb * TP];
__device__ __nv_bfloat16 g_decwb[(size_t)VP * TP];  // 5.1 MB
__device__ float g_zeros[Dd];                     // zero-initialized, never written
__device__ float g_q[Bb * Dd];
__device__ float g_qk[Bb * Dd];
__device__ float g_di[Bb * Dd];
__device__ float g_mu[Bb * Tt];
__device__ float g_lv[Bb * Tt];
__device__ float g_logit[(size_t)Bb * Vv];
__device__ float g_colmu[Vv];
__device__ float g_colinv[Vv];
__device__ float g_recon[Bb];
__device__ float g_kl[Bb];

__device__ __forceinline__ float softplus_f(float x) {
    return x > 0.f ? x + log1pf(expf(-x)) : log1pf(expf(x));
}
__device__ __forceinline__ uint32_t smem_u32(const void* p) {
    uint32_t a;
    asm("{ .reg .u64 t; cvta.to.shared.u64 t, %1; cvt.u32.u64 %0, t; }"
        : "=r"(a) : "l"(p));
    return a;
}
__device__ __forceinline__ void ldsm_x4(uint32_t* r, uint32_t addr) {
    asm volatile("ldmatrix.sync.aligned.m8n8.x4.shared.b16 {%0,%1,%2,%3}, [%4];"
                 : "=r"(r[0]), "=r"(r[1]), "=r"(r[2]), "=r"(r[3]) : "r"(addr));
}

// ---------------- fp32 -> bf16 conversions -----------------------------------
__global__ void cvt_bf16(const float* __restrict__ src, __nv_bfloat16* __restrict__ dst) {
    const int idx = blockIdx.x * 256 + threadIdx.x;
    const int row = idx / (KP / 8);
    const int cp = (idx % (KP / 8)) * 8;
    __nv_bfloat16 o[8];
    if (cp + 8 <= Vv) {
        const float4 v0 = *(const float4*)&src[(size_t)row * Vv + cp];
        const float4 v1 = *(const float4*)&src[(size_t)row * Vv + cp + 4];
        o[0] = __float2bfloat16(v0.x); o[1] = __float2bfloat16(v0.y);
        o[2] = __float2bfloat16(v0.z); o[3] = __float2bfloat16(v0.w);
        o[4] = __float2bfloat16(v1.x); o[5] = __float2bfloat16(v1.y);
        o[6] = __float2bfloat16(v1.z); o[7] = __float2bfloat16(v1.w);
    } else {
#pragma unroll
        for (int i = 0; i < 8; i++) o[i] = __float2bfloat16(0.f);
    }
    *(uint4*)&dst[(size_t)row * KP + cp] = *(uint4*)o;
}

// two plain conversions in one launch (lengths in 8-elem units)
__global__ void cvt_two(const float* __restrict__ sa, __nv_bfloat16* __restrict__ da, int na8,
                        const float* __restrict__ sb, __nv_bfloat16* __restrict__ db) {
    const int idx = blockIdx.x * 256 + threadIdx.x;
    const float* s;
    __nv_bfloat16* d;
    int i;
    if (idx < na8) { s = sa; d = da; i = idx * 8; }
    else           { s = sb; d = db; i = (idx - na8) * 8; }
    const float4 v0 = *(const float4*)&s[i];
    const float4 v1 = *(const float4*)&s[i + 4];
    __nv_bfloat16 o[8];
    o[0] = __float2bfloat16(v0.x); o[1] = __float2bfloat16(v0.y);
    o[2] = __float2bfloat16(v0.z); o[3] = __float2bfloat16(v0.w);
    o[4] = __float2bfloat16(v1.x); o[5] = __float2bfloat16(v1.y);
    o[6] = __float2bfloat16(v1.z); o[7] = __float2bfloat16(v1.w);
    *(uint4*)&d[i] = *(uint4*)o;
}

// k_w transpose-convert + v_w plain convert, one launch.
__global__ void cvt_small(const float* __restrict__ kw, __nv_bfloat16* __restrict__ kwt,
                          const float* __restrict__ vw, __nv_bfloat16* __restrict__ vwb) {
    if (blockIdx.x < 144) {
        __shared__ float t[32][33];
        const int bx = (blockIdx.x % 12) * 32, by = (blockIdx.x / 12) * 32;
        const int tx = threadIdx.x & 31, ty = threadIdx.x >> 5;  // 32x8
#pragma unroll
        for (int i = 0; i < 32; i += 8)
            t[ty + i][tx] = kw[(size_t)(by + ty + i) * Dd + bx + tx];
        __syncthreads();
#pragma unroll
        for (int i = 0; i < 32; i += 8)
            kwt[(size_t)(bx + ty + i) * Dd + by + tx] = __float2bfloat16(t[tx][ty + i]);
    } else {
        const int i = ((blockIdx.x - 144) * 256 + threadIdx.x) * 8;
        const float4 v0 = *(const float4*)&vw[i];
        const float4 v1 = *(const float4*)&vw[i + 4];
        __nv_bfloat16 o[8];
        o[0] = __float2bfloat16(v0.x); o[1] = __float2bfloat16(v0.y);
        o[2] = __float2bfloat16(v0.z); o[3] = __float2bfloat16(v0.w);
        o[4] = __float2bfloat16(v1.x); o[5] = __float2bfloat16(v1.y);
        o[6] = __float2bfloat16(v1.z); o[7] = __float2bfloat16(v1.w);
        *(uint4*)&vwb[i] = *(uint4*)o;
    }
}

// dec_w [Vv, Tt] -> padded bf16 [VP, TP]; 4 elems per thread.
__global__ void cvt_decw(const float* __restrict__ src, __nv_bfloat16* __restrict__ dst) {
    const int e = (blockIdx.x * 256 + threadIdx.x) * 4;  // < VP*TP
    const int r = e >> 7;       // row (padded vocab)
    const int c = e & 127;      // col (padded K), c in {0,4,...,124}
    __nv_bfloat16 o[4];
#pragma unroll
    for (int u = 0; u < 4; u++) {
        const int cc = c + u;
        o[u] = (r < Vv && cc < Tt) ? __float2bfloat16(src[(size_t)r * Tt + cc])
                                   : __float2bfloat16(0.f);
    }
    *(uint2*)&dst[(size_t)r * TP + c] = *(uint2*)o;
}

// ---------------- warp-level bf16 MMA (arch-neutral PTX, sm_80+) ------------
__device__ __forceinline__ void mma16816(float* c, const uint32_t* a, const uint32_t* b) {
    asm volatile(
        "mma.sync.aligned.m16n8k16.row.col.f32.bf16.bf16.f32 "
        "{%0,%1,%2,%3}, {%4,%5,%6,%7}, {%8,%9}, {%0,%1,%2,%3};"
        : "+f"(c[0]), "+f"(c[1]), "+f"(c[2]), "+f"(c[3])
        : "r"(a[0]), "r"(a[1]), "r"(a[2]), "r"(a[3]), "r"(b[0]), "r"(b[1]));
}

// ===================== fc11 via cp.async 3-stage + mma.sync + ldmatrix =======
__device__ __forceinline__ void fc11_load_stage(uint32_t sbase, int st, int kt,
                                                int bm, int bn, int tid) {
    const int k0 = kt * 64;
    const uint32_t abase = sbase + st * 32768;
    const uint32_t bbase = abase + 16384;
#pragma unroll
    for (int i = 0; i < 4; i++) {
        const int idx = tid + 256 * i;
        const int row = idx >> 3, ch = idx & 7;
        const uint32_t off = (uint32_t)row * 128u + (uint32_t)((ch ^ (row & 7)) << 4);
        const void* asrc = &g_xb[(size_t)(bm + row) * KP + k0 + ch * 8];
        asm volatile("cp.async.cg.shared.global [%0], [%1], 16;"
                     :: "r"(abase + off), "l"(asrc));
        const void* bsrc = &g_wb[(size_t)(bn + row) * KP + k0 + ch * 8];
        asm volatile("cp.async.cg.shared.global [%0], [%1], 16;"
                     :: "r"(bbase + off), "l"(bsrc));
    }
    asm volatile("cp.async.commit_group;");
}

__device__ __forceinline__ uint32_t swz(uint32_t row, uint32_t bytecol) {
    return row * 128u + ((((bytecol >> 4) ^ (row & 7u))) << 4) + (bytecol & 15u);
}

__global__ __launch_bounds__(256, 2) void fc11_mma2() {
    extern __shared__ char dynsmem[];
    const uint32_t sbase = smem_u32(dynsmem);
    const int tid = threadIdx.x;
    const int wid = tid >> 5, lane = tid & 31;
    const int wr = wid >> 2, wc = wid & 3;
    const int l4 = lane >> 2, lq = lane & 3;
    // ldmatrix per-lane addressing
    const int lrow16 = lane & 15;                       // A: row within 16-row group
    const uint32_t lhalfA = (uint32_t)((lane >> 4) << 4);  // A: 0/16 byte half
    const int brow = (lane & 7) + ((lane >> 4) << 3);   // B: row within 16-n group
    const uint32_t bhalf = (uint32_t)(((lane >> 3) & 1) << 4);  // B: byte half
    const int bn = blockIdx.x * 128;
    const int bm = blockIdx.y * 128;
    const int s = blockIdx.z;
    const int kt0 = (s * KTOT) / SPLIT, kt1 = ((s + 1) * KTOT) / SPLIT;
    const int niter = kt1 - kt0;

    float c[4][4][4];
#pragma unroll
    for (int i = 0; i < 4; i++)
#pragma unroll
        for (int j = 0; j < 4; j++)
#pragma unroll
            for (int u = 0; u < 4; u++) c[i][j][u] = 0.f;

    fc11_load_stage(sbase, 0, kt0, bm, bn, tid);
    if (niter > 1) fc11_load_stage(sbase, 1, kt0 + 1, bm, bn, tid);

    int st = 0;
    for (int t = 0; t < niter; t++) {
        if (t + 2 < niter) {
            int st2 = st + 2; if (st2 >= 3) st2 -= 3;
            fc11_load_stage(sbase, st2, kt0 + t + 2, bm, bn, tid);
            asm volatile("cp.async.wait_group 2;");
        } else if (t + 1 < niter) {
            asm volatile("cp.async.wait_group 1;");
        } else {
            asm volatile("cp.async.wait_group 0;");
        }
        __syncthreads();

        const uint32_t abase = sbase + st * 32768;
        const uint32_t bbase = abase + 16384;
#pragma unroll
        for (int kk = 0; kk < 4; kk++) {
            const uint32_t kb = (uint32_t)(kk * 32);
            uint32_t a[4][4], bt[8];
#pragma unroll
            for (int i = 0; i < 4; i++)
                ldsm_x4(a[i], abase + swz((uint32_t)(wr * 64 + i * 16 + lrow16), kb + lhalfA));
            ldsm_x4(bt,     bbase + swz((uint32_t)(wc * 32 + brow),      kb + bhalf));
            ldsm_x4(bt + 4, bbase + swz((uint32_t)(wc * 32 + 16 + brow), kb + bhalf));
#pragma unroll
            for (int i = 0; i < 4; i++)
#pragma unroll
                for (int j = 0; j < 4; j++) mma16816(c[i][j], a[i], bt + j * 2);
        }
        __syncthreads();
        if (++st >= 3) st = 0;
    }

#pragma unroll
    for (int i = 0; i < 4; i++) {
        const int row0 = bm + wr * 64 + i * 16 + l4;
#pragma unroll
        for (int j = 0; j < 4; j++) {
            const int col = bn + wc * 32 + j * 8 + lq * 2;
            float* p0 = g_part + ((size_t)s * Bb + row0) * Ee + col;
            float* p1 = g_part + ((size_t)s * Bb + row0 + 8) * Ee + col;
            p0[0] = c[i][j][0]; p0[1] = c[i][j][1];
            p1[0] = c[i][j][2]; p1[1] = c[i][j][3];
        }
    }
}

__global__ void fc11_reduce(const float* __restrict__ bias) {
    const int i = blockIdx.x * 256 + threadIdx.x;
    float v = bias[i & (Ee - 1)];
#pragma unroll
    for (int s = 0; s < SPLIT; s++) v += g_part[(size_t)s * (Bb * Ee) + i];
    g_e1b[i] = __float2bfloat16(softplus_f(v));
}

// ===================== generic bf16 mma GEMM (single-buffer, PADR) ===========
// MODE: 0 = fp32 out only, 1 = bf16 out only, 2 = both
#define PADR 72
template <int ACT, int MODE>
__global__ __launch_bounds__(256) void mma_gemm(const __nv_bfloat16* __restrict__ A,
                                                const __nv_bfloat16* __restrict__ W,
                                                const float* __restrict__ bias,
                                                float* __restrict__ C,
                                                __nv_bfloat16* __restrict__ Cb,
                                                int N, int K) {
    __shared__ __nv_bfloat16 As[128][PADR];
    __shared__ __nv_bfloat16 Bs[128][PADR];
    const int tid = threadIdx.x;
    const int wid = tid >> 5, lane = tid & 31;
    const int wr = wid >> 2, wc = wid & 3;
    const int l4 = lane >> 2, lq = lane & 3;
    const int bn = blockIdx.x * 128;
    const int bm = blockIdx.y * 128;

    float c[4][4][4];
#pragma unroll
    for (int i = 0; i < 4; i++)
#pragma unroll
        for (int j = 0; j < 4; j++)
#pragma unroll
            for (int u = 0; u < 4; u++) c[i][j][u] = 0.f;

    for (int k0 = 0; k0 < K; k0 += 64) {
#pragma unroll
        for (int i = 0; i < 4; i++) {
            const int idx = tid + 256 * i;
            const int row = idx >> 3, ch = idx & 7;
            uint4 va = *(const uint4*)&A[(size_t)(bm + row) * K + k0 + ch * 8];
            *(uint4*)&As[row][ch * 8] = va;
            uint4 vb = *(const uint4*)&W[(size_t)(bn + row) * K + k0 + ch * 8];
            *(uint4*)&Bs[row][ch * 8] = vb;
        }
        __syncthreads();

#pragma unroll
        for (int kk = 0; kk < 4; kk++) {
            const int kb = kk * 16 + lq * 2;
            uint32_t a[4][4], b[4][2];
#pragma unroll
            for (int i = 0; i < 4; i++) {
                const int r = wr * 64 + i * 16 + l4;
                a[i][0] = *(const uint32_t*)&As[r][kb];
                a[i][1] = *(const uint32_t*)&As[r + 8][kb];
                a[i][2] = *(const uint32_t*)&As[r][kb + 8];
                a[i][3] = *(const uint32_t*)&As[r + 8][kb + 8];
            }
#pragma unroll
            for (int j = 0; j < 4; j++) {
                const int n = wc * 32 + j * 8 + l4;
                b[j][0] = *(const uint32_t*)&Bs[n][kb];
                b[j][1] = *(const uint32_t*)&Bs[n][kb + 8];
            }
#pragma unroll
            for (int i = 0; i < 4; i++)
#pragma unroll
                for (int j = 0; j < 4; j++) mma16816(c[i][j], a[i], b[j]);
        }
        __syncthreads();
    }

#pragma unroll
    for (int i = 0; i < 4; i++) {
        const int row0 = bm + wr * 64 + i * 16 + l4;
#pragma unroll
        for (int j = 0; j < 4; j++) {
            const int col = bn + wc * 32 + j * 8 + lq * 2;
#pragma unroll
            for (int h = 0; h < 2; h++) {
                const int row = row0 + h * 8;
#pragma unroll
                for (int u = 0; u < 2; u++) {
                    float v = c[i][j][h * 2 + u] + bias[col + u];
                    if (ACT == 1) v = softplus_f(v);
                    if (MODE == 0 || MODE == 2) C[(size_t)row * N + col + u] = v;
                    if (MODE == 1 || MODE == 2)
                        Cb[(size_t)row * N + col + u] = __float2bfloat16(v);
                }
            }
        }
    }
}

// ===================== logit mma GEMM: [512,VP]x[VP,TP] with col guard =======
__global__ __launch_bounds__(256) void mma_logit(const float* __restrict__ bias) {
    __shared__ __nv_bfloat16 As[128][PADR];
    __shared__ __nv_bfloat16 Bs[128][PADR];
    const int tid = threadIdx.x;
    const int wid = tid >> 5, lane = tid & 31;
    const int wr = wid >> 2, wc = wid & 3;
    const int l4 = lane >> 2, lq = lane & 3;
    const int bn = blockIdx.x * 128;
    const int bm = blockIdx.y * 128;

    float c[4][4][4];
#pragma unroll
    for (int i = 0; i < 4; i++)
#pragma unroll
        for (int j = 0; j < 4; j++)
#pragma unroll
            for (int u = 0; u < 4; u++) c[i][j][u] = 0.f;

    for (int k0 = 0; k0 < TP; k0 += 64) {
#pragma unroll
        for (int i = 0; i < 4; i++) {
            const int idx = tid + 256 * i;
            const int row = idx >> 3, ch = idx & 7;
            uint4 va = *(const uint4*)&g_thetab[(size_t)(bm + row) * TP + k0 + ch * 8];
            *(uint4*)&As[row][ch * 8] = va;
            uint4 vb = *(const uint4*)&g_decwb[(size_t)(bn + row) * TP + k0 + ch * 8];
            *(uint4*)&Bs[row][ch * 8] = vb;
        }
        __syncthreads();

#pragma unroll
        for (int kk = 0; kk < 4; kk++) {
            const int kb = kk * 16 + lq * 2;
            uint32_t a[4][4], b[4][2];
#pragma unroll
            for (int i = 0; i < 4; i++) {
                const int r = wr * 64 + i * 16 + l4;
                a[i][0] = *(const uint32_t*)&As[r][kb];
                a[i][1] = *(const uint32_t*)&As[r + 8][kb];
                a[i][2] = *(const uint32_t*)&As[r][kb + 8];
                a[i][3] = *(const uint32_t*)&As[r + 8][kb + 8];
            }
#pragma unroll
            for (int j = 0; j < 4; j++) {
                const int n = wc * 32 + j * 8 + l4;
                b[j][0] = *(const uint32_t*)&Bs[n][kb];
                b[j][1] = *(const uint32_t*)&Bs[n][kb + 8];
            }
#pragma unroll
            for (int i = 0; i < 4; i++)
#pragma unroll
                for (int j = 0; j < 4; j++) mma16816(c[i][j], a[i], b[j]);
        }
        __syncthreads();
    }

#pragma unroll
    for (int i = 0; i < 4; i++) {
        const int row0 = bm + wr * 64 + i * 16 + l4;
#pragma unroll
        for (int j = 0; j < 4; j++) {
            const int col = bn + wc * 32 + j * 8 + lq * 2;
#pragma unroll
            for (int h = 0; h < 2; h++) {
                const int row = row0 + h * 8;
#pragma unroll
                for (int u = 0; u < 2; u++) {
                    const int cg = col + u;
                    if (cg < Vv)
                        g_logit[(size_t)row * Vv + cg] = c[i][j][h * 2 + u] + bias[cg];
                }
            }
        }
    }
}

// ---------------- packed f32x2 helpers --------------------------------------
__device__ __forceinline__ unsigned long long pk2(float x, float y) {
    unsigned long long r;
    asm("mov.b64 %0, {%1, %2};" : "=l"(r) : "f"(x), "f"(y));
    return r;
}
__device__ __forceinline__ unsigned long long fma2(unsigned long long a,
                                                   unsigned long long b,
                                                   unsigned long long c) {
    unsigned long long d;
    asm("fma.rn.f32x2 %0, %1, %2, %3;" : "=l"(d) : "l"(a), "l"(b), "l"(c));
    return d;
}
__device__ __forceinline__ void upk2(unsigned long long v, float& lo, float& hi) {
    asm("mov.b64 {%0, %1}, %2;" : "=f"(lo), "=f"(hi) : "l"(v));
}

// ---------------- generic fp32 GEMM body (register double-buffered) ---------
template <int ACT, bool BNT>
__device__ __forceinline__ void gemm64_body(const float* __restrict__ A,
                                            const float* __restrict__ Bm,
                                            const float* __restrict__ bias,
                                            float* __restrict__ C,
                                            int M, int N, int K) {
    __shared__ float As[16][64];
    __shared__ float Bs[16][64];
    const int bm = blockIdx.y * 64, bn = blockIdx.x * 64;
    const int tid = threadIdx.x;
    const int tr = tid >> 4, tc = tid & 15;
    const int lrow = tid >> 4;
    const int lk = tid & 15;

    unsigned long long acc[4][2];
#pragma unroll
    for (int i = 0; i < 4; i++) { acc[i][0] = 0ull; acc[i][1] = 0ull; }

    float pa[4], pb[4], na[4], nb[4];

#pragma unroll
    for (int i = 0; i < 4; i++) {
        int r = lrow + i * 16;
        int gk = lk;
        int gm = bm + r;
        pa[i] = (gm < M && gk < K) ? A[(size_t)gm * K + gk] : 0.f;
        int gn = bn + r;
        float v = 0.f;
        if (gn < N && gk < K)
            v = BNT ? Bm[(size_t)gn * K + gk] : Bm[(size_t)gk * N + gn];
        pb[i] = v;
    }

    for (int k0 = 0; k0 < K; k0 += 16) {
#pragma unroll
        for (int i = 0; i < 4; i++) {
            int r = lrow + i * 16;
            As[lk][r] = pa[i];
            Bs[lk][r] = pb[i];
        }
        __syncthreads();

        if (k0 + 16 < K) {
#pragma unroll
            for (int i = 0; i < 4; i++) {
                int r = lrow + i * 16;
                int gk = k0 + 16 + lk;
                int gm = bm + r;
                na[i] = (gm < M && gk < K) ? A[(size_t)gm * K + gk] : 0.f;
                int gn = bn + r;
                float v = 0.f;
                if (gn < N && gk < K)
                    v = BNT ? Bm[(size_t)gn * K + gk] : Bm[(size_t)gk * N + gn];
                nb[i] = v;
            }
        }

#pragma unroll
        for (int kk = 0; kk < 16; kk++) {
            float a0 = As[kk][tr * 4 + 0];
            float a1 = As[kk][tr * 4 + 1];
            float a2 = As[kk][tr * 4 + 2];
            float a3 = As[kk][tr * 4 + 3];
            unsigned long long b0 =
                *reinterpret_cast<const unsigned long long*>(&Bs[kk][tc * 4]);
            unsigned long long b1 =
                *reinterpret_cast<const unsigned long long*>(&Bs[kk][tc * 4 + 2]);
            unsigned long long A0 = pk2(a0, a0), A1 = pk2(a1, a1);
            unsigned long long A2 = pk2(a2, a2), A3 = pk2(a3, a3);
            acc[0][0] = fma2(A0, b0, acc[0][0]); acc[0][1] = fma2(A0, b1, acc[0][1]);
            acc[1][0] = fma2(A1, b0, acc[1][0]); acc[1][1] = fma2(A1, b1, acc[1][1]);
            acc[2][0] = fma2(A2, b0, acc[2][0]); acc[2][1] = fma2(A2, b1, acc[2][1]);
            acc[3][0] = fma2(A3, b0, acc[3][0]); acc[3][1] = fma2(A3, b1, acc[3][1]);
        }
        __syncthreads();
#pragma unroll
        for (int i = 0; i < 4; i++) { pa[i] = na[i]; pb[i] = nb[i]; }
    }

#pragma unroll
    for (int i = 0; i < 4; i++) {
        int gm = bm + tr * 4 + i;
        if (gm >= M) continue;
#pragma unroll
        for (int j2 = 0; j2 < 2; j2++) {
            float lo, hi;
            upk2(acc[i][j2], lo, hi);
            float vals[2] = {lo, hi};
#pragma unroll
            for (int u = 0; u < 2; u++) {
                int gn = bn + tc * 4 + j2 * 2 + u;
                if (gn < N) {
                    float v = vals[u] + (bias ? bias[gn] : 0.f);
                    if (ACT == 1) v = softplus_f(v);
                    C[(size_t)gm * N + gn] = v;
                }
            }
        }
    }
}

// ---- wrapper kernels binding scratch globals --------------------------------
__global__ void gemm_mulv(const float* __restrict__ Wm, const float* __restrict__ bm_,
                          const float* __restrict__ Wl, const float* __restrict__ bl_) {
    if (blockIdx.z == 0)
        gemm64_body<0, true>(g_di, Wm, bm_, g_mu, Bb, Tt, Dd);
    else
        gemm64_body<0, true>(g_di, Wl, bl_, g_lv, Bb, Tt, Dd);
}

// ---------------- fused ragged single-query attention -----------------------
__global__ void attn_kernel(const float* __restrict__ emb,
                            const float* __restrict__ kb,
                            const int* __restrict__ lengths) {
    const int b = blockIdx.x, tid = threadIdx.x;  // 256 threads
    __shared__ float s_qk[Dd];
    __shared__ float s_sc[Mm];
    __shared__ float red[256];
    __shared__ float s_kbdot;
    const int len = lengths[b];

    float part = 0.f;
    for (int d = tid; d < Dd; d += 256) {
        s_qk[d] = g_qk[b * Dd + d];
        part += g_q[b * Dd + d] * kb[d];
    }
    red[tid] = part;
    __syncthreads();
    for (int s = 128; s > 0; s >>= 1) {
        if (tid < s) red[tid] += red[tid + s];
        __syncthreads();
    }
    if (tid == 0) s_kbdot = red[0];
    __syncthreads();
    const float kbdot = s_kbdot;

    const int wid = tid >> 5, lane = tid & 31;
    const float scale = 0.051031036307982884f;  // 1/sqrt(384)
    for (int m = wid; m < Mm; m += 8) {
        const float* er = emb + ((size_t)b * Mm + m) * Dd;
        float sum = 0.f;
#pragma unroll
        for (int i = 0; i < Dd / 32; i++) {
            int d = lane + 32 * i;
            sum += er[d] * s_qk[d];
        }
#pragma unroll
        for (int o = 16; o > 0; o >>= 1) sum += __shfl_xor_sync(0xffffffffu, sum, o);
        if (lane == 0) s_sc[m] = (m < len) ? (sum + kbdot) * scale : -1e30f;
    }
    __syncthreads();

    if (wid == 0) {
        float v0 = s_sc[lane], v1 = s_sc[lane + 32];
        float mx = fmaxf(v0, v1);
#pragma unroll
        for (int o = 16; o > 0; o >>= 1) mx = fmaxf(mx, __shfl_xor_sync(0xffffffffu, mx, o));
        float e0 = expf(v0 - mx), e1 = expf(v1 - mx);
        float ss = e0 + e1;
#pragma unroll
        for (int o = 16; o > 0; o >>= 1) ss += __shfl_xor_sync(0xffffffffu, ss, o);
        float inv = 1.f / ss;
        s_sc[lane] = e0 * inv;
        s_sc[lane + 32] = e1 * inv;
    }
    __syncthreads();

    for (int d = tid; d < Dd; d += 256) {
        float acc = 0.f;
#pragma unroll 8
        for (int m = 0; m < Mm; m++)
            acc += s_sc[m] * emb[((size_t)b * Mm + m) * Dd + d];
        g_ebarb[b * Dd + d] = __float2bfloat16(acc);
    }
}

// ---------------- BatchNorm over batch dim for [B,T], both arrays -----------
__global__ void bn_both(const float* __restrict__ bias_mu,
                        const float* __restrict__ bias_lv) {
    const int which = blockIdx.x >= Tt;
    const int t = which ? blockIdx.x - Tt : blockIdx.x;
    float* h = which ? g_lv : g_mu;
    const float* bias = which ? bias_lv : bias_mu;
    const int tid = threadIdx.x;  // 256
    __shared__ float red[256];
    __shared__ float s_mu, s_inv;
    float v0 = h[(size_t)tid * Tt + t];
    float v1 = h[(size_t)(tid + 256) * Tt + t];
    red[tid] = v0 + v1;
    __syncthreads();
    for (int s = 128; s > 0; s >>= 1) {
        if (tid < s) red[tid] += red[tid + s];
        __syncthreads();
    }
    if (tid == 0) s_mu = red[0] * (1.f / Bb);
    __syncthreads();
    float mu = s_mu;
    float d0 = v0 - mu, d1 = v1 - mu;
    red[tid] = d0 * d0 + d1 * d1;
    __syncthreads();
    for (int s = 128; s > 0; s >>= 1) {
        if (tid < s) red[tid] += red[tid + s];
        __syncthreads();
    }
    if (tid == 0) s_inv = rsqrtf(red[0] * (1.f / Bb) + 1e-5f);
    __syncthreads();
    float inv = s_inv, bbv = bias[t];
    h[(size_t)tid * Tt + t] = d0 * inv + bbv;
    h[(size_t)(tid + 256) * Tt + t] = d1 * inv + bbv;
}

// ---------------- theta = softmax(mu) (bf16 padded), kl per sample ----------
__global__ void theta_kl_kernel() {
    const int b = blockIdx.x, tid = threadIdx.x;  // 128
    __shared__ float red[128];
    __shared__ float s_mx, s_sum;
    const bool ok = tid < Tt;
    const float m = ok ? g_mu[b * Tt + tid] : -1e30f;
    const float l = ok ? g_lv[b * Tt + tid] : 0.f;
    red[tid] = m;
    __syncthreads();
    for (int s = 64; s > 0; s >>= 1) {
        if (tid < s) red[tid] = fmaxf(red[tid], red[tid + s]);
        __syncthreads();
    }
    if (tid == 0) s_mx = red[0];
    __syncthreads();
    const float e = ok ? expf(m - s_mx) : 0.f;
    red[tid] = e;
    __syncthreads();
    for (int s = 64; s > 0; s >>= 1) {
        if (tid < s) red[tid] += red[tid + s];
        __syncthreads();
    }
    if (tid == 0) s_sum = red[0];
    __syncthreads();
    g_thetab[b * TP + tid] = __float2bfloat16(ok ? e / s_sum : 0.f);

    const float INV_VAR2 = 1.0101010101010102f;    // 1/(1 - 1/T), T=100
    const float LOGV2 = -0.010050335853501441f;    // log(0.99)
    float term = ok ? (expf(l) * INV_VAR2 + m * m * INV_VAR2 + LOGV2 - l) : 0.f;
    red[tid] = term;
    __syncthreads();
    for (int s = 64; s > 0; s >>= 1) {
        if (tid < s) red[tid] += red[tid + s];
        __syncthreads();
    }
    if (tid == 0) g_kl[b] = 0.5f * (red[0] - (float)Tt);
}

// ---------------- per-vocab-column batch stats of logit (single pass) -------
__global__ void colstats_kernel() {
    const int v = blockIdx.x * blockDim.x + threadIdx.x;
    if (v >= Vv) return;
    float s = 0.f, s2 = 0.f;
#pragma unroll 8
    for (int b = 0; b < Bb; b++) {
        float x = g_logit[(size_t)b * Vv + v];
        s += x;
        s2 += x * x;
    }
    const float mean = s * (1.f / Bb);
    float var = fmaxf(s2 * (1.f / Bb) - mean * mean, 0.f);
    g_colmu[v] = mean;
    g_colinv[v] = rsqrtf(var + 1e-5f);
}

// ---------------- per-sample reconstruction loss (tree-reduced tail) --------
__global__ void recon_kernel(const float* __restrict__ bnb,
                             const float* __restrict__ x) {
    const int b = blockIdx.x, tid = threadIdx.x;  // 256
    __shared__ float s_m[256], s_s[256], s_xh[256], s_x[256];
    float mx = -1e30f, sm = 0.f, xh = 0.f, xs = 0.f;
    for (int v = tid; v < Vv; v += 256) {
        float hn = (g_logit[(size_t)b * Vv + v] - g_colmu[v]) * g_colinv[v] + bnb[v];
        float xv = x[(size_t)b * Vv + v];
        xh += xv * hn;
        xs += xv;
        float nm = fmaxf(mx, hn);
        sm = sm * expf(mx - nm) + expf(hn - nm);
        mx = nm;
    }
    s_m[tid] = mx; s_s[tid] = sm; s_xh[tid] = xh; s_x[tid] = xs;
    __syncthreads();
    for (int st = 128; st > 0; st >>= 1) {
        if (tid < st) {
            float m2 = s_m[tid + st], sm2 = s_s[tid + st];
            float M = fmaxf(s_m[tid], m2);
            s_s[tid] = s_s[tid] * expf(s_m[tid] - M) + sm2 * expf(m2 - M);
            s_m[tid] = M;
            s_xh[tid] += s_xh[tid + st];
            s_x[tid] += s_x[tid + st];
        }
        __syncthreads();
    }
    if (tid == 0) {
        float lse = s_m[0] + logf(s_s[0]);
        g_recon[b] = lse * s_x[0] - s_xh[0];
    }
}

// ---------------- final scalar -----------------------------------------------
__global__ void final_reduce(float* __restrict__ out) {
    __shared__ float red[512];
    const int tid = threadIdx.x;
    red[tid] = g_recon[tid] + g_kl[tid];
    __syncthreads();
    for (int s = 256; s > 0; s >>= 1) {
        if (tid < s) red[tid] += red[tid + s];
        __syncthreads();
    }
    if (tid == 0) out[0] = red[0] * (1.f / Bb);
}

// =============================================================================
extern "C" void kernel_launch(void* const* d_in, const int* in_sizes, int n_in,
                              void* d_out, int out_size) {
    (void)in_sizes; (void)n_in; (void)out_size;
    const float* x        = (const float*)d_in[0];
    const float* emb      = (const float*)d_in[1];
    const int*   lengths  = (const int*)d_in[2];
    const float* fc11_w   = (const float*)d_in[3];
    const float* fc11_b   = (const float*)d_in[4];
    const float* fc12_w   = (const float*)d_in[5];
    const float* fc12_b   = (const float*)d_in[6];
    const float* q_w      = (const float*)d_in[7];
    const float* q_b      = (const float*)d_in[8];
    const float* k_w      = (const float*)d_in[9];
    const float* k_b      = (const float*)d_in[10];
    const float* v_w      = (const float*)d_in[11];
    const float* v_b      = (const float*)d_in[12];
    const float* mean_w   = (const float*)d_in[13];
    const float* mean_b   = (const float*)d_in[14];
    const float* logvar_w = (const float*)d_in[15];
    const float* logvar_b = (const float*)d_in[16];
    const float* mean_bn_b   = (const float*)d_in[17];
    const float* logvar_bn_b = (const float*)d_in[18];
    const float* dec_w    = (const float*)d_in[19];
    const float* dec_b    = (const float*)d_in[20];
    const float* dec_bn_b = (const float*)d_in[21];

    __nv_bfloat16 *xb, *wb, *fc12b, *qwb, *e1b, *hbowb, *qb, *kwtb, *vwb, *ebarb, *decwb;
    cudaGetSymbolAddress((void**)&xb, g_xb);
    cudaGetSymbolAddress((void**)&wb, g_wb);
    cudaGetSymbolAddress((void**)&fc12b, g_fc12b);
    cudaGetSymbolAddress((void**)&qwb, g_qwb);
    cudaGetSymbolAddress((void**)&e1b, g_e1b);
    cudaGetSymbolAddress((void**)&hbowb, g_hbowb);
    cudaGetSymbolAddress((void**)&qb, g_qb);
    cudaGetSymbolAddress((void**)&kwtb, g_kwtb);
    cudaGetSymbolAddress((void**)&vwb, g_vwb);
    cudaGetSymbolAddress((void**)&ebarb, g_ebarb);
    cudaGetSymbolAddress((void**)&decwb, g_decwb);
    float *q, *qk, *di, *zeros;
    cudaGetSymbolAddress((void**)&q, g_q);
    cudaGetSymbolAddress((void**)&qk, g_qk);
    cudaGetSymbolAddress((void**)&di, g_di);
    cudaGetSymbolAddress((void**)&zeros, g_zeros);

    cudaFuncSetAttribute(fc11_mma2, cudaFuncAttributeMaxDynamicSharedMemorySize, 98304);

    // 1: x conversion                      2: fc11_w conversion
    cvt_bf16<<<(Bb * (KP / 8)) / 256, 256>>>(x, xb);
    cvt_bf16<<<(Ee * (KP / 8)) / 256, 256>>>(fc11_w, wb);
    // 3: fc12_w + q_w conversion in one launch
    cvt_two<<<(Ee * Ee / 8 + Dd * Ee / 8) / 256, 256>>>(fc12_w, fc12b, Ee * Ee / 8, q_w, qwb);
    // 4: fc11 GEMM (3-stage cp.async, ldmatrix, split-K=9)  <- profiled launch
    fc11_mma2<<<dim3(Ee / 128, Bb / 128, SPLIT), 256, 98304>>>();
    // 5: reduce partials -> e1 (bf16)
    fc11_reduce<<<(Bb * Ee) / 256, 256>>>(fc11_b);
    // 6: dec_w pad-convert (off critical path until logit)
    cvt_decw<<<(VP * TP / 4) / 256, 256>>>(dec_w, decwb);
    // 7: h_bow (bf16 out)
    mma_gemm<1, 1><<<dim3(Ee / 128, Bb / 128), 256>>>(e1b, fc12b, fc12_b, (float*)0, hbowb, Ee, Ee);
    // 8: q (fp32 + bf16 out)
    mma_gemm<0, 2><<<dim3(Dd / 128, Bb / 128), 256>>>(hbowb, qwb, q_b, q, qb, Dd, Ee);
    // 9: k_w transpose-convert + v_w convert
    cvt_small<<<216, 256>>>(k_w, kwtb, v_w, vwb);
    // 10: qk = q @ k_w  (bf16 mma, zero bias)
    mma_gemm<0, 0><<<dim3(Dd / 128, Bb / 128), 256>>>(qb, kwtb, zeros, qk, (__nv_bfloat16*)0, Dd, Dd);
    // 11: attention -> ebar (bf16)
    attn_kernel<<<Bb, 256>>>(emb, k_b, lengths);
    // 12: d_i = ebar @ v_w^T + v_b  (bf16 mma)
    mma_gemm<0, 0><<<dim3(Dd / 128, Bb / 128), 256>>>(ebarb, vwb, v_b, di, (__nv_bfloat16*)0, Dd, Dd);
    // 13..: tail
    gemm_mulv<<<dim3(2, Bb / 64, 2), 256>>>(mean_w, mean_b, logvar_w, logvar_b);
    bn_both<<<2 * Tt, 256>>>(mean_bn_b, logvar_bn_b);
    theta_kl_kernel<<<Bb, 128>>>();
    mma_logit<<<dim3(VP / 128, Bb / 128), 256>>>(dec_b);
    colstats_kernel<<<(Vv + 255) / 256, 256>>>();
    recon_kernel<<<Bb, 256>>>(dec_bn_b, x);
    final_reduce<<<1, Bb>>>((float*)d_out);
}

// round 15
// speedup vs baseline: 3.6874x; 1.1707x over previous
#include <cuda_runtime.h>
#include <cuda_bf16.h>
#include <math.h>
#include <stdint.h>

#define Bb 512
#define Mm 64
#define Vv 20000
#define VP 20096            // Vv padded to 128 (N tiles for logit mma)
#define Ee 1024
#define Dd 384
#define Tt 100
#define TP 128              // Tt padded to 128 (K for logit mma)
#define SPLIT 9
#define KP 20032            // Vv padded to 64
#define KTOT 313            // KP / 64

// ---------------- scratch (device globals; no allocations allowed) ----------
__device__ __nv_bfloat16 g_xb[(size_t)Bb * KP];
__device__ __nv_bfloat16 g_wb[(size_t)Ee * KP];
__device__ float g_part[SPLIT * Bb * Ee];
__device__ __nv_bfloat16 g_e1b[Bb * Ee];
__device__ __nv_bfloat16 g_fc12b[Ee * Ee];
__device__ __nv_bfloat16 g_qwb[Dd * Ee];
__device__ __nv_bfloat16 g_hbowb[Bb * Ee];
__device__ __nv_bfloat16 g_qb[Bb * Dd];
__device__ __nv_bfloat16 g_kwtb[Dd * Dd];
__device__ __nv_bfloat16 g_vwb[Dd * Dd];
__device__ __nv_bfloat16 g_ebarb[Bb * Dd];
__device__ __nv_bfloat16 g_thetab[Bb * TP];
__device__ __nv_bfloat16 g_decwb[(size_t)VP * TP];
__device__ float g_zeros[Dd];                     // zero-initialized, never written
__device__ float g_q[Bb * Dd];
__device__ float g_qk[Bb * Dd];
__device__ float g_di[Bb * Dd];
__device__ float g_mu[Bb * Tt];
__device__ float g_lv[Bb * Tt];
__device__ float g_logit[(size_t)Bb * Vv];
__device__ float g_colmu[Vv];
__device__ float g_colinv[Vv];
__device__ float g_recon[Bb];
__device__ float g_kl[Bb];

__device__ __forceinline__ float softplus_f(float x) {
    return x > 0.f ? x + log1pf(expf(-x)) : log1pf(expf(x));
}
__device__ __forceinline__ uint32_t smem_u32(const void* p) {
    uint32_t a;
    asm("{ .reg .u64 t; cvta.to.shared.u64 t, %1; cvt.u32.u64 %0, t; }"
        : "=r"(a) : "l"(p));
    return a;
}
__device__ __forceinline__ void ldsm_x4(uint32_t* r, uint32_t addr) {
    asm volatile("ldmatrix.sync.aligned.m8n8.x4.shared.b16 {%0,%1,%2,%3}, [%4];"
                 : "=r"(r[0]), "=r"(r[1]), "=r"(r[2]), "=r"(r[3]) : "r"(addr));
}

// ============== single fused conversion kernel (all independent) =============
// Block ranges:
//   [0, NB_X)                 : x        -> g_xb   (K-padded)
//   [NB_X, +NB_W)             : fc11_w   -> g_wb   (K-padded)
//   [.., +NB_12)              : fc12_w   -> g_fc12b
//   [.., +NB_QW)              : q_w      -> g_qwb
//   [.., +NB_DW)              : dec_w    -> g_decwb (pad to [VP,TP])
//   [.., +144)                : k_w transpose -> g_kwtb
//   [.., +NB_VW)              : v_w      -> g_vwb
#define NB_X  (Bb * (KP / 8) / 256)          // 5008
#define NB_W  (Ee * (KP / 8) / 256)          // 10016
#define NB_12 (Ee * Ee / 8 / 256)            // 512
#define NB_QW (Dd * Ee / 8 / 256)            // 192
#define NB_DW ((VP * TP / 4) / 256)          // 2512
#define NB_VW (Dd * Dd / 8 / 256)            // 72
#define NB_ALL (NB_X + NB_W + NB_12 + NB_QW + NB_DW + 144 + NB_VW)

__device__ __forceinline__ void cvt_padK(const float* src, __nv_bfloat16* dst, int idx) {
    const int row = idx / (KP / 8);
    const int cp = (idx % (KP / 8)) * 8;
    __nv_bfloat16 o[8];
    if (cp + 8 <= Vv) {
        const float4 v0 = *(const float4*)&src[(size_t)row * Vv + cp];
        const float4 v1 = *(const float4*)&src[(size_t)row * Vv + cp + 4];
        o[0] = __float2bfloat16(v0.x); o[1] = __float2bfloat16(v0.y);
        o[2] = __float2bfloat16(v0.z); o[3] = __float2bfloat16(v0.w);
        o[4] = __float2bfloat16(v1.x); o[5] = __float2bfloat16(v1.y);
        o[6] = __float2bfloat16(v1.z); o[7] = __float2bfloat16(v1.w);
    } else {
#pragma unroll
        for (int i = 0; i < 8; i++) o[i] = __float2bfloat16(0.f);
    }
    *(uint4*)&dst[(size_t)row * KP + cp] = *(uint4*)o;
}
__device__ __forceinline__ void cvt_plain8(const float* s, __nv_bfloat16* d, int i8) {
    const int i = i8 * 8;
    const float4 v0 = *(const float4*)&s[i];
    const float4 v1 = *(const float4*)&s[i + 4];
    __nv_bfloat16 o[8];
    o[0] = __float2bfloat16(v0.x); o[1] = __float2bfloat16(v0.y);
    o[2] = __float2bfloat16(v0.z); o[3] = __float2bfloat16(v0.w);
    o[4] = __float2bfloat16(v1.x); o[5] = __float2bfloat16(v1.y);
    o[6] = __float2bfloat16(v1.z); o[7] = __float2bfloat16(v1.w);
    *(uint4*)&d[i] = *(uint4*)o;
}

__global__ void cvt_all(const float* __restrict__ x, const float* __restrict__ fc11w,
                        const float* __restrict__ fc12w, const float* __restrict__ qw,
                        const float* __restrict__ decw, const float* __restrict__ kw,
                        const float* __restrict__ vw) {
    int b = blockIdx.x;
    if (b < NB_X) { cvt_padK(x, g_xb, b * 256 + threadIdx.x); return; }
    b -= NB_X;
    if (b < NB_W) { cvt_padK(fc11w, g_wb, b * 256 + threadIdx.x); return; }
    b -= NB_W;
    if (b < NB_12) { cvt_plain8(fc12w, g_fc12b, b * 256 + threadIdx.x); return; }
    b -= NB_12;
    if (b < NB_QW) { cvt_plain8(qw, g_qwb, b * 256 + threadIdx.x); return; }
    b -= NB_QW;
    if (b < NB_DW) {
        const int e = (b * 256 + threadIdx.x) * 4;
        const int r = e >> 7, c = e & 127;
        __nv_bfloat16 o[4];
#pragma unroll
        for (int u = 0; u < 4; u++) {
            const int cc = c + u;
            o[u] = (r < Vv && cc < Tt) ? __float2bfloat16(decw[(size_t)r * Tt + cc])
                                       : __float2bfloat16(0.f);
        }
        *(uint2*)&g_decwb[(size_t)r * TP + c] = *(uint2*)o;
        return;
    }
    b -= NB_DW;
    if (b < 144) {
        __shared__ float t[32][33];
        const int bx = (b % 12) * 32, by = (b / 12) * 32;
        const int tx = threadIdx.x & 31, ty = threadIdx.x >> 5;  // 32x8
#pragma unroll
        for (int i = 0; i < 32; i += 8)
            t[ty + i][tx] = kw[(size_t)(by + ty + i) * Dd + bx + tx];
        __syncthreads();
#pragma unroll
        for (int i = 0; i < 32; i += 8)
            g_kwtb[(size_t)(bx + ty + i) * Dd + by + tx] = __float2bfloat16(t[tx][ty + i]);
        return;
    }
    b -= 144;
    cvt_plain8(vw, g_vwb, b * 256 + threadIdx.x);
}

// ---------------- warp-level bf16 MMA ----------------------------------------
__device__ __forceinline__ void mma16816(float* c, const uint32_t* a, const uint32_t* b) {
    asm volatile(
        "mma.sync.aligned.m16n8k16.row.col.f32.bf16.bf16.f32 "
        "{%0,%1,%2,%3}, {%4,%5,%6,%7}, {%8,%9}, {%0,%1,%2,%3};"
        : "+f"(c[0]), "+f"(c[1]), "+f"(c[2]), "+f"(c[3])
        : "r"(a[0]), "r"(a[1]), "r"(a[2]), "r"(a[3]), "r"(b[0]), "r"(b[1]));
}

// ===================== fc11 via cp.async 3-stage + ldmatrix ==================
__device__ __forceinline__ void fc11_load_stage(uint32_t sbase, int st, int kt,
                                                int bm, int bn, int tid) {
    const int k0 = kt * 64;
    const uint32_t abase = sbase + st * 32768;
    const uint32_t bbase = abase + 16384;
#pragma unroll
    for (int i = 0; i < 4; i++) {
        const int idx = tid + 256 * i;
        const int row = idx >> 3, ch = idx & 7;
        const uint32_t off = (uint32_t)row * 128u + (uint32_t)((ch ^ (row & 7)) << 4);
        const void* asrc = &g_xb[(size_t)(bm + row) * KP + k0 + ch * 8];
        asm volatile("cp.async.cg.shared.global [%0], [%1], 16;"
                     :: "r"(abase + off), "l"(asrc));
        const void* bsrc = &g_wb[(size_t)(bn + row) * KP + k0 + ch * 8];
        asm volatile("cp.async.cg.shared.global [%0], [%1], 16;"
                     :: "r"(bbase + off), "l"(bsrc));
    }
    asm volatile("cp.async.commit_group;");
}

__device__ __forceinline__ uint32_t swz(uint32_t row, uint32_t bytecol) {
    return row * 128u + ((((bytecol >> 4) ^ (row & 7u))) << 4) + (bytecol & 15u);
}

__global__ __launch_bounds__(256, 2) void fc11_mma2() {
    extern __shared__ char dynsmem[];
    const uint32_t sbase = smem_u32(dynsmem);
    const int tid = threadIdx.x;
    const int wid = tid >> 5, lane = tid & 31;
    const int wr = wid >> 2, wc = wid & 3;
    const int l4 = lane >> 2, lq = lane & 3;
    const int lrow16 = lane & 15;
    const uint32_t lhalfA = (uint32_t)((lane >> 4) << 4);
    const int brow = (lane & 7) + ((lane >> 4) << 3);
    const uint32_t bhalf = (uint32_t)(((lane >> 3) & 1) << 4);
    const int bn = blockIdx.x * 128;
    const int bm = blockIdx.y * 128;
    const int s = blockIdx.z;
    const int kt0 = (s * KTOT) / SPLIT, kt1 = ((s + 1) * KTOT) / SPLIT;
    const int niter = kt1 - kt0;

    float c[4][4][4];
#pragma unroll
    for (int i = 0; i < 4; i++)
#pragma unroll
        for (int j = 0; j < 4; j++)
#pragma unroll
            for (int u = 0; u < 4; u++) c[i][j][u] = 0.f;

    fc11_load_stage(sbase, 0, kt0, bm, bn, tid);
    if (niter > 1) fc11_load_stage(sbase, 1, kt0 + 1, bm, bn, tid);

    int st = 0;
    for (int t = 0; t < niter; t++) {
        if (t + 2 < niter) {
            int st2 = st + 2; if (st2 >= 3) st2 -= 3;
            fc11_load_stage(sbase, st2, kt0 + t + 2, bm, bn, tid);
            asm volatile("cp.async.wait_group 2;");
        } else if (t + 1 < niter) {
            asm volatile("cp.async.wait_group 1;");
        } else {
            asm volatile("cp.async.wait_group 0;");
        }
        __syncthreads();

        const uint32_t abase = sbase + st * 32768;
        const uint32_t bbase = abase + 16384;
#pragma unroll
        for (int kk = 0; kk < 4; kk++) {
            const uint32_t kb = (uint32_t)(kk * 32);
            uint32_t a[4][4], bt[8];
#pragma unroll
            for (int i = 0; i < 4; i++)
                ldsm_x4(a[i], abase + swz((uint32_t)(wr * 64 + i * 16 + lrow16), kb + lhalfA));
            ldsm_x4(bt,     bbase + swz((uint32_t)(wc * 32 + brow),      kb + bhalf));
            ldsm_x4(bt + 4, bbase + swz((uint32_t)(wc * 32 + 16 + brow), kb + bhalf));
#pragma unroll
            for (int i = 0; i < 4; i++)
#pragma unroll
                for (int j = 0; j < 4; j++) mma16816(c[i][j], a[i], bt + j * 2);
        }
        __syncthreads();
        if (++st >= 3) st = 0;
    }

#pragma unroll
    for (int i = 0; i < 4; i++) {
        const int row0 = bm + wr * 64 + i * 16 + l4;
#pragma unroll
        for (int j = 0; j < 4; j++) {
            const int col = bn + wc * 32 + j * 8 + lq * 2;
            float* p0 = g_part + ((size_t)s * Bb + row0) * Ee + col;
            float* p1 = g_part + ((size_t)s * Bb + row0 + 8) * Ee + col;
            p0[0] = c[i][j][0]; p0[1] = c[i][j][1];
            p1[0] = c[i][j][2]; p1[1] = c[i][j][3];
        }
    }
}

__global__ void fc11_reduce(const float* __restrict__ bias) {
    const int i = blockIdx.x * 256 + threadIdx.x;
    float v = bias[i & (Ee - 1)];
#pragma unroll
    for (int s = 0; s < SPLIT; s++) v += g_part[(size_t)s * (Bb * Ee) + i];
    g_e1b[i] = __float2bfloat16(softplus_f(v));
}

// ===================== 64x64-tile bf16 mma GEMM (128 threads) ================
// MODE: 0 = fp32 out, 1 = bf16 out, 2 = both
#define PADR 72
template <int ACT, int MODE>
__global__ __launch_bounds__(128) void mma_gemm64(const __nv_bfloat16* __restrict__ A,
                                                  const __nv_bfloat16* __restrict__ W,
                                                  const float* __restrict__ bias,
                                                  float* __restrict__ C,
                                                  __nv_bfloat16* __restrict__ Cb,
                                                  int N, int K) {
    __shared__ __nv_bfloat16 As[64][PADR];
    __shared__ __nv_bfloat16 Bs[64][PADR];
    const int tid = threadIdx.x;
    const int wid = tid >> 5, lane = tid & 31;
    const int wr = wid >> 1, wc = wid & 1;   // 2x2 warp grid, warp tile 32x32
    const int l4 = lane >> 2, lq = lane & 3;
    const int bn = blockIdx.x * 64;
    const int bm = blockIdx.y * 64;

    float c[2][4][4];
#pragma unroll
    for (int i = 0; i < 2; i++)
#pragma unroll
        for (int j = 0; j < 4; j++)
#pragma unroll
            for (int u = 0; u < 4; u++) c[i][j][u] = 0.f;

    for (int k0 = 0; k0 < K; k0 += 64) {
#pragma unroll
        for (int i = 0; i < 4; i++) {
            const int idx = tid + 128 * i;
            const int row = idx >> 3, ch = idx & 7;
            uint4 va = *(const uint4*)&A[(size_t)(bm + row) * K + k0 + ch * 8];
            *(uint4*)&As[row][ch * 8] = va;
            uint4 vb = *(const uint4*)&W[(size_t)(bn + row) * K + k0 + ch * 8];
            *(uint4*)&Bs[row][ch * 8] = vb;
        }
        __syncthreads();

#pragma unroll
        for (int kk = 0; kk < 4; kk++) {
            const int kb = kk * 16 + lq * 2;
            uint32_t a[2][4], b[4][2];
#pragma unroll
            for (int i = 0; i < 2; i++) {
                const int r = wr * 32 + i * 16 + l4;
                a[i][0] = *(const uint32_t*)&As[r][kb];
                a[i][1] = *(const uint32_t*)&As[r + 8][kb];
                a[i][2] = *(const uint32_t*)&As[r][kb + 8];
                a[i][3] = *(const uint32_t*)&As[r + 8][kb + 8];
            }
#pragma unroll
            for (int j = 0; j < 4; j++) {
                const int n = wc * 32 + j * 8 + l4;
                b[j][0] = *(const uint32_t*)&Bs[n][kb];
                b[j][1] = *(const uint32_t*)&Bs[n][kb + 8];
            }
#pragma unroll
            for (int i = 0; i < 2; i++)
#pragma unroll
                for (int j = 0; j < 4; j++) mma16816(c[i][j], a[i], b[j]);
        }
        __syncthreads();
    }

#pragma unroll
    for (int i = 0; i < 2; i++) {
        const int row0 = bm + wr * 32 + i * 16 + l4;
#pragma unroll
        for (int j = 0; j < 4; j++) {
            const int col = bn + wc * 32 + j * 8 + lq * 2;
#pragma unroll
            for (int h = 0; h < 2; h++) {
                const int row = row0 + h * 8;
#pragma unroll
                for (int u = 0; u < 2; u++) {
                    float v = c[i][j][h * 2 + u] + bias[col + u];
                    if (ACT == 1) v = softplus_f(v);
                    if (MODE == 0 || MODE == 2) C[(size_t)row * N + col + u] = v;
                    if (MODE == 1 || MODE == 2)
                        Cb[(size_t)row * N + col + u] = __float2bfloat16(v);
                }
            }
        }
    }
}

// ===================== logit mma GEMM: [512,VP]x[VP,TP], col guard ===========
__global__ __launch_bounds__(256) void mma_logit(const float* __restrict__ bias) {
    __shared__ __nv_bfloat16 As[128][PADR];
    __shared__ __nv_bfloat16 Bs[128][PADR];
    const int tid = threadIdx.x;
    const int wid = tid >> 5, lane = tid & 31;
    const int wr = wid >> 2, wc = wid & 3;
    const int l4 = lane >> 2, lq = lane & 3;
    const int bn = blockIdx.x * 128;
    const int bm = blockIdx.y * 128;

    float c[4][4][4];
#pragma unroll
    for (int i = 0; i < 4; i++)
#pragma unroll
        for (int j = 0; j < 4; j++)
#pragma unroll
            for (int u = 0; u < 4; u++) c[i][j][u] = 0.f;

    for (int k0 = 0; k0 < TP; k0 += 64) {
#pragma unroll
        for (int i = 0; i < 4; i++) {
            const int idx = tid + 256 * i;
            const int row = idx >> 3, ch = idx & 7;
            uint4 va = *(const uint4*)&g_thetab[(size_t)(bm + row) * TP + k0 + ch * 8];
            *(uint4*)&As[row][ch * 8] = va;
            uint4 vb = *(const uint4*)&g_decwb[(size_t)(bn + row) * TP + k0 + ch * 8];
            *(uint4*)&Bs[row][ch * 8] = vb;
        }
        __syncthreads();

#pragma unroll
        for (int kk = 0; kk < 4; kk++) {
            const int kb = kk * 16 + lq * 2;
            uint32_t a[4][4], b[4][2];
#pragma unroll
            for (int i = 0; i < 4; i++) {
                const int r = wr * 64 + i * 16 + l4;
                a[i][0] = *(const uint32_t*)&As[r][kb];
                a[i][1] = *(const uint32_t*)&As[r + 8][kb];
                a[i][2] = *(const uint32_t*)&As[r][kb + 8];
                a[i][3] = *(const uint32_t*)&As[r + 8][kb + 8];
            }
#pragma unroll
            for (int j = 0; j < 4; j++) {
                const int n = wc * 32 + j * 8 + l4;
                b[j][0] = *(const uint32_t*)&Bs[n][kb];
                b[j][1] = *(const uint32_t*)&Bs[n][kb + 8];
            }
#pragma unroll
            for (int i = 0; i < 4; i++)
#pragma unroll
                for (int j = 0; j < 4; j++) mma16816(c[i][j], a[i], b[j]);
        }
        __syncthreads();
    }

#pragma unroll
    for (int i = 0; i < 4; i++) {
        const int row0 = bm + wr * 64 + i * 16 + l4;
#pragma unroll
        for (int j = 0; j < 4; j++) {
            const int col = bn + wc * 32 + j * 8 + lq * 2;
#pragma unroll
            for (int h = 0; h < 2; h++) {
                const int row = row0 + h * 8;
#pragma unroll
                for (int u = 0; u < 2; u++) {
                    const int cg = col + u;
                    if (cg < Vv)
                        g_logit[(size_t)row * Vv + cg] = c[i][j][h * 2 + u] + bias[cg];
                }
            }
        }
    }
}

// ---------------- packed f32x2 helpers --------------------------------------
__device__ __forceinline__ unsigned long long pk2(float x, float y) {
    unsigned long long r;
    asm("mov.b64 %0, {%1, %2};" : "=l"(r) : "f"(x), "f"(y));
    return r;
}
__device__ __forceinline__ unsigned long long fma2(unsigned long long a,
                                                   unsigned long long b,
                                                   unsigned long long c) {
    unsigned long long d;
    asm("fma.rn.f32x2 %0, %1, %2, %3;" : "=l"(d) : "l"(a), "l"(b), "l"(c));
    return d;
}
__device__ __forceinline__ void upk2(unsigned long long v, float& lo, float& hi) {
    asm("mov.b64 {%0, %1}, %2;" : "=f"(lo), "=f"(hi) : "l"(v));
}

// ---------------- generic fp32 GEMM body (register double-buffered) ---------
template <int ACT, bool BNT>
__device__ __forceinline__ void gemm64_body(const float* __restrict__ A,
                                            const float* __restrict__ Bm,
                                            const float* __restrict__ bias,
                                            float* __restrict__ C,
                                            int M, int N, int K) {
    __shared__ float As[16][64];
    __shared__ float Bs[16][64];
    const int bm = blockIdx.y * 64, bn = blockIdx.x * 64;
    const int tid = threadIdx.x;
    const int tr = tid >> 4, tc = tid & 15;
    const int lrow = tid >> 4;
    const int lk = tid & 15;

    unsigned long long acc[4][2];
#pragma unroll
    for (int i = 0; i < 4; i++) { acc[i][0] = 0ull; acc[i][1] = 0ull; }

    float pa[4], pb[4], na[4], nb[4];

#pragma unroll
    for (int i = 0; i < 4; i++) {
        int r = lrow + i * 16;
        int gk = lk;
        int gm = bm + r;
        pa[i] = (gm < M && gk < K) ? A[(size_t)gm * K + gk] : 0.f;
        int gn = bn + r;
        float v = 0.f;
        if (gn < N && gk < K)
            v = BNT ? Bm[(size_t)gn * K + gk] : Bm[(size_t)gk * N + gn];
        pb[i] = v;
    }

    for (int k0 = 0; k0 < K; k0 += 16) {
#pragma unroll
        for (int i = 0; i < 4; i++) {
            int r = lrow + i * 16;
            As[lk][r] = pa[i];
            Bs[lk][r] = pb[i];
        }
        __syncthreads();

        if (k0 + 16 < K) {
#pragma unroll
            for (int i = 0; i < 4; i++) {
                int r = lrow + i * 16;
                int gk = k0 + 16 + lk;
                int gm = bm + r;
                na[i] = (gm < M && gk < K) ? A[(size_t)gm * K + gk] : 0.f;
                int gn = bn + r;
                float v = 0.f;
                if (gn < N && gk < K)
                    v = BNT ? Bm[(size_t)gn * K + gk] : Bm[(size_t)gk * N + gn];
                nb[i] = v;
            }
        }

#pragma unroll
        for (int kk = 0; kk < 16; kk++) {
            float a0 = As[kk][tr * 4 + 0];
            float a1 = As[kk][tr * 4 + 1];
            float a2 = As[kk][tr * 4 + 2];
            float a3 = As[kk][tr * 4 + 3];
            unsigned long long b0 =
                *reinterpret_cast<const unsigned long long*>(&Bs[kk][tc * 4]);
            unsigned long long b1 =
                *reinterpret_cast<const unsigned long long*>(&Bs[kk][tc * 4 + 2]);
            unsigned long long A0 = pk2(a0, a0), A1 = pk2(a1, a1);
            unsigned long long A2 = pk2(a2, a2), A3 = pk2(a3, a3);
            acc[0][0] = fma2(A0, b0, acc[0][0]); acc[0][1] = fma2(A0, b1, acc[0][1]);
            acc[1][0] = fma2(A1, b0, acc[1][0]); acc[1][1] = fma2(A1, b1, acc[1][1]);
            acc[2][0] = fma2(A2, b0, acc[2][0]); acc[2][1] = fma2(A2, b1, acc[2][1]);
            acc[3][0] = fma2(A3, b0, acc[3][0]); acc[3][1] = fma2(A3, b1, acc[3][1]);
        }
        __syncthreads();
#pragma unroll
        for (int i = 0; i < 4; i++) { pa[i] = na[i]; pb[i] = nb[i]; }
    }

#pragma unroll
    for (int i = 0; i < 4; i++) {
        int gm = bm + tr * 4 + i;
        if (gm >= M) continue;
#pragma unroll
        for (int j2 = 0; j2 < 2; j2++) {
            float lo, hi;
            upk2(acc[i][j2], lo, hi);
            float vals[2] = {lo, hi};
#pragma unroll
            for (int u = 0; u < 2; u++) {
                int gn = bn + tc * 4 + j2 * 2 + u;
                if (gn < N) {
                    float v = vals[u] + (bias ? bias[gn] : 0.f);
                    if (ACT == 1) v = softplus_f(v);
                    C[(size_t)gm * N + gn] = v;
                }
            }
        }
    }
}

__global__ void gemm_mulv(const float* __restrict__ Wm, const float* __restrict__ bm_,
                          const float* __restrict__ Wl, const float* __restrict__ bl_) {
    if (blockIdx.z == 0)
        gemm64_body<0, true>(g_di, Wm, bm_, g_mu, Bb, Tt, Dd);
    else
        gemm64_body<0, true>(g_di, Wl, bl_, g_lv, Bb, Tt, Dd);
}

// ---------------- fused ragged single-query attention -----------------------
__global__ void attn_kernel(const float* __restrict__ emb,
                            const float* __restrict__ kb,
                            const int* __restrict__ lengths) {
    const int b = blockIdx.x, tid = threadIdx.x;  // 256 threads
    __shared__ float s_qk[Dd];
    __shared__ float s_sc[Mm];
    __shared__ float red[256];
    __shared__ float s_kbdot;
    const int len = lengths[b];

    float part = 0.f;
    for (int d = tid; d < Dd; d += 256) {
        s_qk[d] = g_qk[b * Dd + d];
        part += g_q[b * Dd + d] * kb[d];
    }
    red[tid] = part;
    __syncthreads();
    for (int s = 128; s > 0; s >>= 1) {
        if (tid < s) red[tid] += red[tid + s];
        __syncthreads();
    }
    if (tid == 0) s_kbdot = red[0];
    __syncthreads();
    const float kbdot = s_kbdot;

    const int wid = tid >> 5, lane = tid & 31;
    const float scale = 0.051031036307982884f;  // 1/sqrt(384)
    for (int m = wid; m < Mm; m += 8) {
        const float* er = emb + ((size_t)b * Mm + m) * Dd;
        float sum = 0.f;
#pragma unroll
        for (int i = 0; i < Dd / 32; i++) {
            int d = lane + 32 * i;
            sum += er[d] * s_qk[d];
        }
#pragma unroll
        for (int o = 16; o > 0; o >>= 1) sum += __shfl_xor_sync(0xffffffffu, sum, o);
        if (lane == 0) s_sc[m] = (m < len) ? (sum + kbdot) * scale : -1e30f;
    }
    __syncthreads();

    if (wid == 0) {
        float v0 = s_sc[lane], v1 = s_sc[lane + 32];
        float mx = fmaxf(v0, v1);
#pragma unroll
        for (int o = 16; o > 0; o >>= 1) mx = fmaxf(mx, __shfl_xor_sync(0xffffffffu, mx, o));
        float e0 = expf(v0 - mx), e1 = expf(v1 - mx);
        float ss = e0 + e1;
#pragma unroll
        for (int o = 16; o > 0; o >>= 1) ss += __shfl_xor_sync(0xffffffffu, ss, o);
        float inv = 1.f / ss;
        s_sc[lane] = e0 * inv;
        s_sc[lane + 32] = e1 * inv;
    }
    __syncthreads();

    for (int d = tid; d < Dd; d += 256) {
        float acc = 0.f;
#pragma unroll 8
        for (int m = 0; m < Mm; m++)
            acc += s_sc[m] * emb[((size_t)b * Mm + m) * Dd + d];
        g_ebarb[b * Dd + d] = __float2bfloat16(acc);
    }
}

// ---------------- BatchNorm over batch dim for [B,T], both arrays -----------
__global__ void bn_both(const float* __restrict__ bias_mu,
                        const float* __restrict__ bias_lv) {
    const int which = blockIdx.x >= Tt;
    const int t = which ? blockIdx.x - Tt : blockIdx.x;
    float* h = which ? g_lv : g_mu;
    const float* bias = which ? bias_lv : bias_mu;
    const int tid = threadIdx.x;  // 256
    __shared__ float red[256];
    __shared__ float s_mu, s_inv;
    float v0 = h[(size_t)tid * Tt + t];
    float v1 = h[(size_t)(tid + 256) * Tt + t];
    red[tid] = v0 + v1;
    __syncthreads();
    for (int s = 128; s > 0; s >>= 1) {
        if (tid < s) red[tid] += red[tid + s];
        __syncthreads();
    }
    if (tid == 0) s_mu = red[0] * (1.f / Bb);
    __syncthreads();
    float mu = s_mu;
    float d0 = v0 - mu, d1 = v1 - mu;
    red[tid] = d0 * d0 + d1 * d1;
    __syncthreads();
    for (int s = 128; s > 0; s >>= 1) {
        if (tid < s) red[tid] += red[tid + s];
        __syncthreads();
    }
    if (tid == 0) s_inv = rsqrtf(red[0] * (1.f / Bb) + 1e-5f);
    __syncthreads();
    float inv = s_inv, bbv = bias[t];
    h[(size_t)tid * Tt + t] = d0 * inv + bbv;
    h[(size_t)(tid + 256) * Tt + t] = d1 * inv + bbv;
}

// ---------------- theta = softmax(mu) (bf16 padded), kl per sample ----------
__global__ void theta_kl_kernel() {
    const int b = blockIdx.x, tid = threadIdx.x;  // 128
    __shared__ float red[128];
    __shared__ float s_mx, s_sum;
    const bool ok = tid < Tt;
    const float m = ok ? g_mu[b * Tt + tid] : -1e30f;
    const float l = ok ? g_lv[b * Tt + tid] : 0.f;
    red[tid] = m;
    __syncthreads();
    for (int s = 64; s > 0; s >>= 1) {
        if (tid < s) red[tid] = fmaxf(red[tid], red[tid + s]);
        __syncthreads();
    }
    if (tid == 0) s_mx = red[0];
    __syncthreads();
    const float e = ok ? expf(m - s_mx) : 0.f;
    red[tid] = e;
    __syncthreads();
    for (int s = 64; s > 0; s >>= 1) {
        if (tid < s) red[tid] += red[tid + s];
        __syncthreads();
    }
    if (tid == 0) s_sum = red[0];
    __syncthreads();
    g_thetab[b * TP + tid] = __float2bfloat16(ok ? e / s_sum : 0.f);

    const float INV_VAR2 = 1.0101010101010102f;    // 1/(1 - 1/T), T=100
    const float LOGV2 = -0.010050335853501441f;    // log(0.99)
    float term = ok ? (expf(l) * INV_VAR2 + m * m * INV_VAR2 + LOGV2 - l) : 0.f;
    red[tid] = term;
    __syncthreads();
    for (int s = 64; s > 0; s >>= 1) {
        if (tid < s) red[tid] += red[tid + s];
        __syncthreads();
    }
    if (tid == 0) g_kl[b] = 0.5f * (red[0] - (float)Tt);
}

// ---------------- per-vocab-column batch stats (deep unroll) ----------------
__global__ void colstats_kernel() {
    const int v = blockIdx.x * blockDim.x + threadIdx.x;
    if (v >= Vv) return;
    float s = 0.f, s2 = 0.f;
#pragma unroll 16
    for (int b = 0; b < Bb; b++) {
        float x = g_logit[(size_t)b * Vv + v];
        s += x;
        s2 += x * x;
    }
    const float mean = s * (1.f / Bb);
    float var = fmaxf(s2 * (1.f / Bb) - mean * mean, 0.f);
    g_colmu[v] = mean;
    g_colinv[v] = rsqrtf(var + 1e-5f);
}

// ---------------- per-sample reconstruction loss ----------------------------
__global__ void recon_kernel(const float* __restrict__ bnb,
                             const float* __restrict__ x) {
    const int b = blockIdx.x, tid = threadIdx.x;  // 256
    __shared__ float s_m[256], s_s[256], s_xh[256], s_x[256];
    float mx = -1e30f, sm = 0.f, xh = 0.f, xs = 0.f;
    for (int v = tid; v < Vv; v += 256) {
        float hn = (g_logit[(size_t)b * Vv + v] - g_colmu[v]) * g_colinv[v] + bnb[v];
        float xv = x[(size_t)b * Vv + v];
        xh += xv * hn;
        xs += xv;
        float nm = fmaxf(mx, hn);
        sm = sm * expf(mx - nm) + expf(hn - nm);
        mx = nm;
    }
    s_m[tid] = mx; s_s[tid] = sm; s_xh[tid] = xh; s_x[tid] = xs;
    __syncthreads();
    for (int st = 128; st > 0; st >>= 1) {
        if (tid < st) {
            float m2 = s_m[tid + st], sm2 = s_s[tid + st];
            float M = fmaxf(s_m[tid], m2);
            s_s[tid] = s_s[tid] * expf(s_m[tid] - M) + sm2 * expf(m2 - M);
            s_m[tid] = M;
            s_xh[tid] += s_xh[tid + st];
            s_x[tid] += s_x[tid + st];
        }
        __syncthreads();
    }
    if (tid == 0) {
        float lse = s_m[0] + logf(s_s[0]);
        g_recon[b] = lse * s_x[0] - s_xh[0];
    }
}

// ---------------- final scalar -----------------------------------------------
__global__ void final_reduce(float* __restrict__ out) {
    __shared__ float red[512];
    const int tid = threadIdx.x;
    red[tid] = g_recon[tid] + g_kl[tid];
    __syncthreads();
    for (int s = 256; s > 0; s >>= 1) {
        if (tid < s) red[tid] += red[tid + s];
        __syncthreads();
    }
    if (tid == 0) out[0] = red[0] * (1.f / Bb);
}

// =============================================================================
extern "C" void kernel_launch(void* const* d_in, const int* in_sizes, int n_in,
                              void* d_out, int out_size) {
    (void)in_sizes; (void)n_in; (void)out_size;
    const float* x        = (const float*)d_in[0];
    const float* emb      = (const float*)d_in[1];
    const int*   lengths  = (const int*)d_in[2];
    const float* fc11_w   = (const float*)d_in[3];
    const float* fc11_b   = (const float*)d_in[4];
    const float* fc12_w   = (const float*)d_in[5];
    const float* fc12_b   = (const float*)d_in[6];
    const float* q_w      = (const float*)d_in[7];
    const float* q_b      = (const float*)d_in[8];
    const float* k_w      = (const float*)d_in[9];
    const float* k_b      = (const float*)d_in[10];
    const float* v_w      = (const float*)d_in[11];
    const float* v_b      = (const float*)d_in[12];
    const float* mean_w   = (const float*)d_in[13];
    const float* mean_b   = (const float*)d_in[14];
    const float* logvar_w = (const float*)d_in[15];
    const float* logvar_b = (const float*)d_in[16];
    const float* mean_bn_b   = (const float*)d_in[17];
    const float* logvar_bn_b = (const float*)d_in[18];
    const float* dec_w    = (const float*)d_in[19];
    const float* dec_b    = (const float*)d_in[20];
    const float* dec_bn_b = (const float*)d_in[21];

    __nv_bfloat16 *fc12b, *qwb, *e1b, *hbowb, *qb, *kwtb, *vwb, *ebarb;
    cudaGetSymbolAddress((void**)&fc12b, g_fc12b);
    cudaGetSymbolAddress((void**)&qwb, g_qwb);
    cudaGetSymbolAddress((void**)&e1b, g_e1b);
    cudaGetSymbolAddress((void**)&hbowb, g_hbowb);
    cudaGetSymbolAddress((void**)&qb, g_qb);
    cudaGetSymbolAddress((void**)&kwtb, g_kwtb);
    cudaGetSymbolAddress((void**)&vwb, g_vwb);
    cudaGetSymbolAddress((void**)&ebarb, g_ebarb);
    float *q, *qk, *di, *zeros;
    cudaGetSymbolAddress((void**)&q, g_q);
    cudaGetSymbolAddress((void**)&qk, g_qk);
    cudaGetSymbolAddress((void**)&di, g_di);
    cudaGetSymbolAddress((void**)&zeros, g_zeros);

    cudaFuncSetAttribute(fc11_mma2, cudaFuncAttributeMaxDynamicSharedMemorySize, 98304);

    // 1: ALL conversions in one fused launch
    cvt_all<<<NB_ALL, 256>>>(x, fc11_w, fc12_w, q_w, dec_w, k_w, v_w);
    // 2: fc11 GEMM (3-stage cp.async, ldmatrix, split-K=9)
    fc11_mma2<<<dim3(Ee / 128, Bb / 128, SPLIT), 256, 98304>>>();
    // 3: reduce partials -> e1 (bf16)
    fc11_reduce<<<(Bb * Ee) / 256, 256>>>(fc11_b);
    // 4: h_bow (bf16 out)  <- profiled launch (mid-chain representative)
    mma_gemm64<1, 1><<<dim3(Ee / 64, Bb / 64), 128>>>(e1b, fc12b, fc12_b, (float*)0, hbowb, Ee, Ee);
    // 5: q (fp32 + bf16 out)
    mma_gemm64<0, 2><<<dim3(Dd / 64, Bb / 64), 128>>>(hbowb, qwb, q_b, q, qb, Dd, Ee);
    // 6: qk = q @ k_w  (bf16 mma, zero bias)
    mma_gemm64<0, 0><<<dim3(Dd / 64, Bb / 64), 128>>>(qb, kwtb, zeros, qk, (__nv_bfloat16*)0, Dd, Dd);
    // 7: attention -> ebar (bf16)
    attn_kernel<<<Bb, 256>>>(emb, k_b, lengths);
    // 8: d_i = ebar @ v_w^T + v_b  (bf16 mma)
    mma_gemm64<0, 0><<<dim3(Dd / 64, Bb / 64), 128>>>(ebarb, vwb, v_b, di, (__nv_bfloat16*)0, Dd, Dd);
    // 9..: tail
    gemm_mulv<<<dim3(2, Bb / 64, 2), 256>>>(mean_w, mean_b, logvar_w, logvar_b);
    bn_both<<<2 * Tt, 256>>>(mean_bn_b, logvar_bn_b);
    theta_kl_kernel<<<Bb, 128>>>();
    mma_logit<<<dim3(VP / 128, Bb / 128), 256>>>(dec_b);
    colstats_kernel<<<(Vv + 255) / 256, 256>>>();
    recon_kernel<<<Bb, 256>>>(dec_bn_b, x);
    final_reduce<<<1, Bb>>>((float*)d_out);
}

// round 16
// speedup vs baseline: 4.1586x; 1.1278x over previous
#include <cuda_runtime.h>
#include <cuda_bf16.h>
#include <math.h>
#include <stdint.h>

#define Bb 512
#define Mm 64
#define Vv 20000
#define VP 20096            // Vv padded to 128 (N tiles for logit mma)
#define Ee 1024
#define Dd 384
#define Tt 100
#define TP 128              // Tt padded to 128 (K for logit mma)
#define SPLIT 9
#define KP 20032            // Vv padded to 64
#define KTOT 313            // KP / 64

// ---------------- scratch (device globals; no allocations allowed) ----------
__device__ __nv_bfloat16 g_xb[(size_t)Bb * KP];
__device__ __nv_bfloat16 g_wb[(size_t)Ee * KP];
__device__ float g_part[SPLIT * Bb * Ee];
__device__ __nv_bfloat16 g_e1b[Bb * Ee];
__device__ __nv_bfloat16 g_fc12b[Ee * Ee];
__device__ __nv_bfloat16 g_qwb[Dd * Ee];
__device__ __nv_bfloat16 g_hbowb[Bb * Ee];
__device__ __nv_bfloat16 g_qb[Bb * Dd];
__device__ __nv_bfloat16 g_kwtb[Dd * Dd];
__device__ __nv_bfloat16 g_vwb[Dd * Dd];
__device__ __nv_bfloat16 g_ebarb[Bb * Dd];
__device__ __nv_bfloat16 g_thetab[Bb * TP];
__device__ __nv_bfloat16 g_decwb[(size_t)VP * TP];
__device__ float g_zeros[Dd];                     // zero-initialized, never written
__device__ float g_q[Bb * Dd];
__device__ float g_qk[Bb * Dd];
__device__ float g_di[Bb * Dd];
__device__ float g_mu[Bb * Tt];
__device__ float g_lv[Bb * Tt];
__device__ float g_logit[(size_t)Bb * Vv];
__device__ float g_colmu[Vv];
__device__ float g_colinv[Vv];
__device__ float g_recon[Bb];
__device__ float g_kl[Bb];

__device__ __forceinline__ float softplus_f(float x) {
    return x > 0.f ? x + log1pf(expf(-x)) : log1pf(expf(x));
}
__device__ __forceinline__ uint32_t smem_u32(const void* p) {
    uint32_t a;
    asm("{ .reg .u64 t; cvta.to.shared.u64 t, %1; cvt.u32.u64 %0, t; }"
        : "=r"(a) : "l"(p));
    return a;
}
__device__ __forceinline__ void ldsm_x4(uint32_t* r, uint32_t addr) {
    asm volatile("ldmatrix.sync.aligned.m8n8.x4.shared.b16 {%0,%1,%2,%3}, [%4];"
                 : "=r"(r[0]), "=r"(r[1]), "=r"(r[2]), "=r"(r[3]) : "r"(addr));
}

// ============== single fused conversion kernel (all independent) =============
#define NB_X  (Bb * (KP / 8) / 256)
#define NB_W  (Ee * (KP / 8) / 256)
#define NB_12 (Ee * Ee / 8 / 256)
#define NB_QW (Dd * Ee / 8 / 256)
#define NB_DW ((VP * TP / 4) / 256)
#define NB_VW (Dd * Dd / 8 / 256)
#define NB_ALL (NB_X + NB_W + NB_12 + NB_QW + NB_DW + 144 + NB_VW)

__device__ __forceinline__ void cvt_padK(const float* src, __nv_bfloat16* dst, int idx) {
    const int row = idx / (KP / 8);
    const int cp = (idx % (KP / 8)) * 8;
    __nv_bfloat16 o[8];
    if (cp + 8 <= Vv) {
        const float4 v0 = *(const float4*)&src[(size_t)row * Vv + cp];
        const float4 v1 = *(const float4*)&src[(size_t)row * Vv + cp + 4];
        o[0] = __float2bfloat16(v0.x); o[1] = __float2bfloat16(v0.y);
        o[2] = __float2bfloat16(v0.z); o[3] = __float2bfloat16(v0.w);
        o[4] = __float2bfloat16(v1.x); o[5] = __float2bfloat16(v1.y);
        o[6] = __float2bfloat16(v1.z); o[7] = __float2bfloat16(v1.w);
    } else {
#pragma unroll
        for (int i = 0; i < 8; i++) o[i] = __float2bfloat16(0.f);
    }
    *(uint4*)&dst[(size_t)row * KP + cp] = *(uint4*)o;
}
__device__ __forceinline__ void cvt_plain8(const float* s, __nv_bfloat16* d, int i8) {
    const int i = i8 * 8;
    const float4 v0 = *(const float4*)&s[i];
    const float4 v1 = *(const float4*)&s[i + 4];
    __nv_bfloat16 o[8];
    o[0] = __float2bfloat16(v0.x); o[1] = __float2bfloat16(v0.y);
    o[2] = __float2bfloat16(v0.z); o[3] = __float2bfloat16(v0.w);
    o[4] = __float2bfloat16(v1.x); o[5] = __float2bfloat16(v1.y);
    o[6] = __float2bfloat16(v1.z); o[7] = __float2bfloat16(v1.w);
    *(uint4*)&d[i] = *(uint4*)o;
}

__global__ void cvt_all(const float* __restrict__ x, const float* __restrict__ fc11w,
                        const float* __restrict__ fc12w, const float* __restrict__ qw,
                        const float* __restrict__ decw, const float* __restrict__ kw,
                        const float* __restrict__ vw) {
    int b = blockIdx.x;
    if (b < NB_X) { cvt_padK(x, g_xb, b * 256 + threadIdx.x); return; }
    b -= NB_X;
    if (b < NB_W) { cvt_padK(fc11w, g_wb, b * 256 + threadIdx.x); return; }
    b -= NB_W;
    if (b < NB_12) { cvt_plain8(fc12w, g_fc12b, b * 256 + threadIdx.x); return; }
    b -= NB_12;
    if (b < NB_QW) { cvt_plain8(qw, g_qwb, b * 256 + threadIdx.x); return; }
    b -= NB_QW;
    if (b < NB_DW) {
        const int e = (b * 256 + threadIdx.x) * 4;
        const int r = e >> 7, c = e & 127;
        __nv_bfloat16 o[4];
#pragma unroll
        for (int u = 0; u < 4; u++) {
            const int cc = c + u;
            o[u] = (r < Vv && cc < Tt) ? __float2bfloat16(decw[(size_t)r * Tt + cc])
                                       : __float2bfloat16(0.f);
        }
        *(uint2*)&g_decwb[(size_t)r * TP + c] = *(uint2*)o;
        return;
    }
    b -= NB_DW;
    if (b < 144) {
        __shared__ float t[32][33];
        const int bx = (b % 12) * 32, by = (b / 12) * 32;
        const int tx = threadIdx.x & 31, ty = threadIdx.x >> 5;  // 32x8
#pragma unroll
        for (int i = 0; i < 32; i += 8)
            t[ty + i][tx] = kw[(size_t)(by + ty + i) * Dd + bx + tx];
        __syncthreads();
#pragma unroll
        for (int i = 0; i < 32; i += 8)
            g_kwtb[(size_t)(bx + ty + i) * Dd + by + tx] = __float2bfloat16(t[tx][ty + i]);
        return;
    }
    b -= 144;
    cvt_plain8(vw, g_vwb, b * 256 + threadIdx.x);
}

// ---------------- warp-level bf16 MMA ----------------------------------------
__device__ __forceinline__ void mma16816(float* c, const uint32_t* a, const uint32_t* b) {
    asm volatile(
        "mma.sync.aligned.m16n8k16.row.col.f32.bf16.bf16.f32 "
        "{%0,%1,%2,%3}, {%4,%5,%6,%7}, {%8,%9}, {%0,%1,%2,%3};"
        : "+f"(c[0]), "+f"(c[1]), "+f"(c[2]), "+f"(c[3])
        : "r"(a[0]), "r"(a[1]), "r"(a[2]), "r"(a[3]), "r"(b[0]), "r"(b[1]));
}

// ===================== fc11 via cp.async 3-stage + ldmatrix ==================
__device__ __forceinline__ void fc11_load_stage(uint32_t sbase, int st, int kt,
                                                int bm, int bn, int tid) {
    const int k0 = kt * 64;
    const uint32_t abase = sbase + st * 32768;
    const uint32_t bbase = abase + 16384;
#pragma unroll
    for (int i = 0; i < 4; i++) {
        const int idx = tid + 256 * i;
        const int row = idx >> 3, ch = idx & 7;
        const uint32_t off = (uint32_t)row * 128u + (uint32_t)((ch ^ (row & 7)) << 4);
        const void* asrc = &g_xb[(size_t)(bm + row) * KP + k0 + ch * 8];
        asm volatile("cp.async.cg.shared.global [%0], [%1], 16;"
                     :: "r"(abase + off), "l"(asrc));
        const void* bsrc = &g_wb[(size_t)(bn + row) * KP + k0 + ch * 8];
        asm volatile("cp.async.cg.shared.global [%0], [%1], 16;"
                     :: "r"(bbase + off), "l"(bsrc));
    }
    asm volatile("cp.async.commit_group;");
}

__device__ __forceinline__ uint32_t swz(uint32_t row, uint32_t bytecol) {
    return row * 128u + ((((bytecol >> 4) ^ (row & 7u))) << 4) + (bytecol & 15u);
}

__global__ __launch_bounds__(256, 2) void fc11_mma2() {
    extern __shared__ char dynsmem[];
    const uint32_t sbase = smem_u32(dynsmem);
    const int tid = threadIdx.x;
    const int wid = tid >> 5, lane = tid & 31;
    const int wr = wid >> 2, wc = wid & 3;
    const int l4 = lane >> 2, lq = lane & 3;
    const int lrow16 = lane & 15;
    const uint32_t lhalfA = (uint32_t)((lane >> 4) << 4);
    const int brow = (lane & 7) + ((lane >> 4) << 3);
    const uint32_t bhalf = (uint32_t)(((lane >> 3) & 1) << 4);
    const int bn = blockIdx.x * 128;
    const int bm = blockIdx.y * 128;
    const int s = blockIdx.z;
    const int kt0 = (s * KTOT) / SPLIT, kt1 = ((s + 1) * KTOT) / SPLIT;
    const int niter = kt1 - kt0;

    float c[4][4][4];
#pragma unroll
    for (int i = 0; i < 4; i++)
#pragma unroll
        for (int j = 0; j < 4; j++)
#pragma unroll
            for (int u = 0; u < 4; u++) c[i][j][u] = 0.f;

    fc11_load_stage(sbase, 0, kt0, bm, bn, tid);
    if (niter > 1) fc11_load_stage(sbase, 1, kt0 + 1, bm, bn, tid);

    int st = 0;
    for (int t = 0; t < niter; t++) {
        if (t + 2 < niter) {
            int st2 = st + 2; if (st2 >= 3) st2 -= 3;
            fc11_load_stage(sbase, st2, kt0 + t + 2, bm, bn, tid);
            asm volatile("cp.async.wait_group 2;");
        } else if (t + 1 < niter) {
            asm volatile("cp.async.wait_group 1;");
        } else {
            asm volatile("cp.async.wait_group 0;");
        }
        __syncthreads();

        const uint32_t abase = sbase + st * 32768;
        const uint32_t bbase = abase + 16384;
#pragma unroll
        for (int kk = 0; kk < 4; kk++) {
            const uint32_t kb = (uint32_t)(kk * 32);
            uint32_t a[4][4], bt[8];
#pragma unroll
            for (int i = 0; i < 4; i++)
                ldsm_x4(a[i], abase + swz((uint32_t)(wr * 64 + i * 16 + lrow16), kb + lhalfA));
            ldsm_x4(bt,     bbase + swz((uint32_t)(wc * 32 + brow),      kb + bhalf));
            ldsm_x4(bt + 4, bbase + swz((uint32_t)(wc * 32 + 16 + brow), kb + bhalf));
#pragma unroll
            for (int i = 0; i < 4; i++)
#pragma unroll
                for (int j = 0; j < 4; j++) mma16816(c[i][j], a[i], bt + j * 2);
        }
        __syncthreads();
        if (++st >= 3) st = 0;
    }

#pragma unroll
    for (int i = 0; i < 4; i++) {
        const int row0 = bm + wr * 64 + i * 16 + l4;
#pragma unroll
        for (int j = 0; j < 4; j++) {
            const int col = bn + wc * 32 + j * 8 + lq * 2;
            float* p0 = g_part + ((size_t)s * Bb + row0) * Ee + col;
            float* p1 = g_part + ((size_t)s * Bb + row0 + 8) * Ee + col;
            p0[0] = c[i][j][0]; p0[1] = c[i][j][1];
            p1[0] = c[i][j][2]; p1[1] = c[i][j][3];
        }
    }
}

__global__ void fc11_reduce(const float* __restrict__ bias) {
    const int i = blockIdx.x * 256 + threadIdx.x;
    float v = bias[i & (Ee - 1)];
#pragma unroll
    for (int s = 0; s < SPLIT; s++) v += g_part[(size_t)s * (Bb * Ee) + i];
    g_e1b[i] = __float2bfloat16(softplus_f(v));
}

// ===================== 64x64-tile bf16 mma GEMM, 2-stage cp.async ============
// MODE: 0 = fp32 out, 1 = bf16 out, 2 = both
#define PADR 72
template <int ACT, int MODE>
__global__ __launch_bounds__(128) void mma_gemm64(const __nv_bfloat16* __restrict__ A,
                                                  const __nv_bfloat16* __restrict__ W,
                                                  const float* __restrict__ bias,
                                                  float* __restrict__ C,
                                                  __nv_bfloat16* __restrict__ Cb,
                                                  int N, int K) {
    __shared__ __nv_bfloat16 As[2][64][PADR];
    __shared__ __nv_bfloat16 Bs[2][64][PADR];
    const int tid = threadIdx.x;
    const int wid = tid >> 5, lane = tid & 31;
    const int wr = wid >> 1, wc = wid & 1;   // 2x2 warp grid, warp tile 32x32
    const int l4 = lane >> 2, lq = lane & 3;
    const int bn = blockIdx.x * 64;
    const int bm = blockIdx.y * 64;
    const int lrow = tid >> 3, lch = tid & 7;   // 16 rows x 8 chunks per pass
    const int niter = K >> 6;

    float c[2][4][4];
#pragma unroll
    for (int i = 0; i < 2; i++)
#pragma unroll
        for (int j = 0; j < 4; j++)
#pragma unroll
            for (int u = 0; u < 4; u++) c[i][j][u] = 0.f;

    // prologue: stage 0
#pragma unroll
    for (int i = 0; i < 4; i++) {
        const int row = lrow + 16 * i;
        asm volatile("cp.async.cg.shared.global [%0], [%1], 16;"
                     :: "r"(smem_u32(&As[0][row][lch * 8])),
                        "l"(&A[(size_t)(bm + row) * K + lch * 8]));
        asm volatile("cp.async.cg.shared.global [%0], [%1], 16;"
                     :: "r"(smem_u32(&Bs[0][row][lch * 8])),
                        "l"(&W[(size_t)(bn + row) * K + lch * 8]));
    }
    asm volatile("cp.async.commit_group;");

    for (int t = 0; t < niter; t++) {
        if (t + 1 < niter) {
            const int k1 = (t + 1) << 6;
            const int sg1 = (t + 1) & 1;
#pragma unroll
            for (int i = 0; i < 4; i++) {
                const int row = lrow + 16 * i;
                asm volatile("cp.async.cg.shared.global [%0], [%1], 16;"
                             :: "r"(smem_u32(&As[sg1][row][lch * 8])),
                                "l"(&A[(size_t)(bm + row) * K + k1 + lch * 8]));
                asm volatile("cp.async.cg.shared.global [%0], [%1], 16;"
                             :: "r"(smem_u32(&Bs[sg1][row][lch * 8])),
                                "l"(&W[(size_t)(bn + row) * K + k1 + lch * 8]));
            }
            asm volatile("cp.async.commit_group;");
            asm volatile("cp.async.wait_group 1;");
        } else {
            asm volatile("cp.async.wait_group 0;");
        }
        __syncthreads();

        const int sg = t & 1;
#pragma unroll
        for (int kk = 0; kk < 4; kk++) {
            const int kb = kk * 16 + lq * 2;
            uint32_t a[2][4], b[4][2];
#pragma unroll
            for (int i = 0; i < 2; i++) {
                const int r = wr * 32 + i * 16 + l4;
                a[i][0] = *(const uint32_t*)&As[sg][r][kb];
                a[i][1] = *(const uint32_t*)&As[sg][r + 8][kb];
                a[i][2] = *(const uint32_t*)&As[sg][r][kb + 8];
                a[i][3] = *(const uint32_t*)&As[sg][r + 8][kb + 8];
            }
#pragma unroll
            for (int j = 0; j < 4; j++) {
                const int n = wc * 32 + j * 8 + l4;
                b[j][0] = *(const uint32_t*)&Bs[sg][n][kb];
                b[j][1] = *(const uint32_t*)&Bs[sg][n][kb + 8];
            }
#pragma unroll
            for (int i = 0; i < 2; i++)
#pragma unroll
                for (int j = 0; j < 4; j++) mma16816(c[i][j], a[i], b[j]);
        }
        __syncthreads();
    }

#pragma unroll
    for (int i = 0; i < 2; i++) {
        const int row0 = bm + wr * 32 + i * 16 + l4;
#pragma unroll
        for (int j = 0; j < 4; j++) {
            const int col = bn + wc * 32 + j * 8 + lq * 2;
#pragma unroll
            for (int h = 0; h < 2; h++) {
                const int row = row0 + h * 8;
#pragma unroll
                for (int u = 0; u < 2; u++) {
                    float v = c[i][j][h * 2 + u] + bias[col + u];
                    if (ACT == 1) v = softplus_f(v);
                    if (MODE == 0 || MODE == 2) C[(size_t)row * N + col + u] = v;
                    if (MODE == 1 || MODE == 2)
                        Cb[(size_t)row * N + col + u] = __float2bfloat16(v);
                }
            }
        }
    }
}

// ===================== logit mma GEMM: [512,VP]x[VP,TP], col guard ===========
__global__ __launch_bounds__(256) void mma_logit(const float* __restrict__ bias) {
    __shared__ __nv_bfloat16 As[128][PADR];
    __shared__ __nv_bfloat16 Bs[128][PADR];
    const int tid = threadIdx.x;
    const int wid = tid >> 5, lane = tid & 31;
    const int wr = wid >> 2, wc = wid & 3;
    const int l4 = lane >> 2, lq = lane & 3;
    const int bn = blockIdx.x * 128;
    const int bm = blockIdx.y * 128;

    float c[4][4][4];
#pragma unroll
    for (int i = 0; i < 4; i++)
#pragma unroll
        for (int j = 0; j < 4; j++)
#pragma unroll
            for (int u = 0; u < 4; u++) c[i][j][u] = 0.f;

    for (int k0 = 0; k0 < TP; k0 += 64) {
#pragma unroll
        for (int i = 0; i < 4; i++) {
            const int idx = tid + 256 * i;
            const int row = idx >> 3, ch = idx & 7;
            uint4 va = *(const uint4*)&g_thetab[(size_t)(bm + row) * TP + k0 + ch * 8];
            *(uint4*)&As[row][ch * 8] = va;
            uint4 vb = *(const uint4*)&g_decwb[(size_t)(bn + row) * TP + k0 + ch * 8];
            *(uint4*)&Bs[row][ch * 8] = vb;
        }
        __syncthreads();

#pragma unroll
        for (int kk = 0; kk < 4; kk++) {
            const int kb = kk * 16 + lq * 2;
            uint32_t a[4][4], b[4][2];
#pragma unroll
            for (int i = 0; i < 4; i++) {
                const int r = wr * 64 + i * 16 + l4;
                a[i][0] = *(const uint32_t*)&As[r][kb];
                a[i][1] = *(const uint32_t*)&As[r + 8][kb];
                a[i][2] = *(const uint32_t*)&As[r][kb + 8];
                a[i][3] = *(const uint32_t*)&As[r + 8][kb + 8];
            }
#pragma unroll
            for (int j = 0; j < 4; j++) {
                const int n = wc * 32 + j * 8 + l4;
                b[j][0] = *(const uint32_t*)&Bs[n][kb];
                b[j][1] = *(const uint32_t*)&Bs[n][kb + 8];
            }
#pragma unroll
            for (int i = 0; i < 4; i++)
#pragma unroll
                for (int j = 0; j < 4; j++) mma16816(c[i][j], a[i], b[j]);
        }
        __syncthreads();
    }

#pragma unroll
    for (int i = 0; i < 4; i++) {
        const int row0 = bm + wr * 64 + i * 16 + l4;
#pragma unroll
        for (int j = 0; j < 4; j++) {
            const int col = bn + wc * 32 + j * 8 + lq * 2;
#pragma unroll
            for (int h = 0; h < 2; h++) {
                const int row = row0 + h * 8;
#pragma unroll
                for (int u = 0; u < 2; u++) {
                    const int cg = col + u;
                    if (cg < Vv)
                        g_logit[(size_t)row * Vv + cg] = c[i][j][h * 2 + u] + bias[cg];
                }
            }
        }
    }
}

// ---------------- packed f32x2 helpers --------------------------------------
__device__ __forceinline__ unsigned long long pk2(float x, float y) {
    unsigned long long r;
    asm("mov.b64 %0, {%1, %2};" : "=l"(r) : "f"(x), "f"(y));
    return r;
}
__device__ __forceinline__ unsigned long long fma2(unsigned long long a,
                                                   unsigned long long b,
                                                   unsigned long long c) {
    unsigned long long d;
    asm("fma.rn.f32x2 %0, %1, %2, %3;" : "=l"(d) : "l"(a), "l"(b), "l"(c));
    return d;
}
__device__ __forceinline__ void upk2(unsigned long long v, float& lo, float& hi) {
    asm("mov.b64 {%0, %1}, %2;" : "=f"(lo), "=f"(hi) : "l"(v));
}

// ---------------- generic fp32 GEMM body (register double-buffered) ---------
template <int ACT, bool BNT>
__device__ __forceinline__ void gemm64_body(const float* __restrict__ A,
                                            const float* __restrict__ Bm,
                                            const float* __restrict__ bias,
                                            float* __restrict__ C,
                                            int M, int N, int K) {
    __shared__ float As[16][64];
    __shared__ float Bs[16][64];
    const int bm = blockIdx.y * 64, bn = blockIdx.x * 64;
    const int tid = threadIdx.x;
    const int tr = tid >> 4, tc = tid & 15;
    const int lrow = tid >> 4;
    const int lk = tid & 15;

    unsigned long long acc[4][2];
#pragma unroll
    for (int i = 0; i < 4; i++) { acc[i][0] = 0ull; acc[i][1] = 0ull; }

    float pa[4], pb[4], na[4], nb[4];

#pragma unroll
    for (int i = 0; i < 4; i++) {
        int r = lrow + i * 16;
        int gk = lk;
        int gm = bm + r;
        pa[i] = (gm < M && gk < K) ? A[(size_t)gm * K + gk] : 0.f;
        int gn = bn + r;
        float v = 0.f;
        if (gn < N && gk < K)
            v = BNT ? Bm[(size_t)gn * K + gk] : Bm[(size_t)gk * N + gn];
        pb[i] = v;
    }

    for (int k0 = 0; k0 < K; k0 += 16) {
#pragma unroll
        for (int i = 0; i < 4; i++) {
            int r = lrow + i * 16;
            As[lk][r] = pa[i];
            Bs[lk][r] = pb[i];
        }
        __syncthreads();

        if (k0 + 16 < K) {
#pragma unroll
            for (int i = 0; i < 4; i++) {
                int r = lrow + i * 16;
                int gk = k0 + 16 + lk;
                int gm = bm + r;
                na[i] = (gm < M && gk < K) ? A[(size_t)gm * K + gk] : 0.f;
                int gn = bn + r;
                float v = 0.f;
                if (gn < N && gk < K)
                    v = BNT ? Bm[(size_t)gn * K + gk] : Bm[(size_t)gk * N + gn];
                nb[i] = v;
            }
        }

#pragma unroll
        for (int kk = 0; kk < 16; kk++) {
            float a0 = As[kk][tr * 4 + 0];
            float a1 = As[kk][tr * 4 + 1];
            float a2 = As[kk][tr * 4 + 2];
            float a3 = As[kk][tr * 4 + 3];
            unsigned long long b0 =
                *reinterpret_cast<const unsigned long long*>(&Bs[kk][tc * 4]);
            unsigned long long b1 =
                *reinterpret_cast<const unsigned long long*>(&Bs[kk][tc * 4 + 2]);
            unsigned long long A0 = pk2(a0, a0), A1 = pk2(a1, a1);
            unsigned long long A2 = pk2(a2, a2), A3 = pk2(a3, a3);
            acc[0][0] = fma2(A0, b0, acc[0][0]); acc[0][1] = fma2(A0, b1, acc[0][1]);
            acc[1][0] = fma2(A1, b0, acc[1][0]); acc[1][1] = fma2(A1, b1, acc[1][1]);
            acc[2][0] = fma2(A2, b0, acc[2][0]); acc[2][1] = fma2(A2, b1, acc[2][1]);
            acc[3][0] = fma2(A3, b0, acc[3][0]); acc[3][1] = fma2(A3, b1, acc[3][1]);
        }
        __syncthreads();
#pragma unroll
        for (int i = 0; i < 4; i++) { pa[i] = na[i]; pb[i] = nb[i]; }
    }

#pragma unroll
    for (int i = 0; i < 4; i++) {
        int gm = bm + tr * 4 + i;
        if (gm >= M) continue;
#pragma unroll
        for (int j2 = 0; j2 < 2; j2++) {
            float lo, hi;
            upk2(acc[i][j2], lo, hi);
            float vals[2] = {lo, hi};
#pragma unroll
            for (int u = 0; u < 2; u++) {
                int gn = bn + tc * 4 + j2 * 2 + u;
                if (gn < N) {
                    float v = vals[u] + (bias ? bias[gn] : 0.f);
                    if (ACT == 1) v = softplus_f(v);
                    C[(size_t)gm * N + gn] = v;
                }
            }
        }
    }
}

__global__ void gemm_mulv(const float* __restrict__ Wm, const float* __restrict__ bm_,
                          const float* __restrict__ Wl, const float* __restrict__ bl_) {
    if (blockIdx.z == 0)
        gemm64_body<0, true>(g_di, Wm, bm_, g_mu, Bb, Tt, Dd);
    else
        gemm64_body<0, true>(g_di, Wl, bl_, g_lv, Bb, Tt, Dd);
}

// ---------------- fused ragged single-query attention -----------------------
__global__ void attn_kernel(const float* __restrict__ emb,
                            const float* __restrict__ kb,
                            const int* __restrict__ lengths) {
    const int b = blockIdx.x, tid = threadIdx.x;  // 256 threads
    __shared__ float s_qk[Dd];
    __shared__ float s_sc[Mm];
    __shared__ float red[256];
    __shared__ float s_kbdot;
    const int len = lengths[b];

    float part = 0.f;
    for (int d = tid; d < Dd; d += 256) {
        s_qk[d] = g_qk[b * Dd + d];
        part += g_q[b * Dd + d] * kb[d];
    }
    red[tid] = part;
    __syncthreads();
    for (int s = 128; s > 0; s >>= 1) {
        if (tid < s) red[tid] += red[tid + s];
        __syncthreads();
    }
    if (tid == 0) s_kbdot = red[0];
    __syncthreads();
    const float kbdot = s_kbdot;

    const int wid = tid >> 5, lane = tid & 31;
    const float scale = 0.051031036307982884f;  // 1/sqrt(384)
    for (int m = wid; m < Mm; m += 8) {
        const float* er = emb + ((size_t)b * Mm + m) * Dd;
        float sum = 0.f;
#pragma unroll
        for (int i = 0; i < Dd / 32; i++) {
            int d = lane + 32 * i;
            sum += er[d] * s_qk[d];
        }
#pragma unroll
        for (int o = 16; o > 0; o >>= 1) sum += __shfl_xor_sync(0xffffffffu, sum, o);
        if (lane == 0) s_sc[m] = (m < len) ? (sum + kbdot) * scale : -1e30f;
    }
    __syncthreads();

    if (wid == 0) {
        float v0 = s_sc[lane], v1 = s_sc[lane + 32];
        float mx = fmaxf(v0, v1);
#pragma unroll
        for (int o = 16; o > 0; o >>= 1) mx = fmaxf(mx, __shfl_xor_sync(0xffffffffu, mx, o));
        float e0 = expf(v0 - mx), e1 = expf(v1 - mx);
        float ss = e0 + e1;
#pragma unroll
        for (int o = 16; o > 0; o >>= 1) ss += __shfl_xor_sync(0xffffffffu, ss, o);
        float inv = 1.f / ss;
        s_sc[lane] = e0 * inv;
        s_sc[lane + 32] = e1 * inv;
    }
    __syncthreads();

    for (int d = tid; d < Dd; d += 256) {
        float acc = 0.f;
#pragma unroll 8
        for (int m = 0; m < Mm; m++)
            acc += s_sc[m] * emb[((size_t)b * Mm + m) * Dd + d];
        g_ebarb[b * Dd + d] = __float2bfloat16(acc);
    }
}

// ---------------- BatchNorm over batch dim for [B,T], both arrays -----------
__global__ void bn_both(const float* __restrict__ bias_mu,
                        const float* __restrict__ bias_lv) {
    const int which = blockIdx.x >= Tt;
    const int t = which ? blockIdx.x - Tt : blockIdx.x;
    float* h = which ? g_lv : g_mu;
    const float* bias = which ? bias_lv : bias_mu;
    const int tid = threadIdx.x;  // 256
    __shared__ float red[256];
    __shared__ float s_mu, s_inv;
    float v0 = h[(size_t)tid * Tt + t];
    float v1 = h[(size_t)(tid + 256) * Tt + t];
    red[tid] = v0 + v1;
    __syncthreads();
    for (int s = 128; s > 0; s >>= 1) {
        if (tid < s) red[tid] += red[tid + s];
        __syncthreads();
    }
    if (tid == 0) s_mu = red[0] * (1.f / Bb);
    __syncthreads();
    float mu = s_mu;
    float d0 = v0 - mu, d1 = v1 - mu;
    red[tid] = d0 * d0 + d1 * d1;
    __syncthreads();
    for (int s = 128; s > 0; s >>= 1) {
        if (tid < s) red[tid] += red[tid + s];
        __syncthreads();
    }
    if (tid == 0) s_inv = rsqrtf(red[0] * (1.f / Bb) + 1e-5f);
    __syncthreads();
    float inv = s_inv, bbv = bias[t];
    h[(size_t)tid * Tt + t] = d0 * inv + bbv;
    h[(size_t)(tid + 256) * Tt + t] = d1 * inv + bbv;
}

// ---------------- theta = softmax(mu) (bf16 padded), kl per sample ----------
__global__ void theta_kl_kernel() {
    const int b = blockIdx.x, tid = threadIdx.x;  // 128
    __shared__ float red[128];
    __shared__ float s_mx, s_sum;
    const bool ok = tid < Tt;
    const float m = ok ? g_mu[b * Tt + tid] : -1e30f;
    const float l = ok ? g_lv[b * Tt + tid] : 0.f;
    red[tid] = m;
    __syncthreads();
    for (int s = 64; s > 0; s >>= 1) {
        if (tid < s) red[tid] = fmaxf(red[tid], red[tid + s]);
        __syncthreads();
    }
    if (tid == 0) s_mx = red[0];
    __syncthreads();
    const float e = ok ? expf(m - s_mx) : 0.f;
    red[tid] = e;
    __syncthreads();
    for (int s = 64; s > 0; s >>= 1) {
        if (tid < s) red[tid] += red[tid + s];
        __syncthreads();
    }
    if (tid == 0) s_sum = red[0];
    __syncthreads();
    g_thetab[b * TP + tid] = __float2bfloat16(ok ? e / s_sum : 0.f);

    const float INV_VAR2 = 1.0101010101010102f;    // 1/(1 - 1/T), T=100
    const float LOGV2 = -0.010050335853501441f;    // log(0.99)
    float term = ok ? (expf(l) * INV_VAR2 + m * m * INV_VAR2 + LOGV2 - l) : 0.f;
    red[tid] = term;
    __syncthreads();
    for (int s = 64; s > 0; s >>= 1) {
        if (tid < s) red[tid] += red[tid + s];
        __syncthreads();
    }
    if (tid == 0) g_kl[b] = 0.5f * (red[0] - (float)Tt);
}

// ---------------- per-vocab-column batch stats (deep unroll) ----------------
__global__ void colstats_kernel() {
    const int v = blockIdx.x * blockDim.x + threadIdx.x;
    if (v >= Vv) return;
    float s = 0.f, s2 = 0.f;
#pragma unroll 16
    for (int b = 0; b < Bb; b++) {
        float x = g_logit[(size_t)b * Vv + v];
        s += x;
        s2 += x * x;
    }
    const float mean = s * (1.f / Bb);
    float var = fmaxf(s2 * (1.f / Bb) - mean * mean, 0.f);
    g_colmu[v] = mean;
    g_colinv[v] = rsqrtf(var + 1e-5f);
}

// ---------------- per-sample reconstruction loss ----------------------------
__global__ void recon_kernel(const float* __restrict__ bnb,
                             const float* __restrict__ x) {
    const int b = blockIdx.x, tid = threadIdx.x;  // 256
    __shared__ float s_m[256], s_s[256], s_xh[256], s_x[256];
    float mx = -1e30f, sm = 0.f, xh = 0.f, xs = 0.f;
    for (int v = tid; v < Vv; v += 256) {
        float hn = (g_logit[(size_t)b * Vv + v] - g_colmu[v]) * g_colinv[v] + bnb[v];
        float xv = x[(size_t)b * Vv + v];
        xh += xv * hn;
        xs += xv;
        float nm = fmaxf(mx, hn);
        sm = sm * expf(mx - nm) + expf(hn - nm);
        mx = nm;
    }
    s_m[tid] = mx; s_s[tid] = sm; s_xh[tid] = xh; s_x[tid] = xs;
    __syncthreads();
    for (int st = 128; st > 0; st >>= 1) {
        if (tid < st) {
            float m2 = s_m[tid + st], sm2 = s_s[tid + st];
            float M = fmaxf(s_m[tid], m2);
            s_s[tid] = s_s[tid] * expf(s_m[tid] - M) + sm2 * expf(m2 - M);
            s_m[tid] = M;
            s_xh[tid] += s_xh[tid + st];
            s_x[tid] += s_x[tid + st];
        }
        __syncthreads();
    }
    if (tid == 0) {
        float lse = s_m[0] + logf(s_s[0]);
        g_recon[b] = lse * s_x[0] - s_xh[0];
    }
}

// ---------------- final scalar -----------------------------------------------
__global__ void final_reduce(float* __restrict__ out) {
    __shared__ float red[512];
    const int tid = threadIdx.x;
    red[tid] = g_recon[tid] + g_kl[tid];
    __syncthreads();
    for (int s = 256; s > 0; s >>= 1) {
        if (tid < s) red[tid] += red[tid + s];
        __syncthreads();
    }
    if (tid == 0) out[0] = red[0] * (1.f / Bb);
}

// =============================================================================
extern "C" void kernel_launch(void* const* d_in, const int* in_sizes, int n_in,
                              void* d_out, int out_size) {
    (void)in_sizes; (void)n_in; (void)out_size;
    const float* x        = (const float*)d_in[0];
    const float* emb      = (const float*)d_in[1];
    const int*   lengths  = (const int*)d_in[2];
    const float* fc11_w   = (const float*)d_in[3];
    const float* fc11_b   = (const float*)d_in[4];
    const float* fc12_w   = (const float*)d_in[5];
    const float* fc12_b   = (const float*)d_in[6];
    const float* q_w      = (const float*)d_in[7];
    const float* q_b      = (const float*)d_in[8];
    const float* k_w      = (const float*)d_in[9];
    const float* k_b      = (const float*)d_in[10];
    const float* v_w      = (const float*)d_in[11];
    const float* v_b      = (const float*)d_in[12];
    const float* mean_w   = (const float*)d_in[13];
    const float* mean_b   = (const float*)d_in[14];
    const float* logvar_w = (const float*)d_in[15];
    const float* logvar_b = (const float*)d_in[16];
    const float* mean_bn_b   = (const float*)d_in[17];
    const float* logvar_bn_b = (const float*)d_in[18];
    const float* dec_w    = (const float*)d_in[19];
    const float* dec_b    = (const float*)d_in[20];
    const float* dec_bn_b = (const float*)d_in[21];

    __nv_bfloat16 *fc12b, *qwb, *e1b, *hbowb, *qb, *kwtb, *vwb, *ebarb;
    cudaGetSymbolAddress((void**)&fc12b, g_fc12b);
    cudaGetSymbolAddress((void**)&qwb, g_qwb);
    cudaGetSymbolAddress((void**)&e1b, g_e1b);
    cudaGetSymbolAddress((void**)&hbowb, g_hbowb);
    cudaGetSymbolAddress((void**)&qb, g_qb);
    cudaGetSymbolAddress((void**)&kwtb, g_kwtb);
    cudaGetSymbolAddress((void**)&vwb, g_vwb);
    cudaGetSymbolAddress((void**)&ebarb, g_ebarb);
    float *q, *qk, *di, *zeros;
    cudaGetSymbolAddress((void**)&q, g_q);
    cudaGetSymbolAddress((void**)&qk, g_qk);
    cudaGetSymbolAddress((void**)&di, g_di);
    cudaGetSymbolAddress((void**)&zeros, g_zeros);

    cudaFuncSetAttribute(fc11_mma2, cudaFuncAttributeMaxDynamicSharedMemorySize, 98304);

    // 1: ALL conversions in one fused launch
    cvt_all<<<NB_ALL, 256>>>(x, fc11_w, fc12_w, q_w, dec_w, k_w, v_w);
    // 2: fc11 GEMM (3-stage cp.async, ldmatrix, split-K=9)
    fc11_mma2<<<dim3(Ee / 128, Bb / 128, SPLIT), 256, 98304>>>();
    // 3: reduce partials -> e1 (bf16)
    fc11_reduce<<<(Bb * Ee) / 256, 256>>>(fc11_b);
    // 4: h_bow (bf16 out, 2-stage pipelined)  <- profiled launch
    mma_gemm64<1, 1><<<dim3(Ee / 64, Bb / 64), 128>>>(e1b, fc12b, fc12_b, (float*)0, hbowb, Ee, Ee);
    // 5: q (fp32 + bf16 out)
    mma_gemm64<0, 2><<<dim3(Dd / 64, Bb / 64), 128>>>(hbowb, qwb, q_b, q, qb, Dd, Ee);
    // 6: qk = q @ k_w  (bf16 mma, zero bias)
    mma_gemm64<0, 0><<<dim3(Dd / 64, Bb / 64), 128>>>(qb, kwtb, zeros, qk, (__nv_bfloat16*)0, Dd, Dd);
    // 7: attention -> ebar (bf16)
    attn_kernel<<<Bb, 256>>>(emb, k_b, lengths);
    // 8: d_i = ebar @ v_w^T + v_b  (bf16 mma)
    mma_gemm64<0, 0><<<dim3(Dd / 64, Bb / 64), 128>>>(ebarb, vwb, v_b, di, (__nv_bfloat16*)0, Dd, Dd);
    // 9..: tail
    gemm_mulv<<<dim3(2, Bb / 64, 2), 256>>>(mean_w, mean_b, logvar_w, logvar_b);
    bn_both<<<2 * Tt, 256>>>(mean_bn_b, logvar_bn_b);
    theta_kl_kernel<<<Bb, 128>>>();
    mma_logit<<<dim3(VP / 128, Bb / 128), 256>>>(dec_b);
    colstats_kernel<<<(Vv + 255) / 256, 256>>>();
    recon_kernel<<<Bb, 256>>>(dec_bn_b, x);
    final_reduce<<<1, Bb>>>((float*)d_out);
}